// round 7
// baseline (speedup 1.0000x reference)
#include <cuda_runtime.h>
#include <cuda_bf16.h>
#include <math.h>

#define B_ 16
#define N_ 512
#define H_ 8
#define E_ 128
#define BH_ (B_*H_)
#define NEGV (-1000000000.0f)
#define SCALE_ 0.08838834764831845f

// Intermediates as packed bf16x2 (unsigned) arrays. hi/lo split pairs.
__device__ unsigned g_qh[BH_*N_*E_/2];
__device__ unsigned g_ql[BH_*N_*E_/2];
__device__ unsigned g_kh[BH_*N_*E_/2];
__device__ unsigned g_kl[BH_*N_*E_/2];
__device__ unsigned g_vh[BH_*N_*E_/2];
__device__ unsigned g_vl[BH_*N_*E_/2];
__device__ unsigned g_yh[BH_*N_*E_/2];
__device__ unsigned g_yl[BH_*N_*E_/2];
__device__ unsigned g_woh[E_*1024/2];
__device__ unsigned g_wol[E_*1024/2];

// ---------------------------------------------------------------------------
// helpers
// ---------------------------------------------------------------------------
__device__ __forceinline__ unsigned smem_u32(const void* p) {
    unsigned r;
    asm("{ .reg .u64 t; cvta.to.shared.u64 t, %1; cvt.u32.u64 %0, t; }" : "=r"(r) : "l"(p));
    return r;
}
__device__ __forceinline__ void ldsm4(unsigned r[4], unsigned addr) {
    asm volatile("ldmatrix.sync.aligned.m8n8.x4.shared.b16 {%0,%1,%2,%3}, [%4];"
        : "=r"(r[0]), "=r"(r[1]), "=r"(r[2]), "=r"(r[3]) : "r"(addr));
}
__device__ __forceinline__ void ldsm4t(unsigned r[4], unsigned addr) {
    asm volatile("ldmatrix.sync.aligned.m8n8.x4.trans.shared.b16 {%0,%1,%2,%3}, [%4];"
        : "=r"(r[0]), "=r"(r[1]), "=r"(r[2]), "=r"(r[3]) : "r"(addr));
}
__device__ __forceinline__ void mma16816(float c[4], const unsigned a[4],
                                         unsigned b0, unsigned b1) {
    asm volatile("mma.sync.aligned.m16n8k16.row.col.f32.bf16.bf16.f32 "
        "{%0,%1,%2,%3}, {%4,%5,%6,%7}, {%8,%9}, {%0,%1,%2,%3};"
        : "+f"(c[0]), "+f"(c[1]), "+f"(c[2]), "+f"(c[3])
        : "r"(a[0]), "r"(a[1]), "r"(a[2]), "r"(a[3]), "r"(b0), "r"(b1));
}
__device__ __forceinline__ unsigned pack_hi(float a, float b) {
    __nv_bfloat162 h = __floats2bfloat162_rn(a, b);
    return *(unsigned*)&h;
}
__device__ __forceinline__ unsigned pack_lo(float a, float b, unsigned hi) {
    __nv_bfloat162 h = *(__nv_bfloat162*)&hi;
    __nv_bfloat162 l = __floats2bfloat162_rn(a - __bfloat162float(__low2bfloat16(h)),
                                             b - __bfloat162float(__high2bfloat16(h)));
    return *(unsigned*)&l;
}

// fp32 tile -> split bf16 hi/lo smem (272B row stride). nthr threads.
__device__ __forceinline__ void load_split(const float* __restrict__ src,
        size_t stride, char* smc, int offH, int offL, int rows, int tid, int nthr)
{
    const int total = rows * 32;
    for (int idx = tid; idx < total; idx += nthr) {
        int r = idx >> 5, c4 = idx & 31;
        float4 v = *(const float4*)(src + (size_t)r * stride + c4 * 4);
        unsigned h0 = pack_hi(v.x, v.y), h1 = pack_hi(v.z, v.w);
        unsigned l0 = pack_lo(v.x, v.y, h0), l1 = pack_lo(v.z, v.w, h1);
        *(uint2*)(smc + offH + r * 272 + c4 * 8) = make_uint2(h0, h1);
        *(uint2*)(smc + offL + r * 272 + c4 * 8) = make_uint2(l0, l1);
    }
}

// packed-bf16 tile copy: global (row stride 64 unsigned) -> smem 272B stride
__device__ __forceinline__ void copy_tile(const unsigned* __restrict__ srcH,
        const unsigned* __restrict__ srcL, char* smc, int offH, int offL,
        int rows, int tid, int nthr)
{
    const int total = rows * 16;
    for (int idx = tid; idx < total; idx += nthr) {
        int r = idx >> 4, c = idx & 15;
        *(uint4*)(smc + offH + r * 272 + c * 16) = *(const uint4*)(srcH + (size_t)r * 64 + c * 4);
        *(uint4*)(smc + offL + r * 272 + c * 16) = *(const uint4*)(srcL + (size_t)r * 64 + c * 4);
    }
}

// ---------------------------------------------------------------------------
// Kernel 0: split Wo into bf16 hi/lo
// ---------------------------------------------------------------------------
__global__ void wsplit_kernel(const float* __restrict__ Wo) {
    int i = blockIdx.x * 256 + threadIdx.x;
    float2 v = *(const float2*)(Wo + 2 * i);
    unsigned h = pack_hi(v.x, v.y);
    g_woh[i] = h;
    g_wol[i] = pack_lo(v.x, v.y, h);
}

// ---------------------------------------------------------------------------
// Kernel 1: QKV projection. 512 threads, 4x4 warp grid, 32x32 per warp.
// ---------------------------------------------------------------------------
#define QG_XH 0
#define QG_XL 34816
#define QG_WH 69632
#define QG_WL 104448
#define SMEM_QKV 139264

__global__ __launch_bounds__(512, 1) void qkv_mma_kernel(
    const float* __restrict__ x,
    const float* __restrict__ Wq, const float* __restrict__ bq,
    const float* __restrict__ Wk, const float* __restrict__ bk,
    const float* __restrict__ Wv, const float* __restrict__ bv)
{
    extern __shared__ char smc[];
    const unsigned sb = smem_u32(smc);

    const int which = blockIdx.z;
    const float* __restrict__ W    = (which == 0) ? Wq : (which == 1) ? Wk : Wv;
    const float* __restrict__ bias = (which == 0) ? bq : (which == 1) ? bk : bv;
    unsigned* __restrict__ dH = (which == 0) ? g_qh : (which == 1) ? g_kh : g_vh;
    unsigned* __restrict__ dL = (which == 0) ? g_ql : (which == 1) ? g_kl : g_vl;

    const int tid  = threadIdx.x;
    const int lane = tid & 31;
    const int wid  = tid >> 5;
    const int wm   = wid >> 2;          // 0..3 -> 32 rows
    const int wn   = wid & 3;           // 0..3 -> 32 cols
    const int gid  = lane >> 2;
    const int tig  = lane & 3;

    const int row0 = blockIdx.x << 7;
    const int col0 = blockIdx.y << 7;

    const int a_row = (lane & 15);
    const int a_col = ((lane >> 4) << 3);
    const int b_key = (lane & 7) + ((lane >> 4) << 3);
    const int b_ecol = (((lane >> 3) & 1) << 3);

    load_split(x + (size_t)row0 * E_, E_, smc, QG_XH, QG_XL, 128, tid, 512);
    load_split(W + (size_t)col0 * E_, E_, smc, QG_WH, QG_WL, 128, tid, 512);
    __syncthreads();

    float acc[2][4][4] = {};
    #pragma unroll
    for (int k = 0; k < 8; k++) {
        unsigned ah[2][4], al[2][4], bh4[2][4], bl4[2][4];
        #pragma unroll
        for (int mf = 0; mf < 2; mf++) {
            unsigned ao = (unsigned)((wm * 32 + mf * 16 + a_row) * 272 + (k * 16 + a_col) * 2);
            ldsm4(ah[mf], sb + QG_XH + ao);
            ldsm4(al[mf], sb + QG_XL + ao);
        }
        #pragma unroll
        for (int ng = 0; ng < 2; ng++) {
            unsigned bo = (unsigned)((wn * 32 + ng * 16 + b_key) * 272 + (k * 16 + b_ecol) * 2);
            ldsm4(bh4[ng], sb + QG_WH + bo);
            ldsm4(bl4[ng], sb + QG_WL + bo);
        }
        #pragma unroll
        for (int ng = 0; ng < 2; ng++)
            #pragma unroll
            for (int mf = 0; mf < 2; mf++) {
                mma16816(acc[mf][2*ng],   ah[mf], bh4[ng][0], bh4[ng][1]);
                mma16816(acc[mf][2*ng+1], ah[mf], bh4[ng][2], bh4[ng][3]);
            }
        #pragma unroll
        for (int ng = 0; ng < 2; ng++)
            #pragma unroll
            for (int mf = 0; mf < 2; mf++) {
                mma16816(acc[mf][2*ng],   ah[mf], bl4[ng][0], bl4[ng][1]);
                mma16816(acc[mf][2*ng+1], ah[mf], bl4[ng][2], bl4[ng][3]);
            }
        #pragma unroll
        for (int ng = 0; ng < 2; ng++)
            #pragma unroll
            for (int mf = 0; mf < 2; mf++) {
                mma16816(acc[mf][2*ng],   al[mf], bh4[ng][0], bh4[ng][1]);
                mma16816(acc[mf][2*ng+1], al[mf], bh4[ng][2], bh4[ng][3]);
            }
    }

    const int hh = col0 >> 7;
    const float sc = (which == 0) ? SCALE_ : 1.0f;
    #pragma unroll
    for (int mf = 0; mf < 2; mf++) {
        const int lr0 = wm * 32 + mf * 16 + gid;
        #pragma unroll
        for (int nf = 0; nf < 4; nf++) {
            const int cb = wn * 32 + nf * 8 + 2 * tig;
            const float b0v = bias[col0 + cb], b1v = bias[col0 + cb + 1];
            float v0 = (acc[mf][nf][0] + b0v) * sc;
            float v1 = (acc[mf][nf][1] + b1v) * sc;
            float v2 = (acc[mf][nf][2] + b0v) * sc;
            float v3 = (acc[mf][nf][3] + b1v) * sc;
            int rw = row0 + lr0;
            int b = rw >> 9, n = rw & 511;
            size_t u = (((size_t)(b * H_ + hh) * N_ + n) << 6) + (cb >> 1);
            unsigned h0 = pack_hi(v0, v1);
            dH[u] = h0; dL[u] = pack_lo(v0, v1, h0);
            rw += 8; b = rw >> 9; n = rw & 511;
            u = (((size_t)(b * H_ + hh) * N_ + n) << 6) + (cb >> 1);
            unsigned h1 = pack_hi(v2, v3);
            dH[u] = h1; dL[u] = pack_lo(v2, v3, h1);
        }
    }
}

// ---------------------------------------------------------------------------
// Kernel 2: flash attention. 512 threads, 4x4 warp grid, 32x32 per warp.
// Row ownership identical in S and PV phases.
// ---------------------------------------------------------------------------
#define QH_OFF   0
#define QL_OFF   34816
#define KH_OFF   69632
#define KL_OFF   104448
#define PH_OFF   139264
#define PL_OFF   174080
#define MK_OFF   208896
#define MS_OFF   210944
#define LS_OFF   211456
#define WMAX_OFF 211968     /* 4 x 128 f32 */
#define WSUM_OFF 214016     /* 4 x 128 f32 */
#define SMEM_ATTN 216064

__global__ __launch_bounds__(512, 1) void attn_mma_kernel(
    const float* __restrict__ dist, const float* __restrict__ mask)
{
    extern __shared__ char smc[];
    const unsigned sb = smem_u32(smc);
    float* mk   = (float*)(smc + MK_OFF);
    float* m_s  = (float*)(smc + MS_OFF);
    float* l_s  = (float*)(smc + LS_OFF);
    float* wmax = (float*)(smc + WMAX_OFF);
    float* wsum = (float*)(smc + WSUM_OFF);

    const int tid  = threadIdx.x;
    const int lane = tid & 31;
    const int wid  = tid >> 5;
    const int wm   = wid >> 2;
    const int wn   = wid & 3;
    const int gid  = lane >> 2;
    const int tig  = lane & 3;

    const int q0 = blockIdx.x << 7;
    const int bh = blockIdx.y;
    const int b  = bh >> 3;

    for (int i = tid; i < 512; i += 512) mk[i] = mask[b * 512 + i];
    if (tid < 128) { m_s[tid] = -3.0e38f; l_s[tid] = 0.f; }

    copy_tile(g_qh + (((size_t)bh * N_ + q0) << 6), g_ql + (((size_t)bh * N_ + q0) << 6),
              smc, QH_OFF, QL_OFF, 128, tid, 512);

    float o[2][4][4] = {};

    const int a_row = (lane & 15);
    const int a_col = ((lane >> 4) << 3);
    const int b_key = (lane & 7) + ((lane >> 4) << 3);
    const int b_ecol = (((lane >> 3) & 1) << 3);
    const int v_key = (lane & 7) + (((lane >> 3) & 1) << 3);
    const int v_ecol = ((lane >> 4) << 3);

    for (int kt = 0; kt < 4; kt++) {
        const size_t kb = ((size_t)bh * N_ + kt * 128) << 6;
        copy_tile(g_kh + kb, g_kl + kb, smc, KH_OFF, KL_OFF, 128, tid, 512);
        __syncthreads();

        // ---- S = Q K^T ----
        float acc[2][4][4] = {};
        #pragma unroll
        for (int k = 0; k < 8; k++) {
            unsigned ah[2][4], al[2][4], bh4[2][4], bl4[2][4];
            #pragma unroll
            for (int mf = 0; mf < 2; mf++) {
                unsigned ao = (unsigned)((wm * 32 + mf * 16 + a_row) * 272 + (k * 16 + a_col) * 2);
                ldsm4(ah[mf], sb + QH_OFF + ao);
                ldsm4(al[mf], sb + QL_OFF + ao);
            }
            #pragma unroll
            for (int ng = 0; ng < 2; ng++) {
                unsigned bo = (unsigned)((wn * 32 + ng * 16 + b_key) * 272 + (k * 16 + b_ecol) * 2);
                ldsm4(bh4[ng], sb + KH_OFF + bo);
                ldsm4(bl4[ng], sb + KL_OFF + bo);
            }
            #pragma unroll
            for (int ng = 0; ng < 2; ng++)
                #pragma unroll
                for (int mf = 0; mf < 2; mf++) {
                    mma16816(acc[mf][2*ng],   ah[mf], bh4[ng][0], bh4[ng][1]);
                    mma16816(acc[mf][2*ng+1], ah[mf], bh4[ng][2], bh4[ng][3]);
                }
            #pragma unroll
            for (int ng = 0; ng < 2; ng++)
                #pragma unroll
                for (int mf = 0; mf < 2; mf++) {
                    mma16816(acc[mf][2*ng],   ah[mf], bl4[ng][0], bl4[ng][1]);
                    mma16816(acc[mf][2*ng+1], ah[mf], bl4[ng][2], bl4[ng][3]);
                }
            #pragma unroll
            for (int ng = 0; ng < 2; ng++)
                #pragma unroll
                for (int mf = 0; mf < 2; mf++) {
                    mma16816(acc[mf][2*ng],   al[mf], bh4[ng][0], bh4[ng][1]);
                    mma16816(acc[mf][2*ng+1], al[mf], bh4[ng][2], bh4[ng][3]);
                }
        }

        // ---- epilogue: + dist, key mask, row max ----
        float mx[2][2] = {{-3.0e38f, -3.0e38f}, {-3.0e38f, -3.0e38f}};
        #pragma unroll
        for (int mf = 0; mf < 2; mf++) {
            const int lr0 = wm * 32 + mf * 16 + gid;
            #pragma unroll
            for (int nf = 0; nf < 4; nf++) {
                const int cb = wn * 32 + nf * 8 + 2 * tig;
                const int gcol = kt * 128 + cb;
                const float* dp = dist + ((size_t)b * N_ + q0 + lr0) * N_ + gcol;
                float2 d0 = *(const float2*)dp;
                float2 d1 = *(const float2*)(dp + 8 * N_);
                const bool k0 = (mk[gcol] != 0.f), k1 = (mk[gcol + 1] != 0.f);
                float s0 = k0 ? acc[mf][nf][0] + d0.x : NEGV;
                float s1 = k1 ? acc[mf][nf][1] + d0.y : NEGV;
                float s2 = k0 ? acc[mf][nf][2] + d1.x : NEGV;
                float s3 = k1 ? acc[mf][nf][3] + d1.y : NEGV;
                acc[mf][nf][0] = s0; acc[mf][nf][1] = s1;
                acc[mf][nf][2] = s2; acc[mf][nf][3] = s3;
                mx[mf][0] = fmaxf(mx[mf][0], fmaxf(s0, s1));
                mx[mf][1] = fmaxf(mx[mf][1], fmaxf(s2, s3));
            }
        }
        #pragma unroll
        for (int mf = 0; mf < 2; mf++)
            #pragma unroll
            for (int hh = 0; hh < 2; hh++) {
                float m = mx[mf][hh];
                m = fmaxf(m, __shfl_xor_sync(0xffffffffu, m, 1));
                m = fmaxf(m, __shfl_xor_sync(0xffffffffu, m, 2));
                mx[mf][hh] = m;
            }
        if (tig == 0) {
            #pragma unroll
            for (int mf = 0; mf < 2; mf++)
                #pragma unroll
                for (int hh = 0; hh < 2; hh++)
                    wmax[wn * 128 + wm * 32 + mf * 16 + gid + 8 * hh] = mx[mf][hh];
        }
        __syncthreads();   // wmax ready; K smem dead

        const size_t vb = ((size_t)bh * N_ + kt * 128) << 6;
        copy_tile(g_vh + vb, g_vl + vb, smc, KH_OFF, KL_OFF, 128, tid, 512);

        // ---- online stats + P, rescale O with same alpha (same rows) ----
        float mnew[2][2], alph[2][2], rs[2][2] = {};
        #pragma unroll
        for (int mf = 0; mf < 2; mf++)
            #pragma unroll
            for (int hh = 0; hh < 2; hh++) {
                const int r = wm * 32 + mf * 16 + gid + 8 * hh;
                const float mo = m_s[r];
                float mn = fmaxf(fmaxf(wmax[r], wmax[128 + r]),
                                 fmaxf(wmax[256 + r], wmax[384 + r]));
                mn = fmaxf(mn, mo);
                mnew[mf][hh] = mn;
                alph[mf][hh] = __expf(mo - mn);
            }
        #pragma unroll
        for (int mf = 0; mf < 2; mf++) {
            const int lr0 = wm * 32 + mf * 16 + gid;
            #pragma unroll
            for (int nf = 0; nf < 4; nf++) {
                const int cb = wn * 32 + nf * 8 + 2 * tig;
                float p0 = __expf(acc[mf][nf][0] - mnew[mf][0]);
                float p1 = __expf(acc[mf][nf][1] - mnew[mf][0]);
                float p2 = __expf(acc[mf][nf][2] - mnew[mf][1]);
                float p3 = __expf(acc[mf][nf][3] - mnew[mf][1]);
                rs[mf][0] += p0 + p1;
                rs[mf][1] += p2 + p3;
                unsigned hA = pack_hi(p0, p1), hB = pack_hi(p2, p3);
                *(unsigned*)(smc + PH_OFF + lr0 * 272 + cb * 2)       = hA;
                *(unsigned*)(smc + PL_OFF + lr0 * 272 + cb * 2)       = pack_lo(p0, p1, hA);
                *(unsigned*)(smc + PH_OFF + (lr0 + 8) * 272 + cb * 2) = hB;
                *(unsigned*)(smc + PL_OFF + (lr0 + 8) * 272 + cb * 2) = pack_lo(p2, p3, hB);
            }
        }
        #pragma unroll
        for (int mf = 0; mf < 2; mf++)
            #pragma unroll
            for (int hh = 0; hh < 2; hh++) {
                float s = rs[mf][hh];
                s += __shfl_xor_sync(0xffffffffu, s, 1);
                s += __shfl_xor_sync(0xffffffffu, s, 2);
                rs[mf][hh] = s;
            }
        if (tig == 0) {
            #pragma unroll
            for (int mf = 0; mf < 2; mf++)
                #pragma unroll
                for (int hh = 0; hh < 2; hh++)
                    wsum[wn * 128 + wm * 32 + mf * 16 + gid + 8 * hh] = rs[mf][hh];
        }
        // rescale O (rows match S rows)
        #pragma unroll
        for (int nf = 0; nf < 4; nf++)
            #pragma unroll
            for (int mf = 0; mf < 2; mf++) {
                o[mf][nf][0] *= alph[mf][0]; o[mf][nf][1] *= alph[mf][0];
                o[mf][nf][2] *= alph[mf][1]; o[mf][nf][3] *= alph[mf][1];
            }
        __syncthreads();   // P, V, wsum ready; m_s reads done

        if (wn == 0 && tig == 0) {
            #pragma unroll
            for (int mf = 0; mf < 2; mf++)
                #pragma unroll
                for (int hh = 0; hh < 2; hh++) {
                    const int r = wm * 32 + mf * 16 + gid + 8 * hh;
                    m_s[r] = mnew[mf][hh];
                    l_s[r] = alph[mf][hh] * l_s[r]
                           + wsum[r] + wsum[128 + r] + wsum[256 + r] + wsum[384 + r];
                }
        }

        // ---- O += P V ----
        #pragma unroll
        for (int k = 0; k < 8; k++) {
            unsigned ph4[2][4], pl4[2][4], vh4[2][4], vl4[2][4];
            #pragma unroll
            for (int mf = 0; mf < 2; mf++) {
                unsigned po = (unsigned)((wm * 32 + mf * 16 + a_row) * 272 + (k * 16 + a_col) * 2);
                ldsm4(ph4[mf], sb + PH_OFF + po);
                ldsm4(pl4[mf], sb + PL_OFF + po);
            }
            #pragma unroll
            for (int vg = 0; vg < 2; vg++) {
                unsigned vo = (unsigned)((k * 16 + v_key) * 272 + (wn * 32 + vg * 16 + v_ecol) * 2);
                ldsm4t(vh4[vg], sb + KH_OFF + vo);
                ldsm4t(vl4[vg], sb + KL_OFF + vo);
            }
            #pragma unroll
            for (int vg = 0; vg < 2; vg++)
                #pragma unroll
                for (int mf = 0; mf < 2; mf++) {
                    mma16816(o[mf][2*vg],   ph4[mf], vh4[vg][0], vh4[vg][1]);
                    mma16816(o[mf][2*vg+1], ph4[mf], vh4[vg][2], vh4[vg][3]);
                }
            #pragma unroll
            for (int vg = 0; vg < 2; vg++)
                #pragma unroll
                for (int mf = 0; mf < 2; mf++) {
                    mma16816(o[mf][2*vg],   ph4[mf], vl4[vg][0], vl4[vg][1]);
                    mma16816(o[mf][2*vg+1], ph4[mf], vl4[vg][2], vl4[vg][3]);
                }
            #pragma unroll
            for (int vg = 0; vg < 2; vg++)
                #pragma unroll
                for (int mf = 0; mf < 2; mf++) {
                    mma16816(o[mf][2*vg],   pl4[mf], vh4[vg][0], vh4[vg][1]);
                    mma16816(o[mf][2*vg+1], pl4[mf], vh4[vg][2], vh4[vg][3]);
                }
        }
        __syncthreads();
    }

    // ---- normalize, split, store ----
    unsigned* YH = g_yh + (((size_t)bh * N_ + q0) << 6);
    unsigned* YL = g_yl + (((size_t)bh * N_ + q0) << 6);
    #pragma unroll
    for (int mf = 0; mf < 2; mf++) {
        const int r0 = wm * 32 + mf * 16 + gid;
        const float li0 = 1.f / l_s[r0];
        const float li1 = 1.f / l_s[r0 + 8];
        #pragma unroll
        for (int nf = 0; nf < 4; nf++) {
            const int e = wn * 32 + nf * 8 + 2 * tig;
            float v0 = o[mf][nf][0] * li0, v1 = o[mf][nf][1] * li0;
            float v2 = o[mf][nf][2] * li1, v3 = o[mf][nf][3] * li1;
            unsigned h0 = pack_hi(v0, v1), h1 = pack_hi(v2, v3);
            YH[(size_t)r0 * 64 + (e >> 1)]       = h0;
            YL[(size_t)r0 * 64 + (e >> 1)]       = pack_lo(v0, v1, h0);
            YH[(size_t)(r0 + 8) * 64 + (e >> 1)] = h1;
            YL[(size_t)(r0 + 8) * 64 + (e >> 1)] = pack_lo(v2, v3, h1);
        }
    }
}

// ---------------------------------------------------------------------------
// Kernel 3: out = Y @ Wo^T + bo, * mask. 512 threads, 4x4 warp grid.
// ---------------------------------------------------------------------------
#define OG_AH 0
#define OG_AL 17408
#define OG_BH 34816
#define OG_BL 69632
#define SMEM_OPROJ 104448

__global__ __launch_bounds__(512, 1) void oproj_mma_kernel(
    const float* __restrict__ bo,
    const float* __restrict__ mask, float* __restrict__ out)
{
    extern __shared__ char smc[];
    const unsigned sb = smem_u32(smc);

    const int tid  = threadIdx.x;
    const int lane = tid & 31;
    const int wid  = tid >> 5;
    const int wm   = wid >> 2;          // 0..3 -> 16 rows
    const int wn   = wid & 3;           // 0..3 -> 32 cols
    const int gid  = lane >> 2;
    const int tig  = lane & 3;

    const int row0 = blockIdx.x << 6;
    const int b    = row0 >> 9;
    const int n0   = row0 & 511;

    const int a_row = (lane & 15);
    const int a_col = ((lane >> 4) << 3);
    const int b_key = (lane & 7) + ((lane >> 4) << 3);
    const int b_ecol = (((lane >> 3) & 1) << 3);

    float acc[4][4] = {};

    for (int h = 0; h < 8; h++) {
        const size_t ab = ((size_t)(b * H_ + h) * N_ + n0) << 6;
        copy_tile(g_yh + ab, g_yl + ab, smc, OG_AH, OG_AL, 64, tid, 512);
        for (int idx = tid; idx < 2048; idx += 512) {
            int r = idx >> 4, c = idx & 15;
            size_t su = (size_t)r * 512 + h * 64 + c * 4;
            *(uint4*)(smc + OG_BH + r * 272 + c * 16) = *(const uint4*)(g_woh + su);
            *(uint4*)(smc + OG_BL + r * 272 + c * 16) = *(const uint4*)(g_wol + su);
        }
        __syncthreads();

        #pragma unroll
        for (int k = 0; k < 8; k++) {
            unsigned ah[4], al[4], bh4[2][4], bl4[2][4];
            unsigned ao = (unsigned)((wm * 16 + a_row) * 272 + (k * 16 + a_col) * 2);
            ldsm4(ah, sb + OG_AH + ao);
            ldsm4(al, sb + OG_AL + ao);
            #pragma unroll
            for (int ng = 0; ng < 2; ng++) {
                unsigned bo_ = (unsigned)((wn * 32 + ng * 16 + b_key) * 272 + (k * 16 + b_ecol) * 2);
                ldsm4(bh4[ng], sb + OG_BH + bo_);
                ldsm4(bl4[ng], sb + OG_BL + bo_);
            }
            #pragma unroll
            for (int ng = 0; ng < 2; ng++) {
                mma16816(acc[2*ng],   ah, bh4[ng][0], bh4[ng][1]);
                mma16816(acc[2*ng+1], ah, bh4[ng][2], bh4[ng][3]);
            }
            #pragma unroll
            for (int ng = 0; ng < 2; ng++) {
                mma16816(acc[2*ng],   ah, bl4[ng][0], bl4[ng][1]);
                mma16816(acc[2*ng+1], ah, bl4[ng][2], bl4[ng][3]);
            }
            #pragma unroll
            for (int ng = 0; ng < 2; ng++) {
                mma16816(acc[2*ng],   al, bh4[ng][0], bh4[ng][1]);
                mma16816(acc[2*ng+1], al, bh4[ng][2], bh4[ng][3]);
            }
        }
        __syncthreads();
    }

    const int lr0 = wm * 16 + gid;
    const int rw0 = row0 + lr0;
    const float mv0 = mask[b * 512 + (rw0 & 511)];
    const float mv1 = mask[b * 512 + ((rw0 + 8) & 511)];
    #pragma unroll
    for (int nf = 0; nf < 4; nf++) {
        const int cb = wn * 32 + nf * 8 + 2 * tig;
        const float b0v = bo[cb], b1v = bo[cb + 1];
        *(float2*)&out[(size_t)rw0 * E_ + cb] =
            make_float2((acc[nf][0] + b0v) * mv0, (acc[nf][1] + b1v) * mv0);
        *(float2*)&out[(size_t)(rw0 + 8) * E_ + cb] =
            make_float2((acc[nf][2] + b0v) * mv1, (acc[nf][3] + b1v) * mv1);
    }
}

// ---------------------------------------------------------------------------
extern "C" void kernel_launch(void* const* d_in, const int* in_sizes, int n_in,
                              void* d_out, int out_size)
{
    const float* x    = (const float*)d_in[0];
    const float* dist = (const float*)d_in[1];
    const float* mask = (const float*)d_in[2];
    const float* Wq   = (const float*)d_in[3];
    const float* bq   = (const float*)d_in[4];
    const float* Wk   = (const float*)d_in[5];
    const float* bk   = (const float*)d_in[6];
    const float* Wv   = (const float*)d_in[7];
    const float* bv   = (const float*)d_in[8];
    const float* Wo   = (const float*)d_in[9];
    const float* bo   = (const float*)d_in[10];
    float* out = (float*)d_out;

    cudaFuncSetAttribute(qkv_mma_kernel,
                         cudaFuncAttributeMaxDynamicSharedMemorySize, SMEM_QKV);
    cudaFuncSetAttribute(attn_mma_kernel,
                         cudaFuncAttributeMaxDynamicSharedMemorySize, SMEM_ATTN);
    cudaFuncSetAttribute(oproj_mma_kernel,
                         cudaFuncAttributeMaxDynamicSharedMemorySize, SMEM_OPROJ);

    wsplit_kernel<<<256, 256>>>(Wo);
    qkv_mma_kernel<<<dim3(64, 8, 3), 512, SMEM_QKV>>>(x, Wq, bq, Wk, bk, Wv, bv);
    attn_mma_kernel<<<dim3(4, 128), 512, SMEM_ATTN>>>(dist, mask);
    oproj_mma_kernel<<<128, 512, SMEM_OPROJ>>>(bo, mask, out);
}

// round 8
// speedup vs baseline: 1.1227x; 1.1227x over previous
#include <cuda_runtime.h>
#include <cuda_bf16.h>
#include <math.h>

#define B_ 16
#define N_ 512
#define H_ 8
#define E_ 128
#define BH_ (B_*H_)
#define NEGV (-1000000000.0f)
#define SCALE_ 0.08838834764831845f

// Intermediates as packed bf16x2 (unsigned) arrays, hi/lo split pairs.
__device__ unsigned g_qh[BH_*N_*E_/2];
__device__ unsigned g_ql[BH_*N_*E_/2];
__device__ unsigned g_kh[BH_*N_*E_/2];
__device__ unsigned g_kl[BH_*N_*E_/2];
__device__ unsigned g_vh[BH_*N_*E_/2];
__device__ unsigned g_vl[BH_*N_*E_/2];
__device__ unsigned g_yh[BH_*N_*E_/2];
__device__ unsigned g_yl[BH_*N_*E_/2];
__device__ unsigned g_woh[E_*1024/2];
__device__ unsigned g_wol[E_*1024/2];

// ---------------------------------------------------------------------------
// helpers
// ---------------------------------------------------------------------------
__device__ __forceinline__ unsigned smem_u32(const void* p) {
    unsigned r;
    asm("{ .reg .u64 t; cvta.to.shared.u64 t, %1; cvt.u32.u64 %0, t; }" : "=r"(r) : "l"(p));
    return r;
}
__device__ __forceinline__ void ldsm4(unsigned r[4], unsigned addr) {
    asm volatile("ldmatrix.sync.aligned.m8n8.x4.shared.b16 {%0,%1,%2,%3}, [%4];"
        : "=r"(r[0]), "=r"(r[1]), "=r"(r[2]), "=r"(r[3]) : "r"(addr));
}
__device__ __forceinline__ void ldsm4t(unsigned r[4], unsigned addr) {
    asm volatile("ldmatrix.sync.aligned.m8n8.x4.trans.shared.b16 {%0,%1,%2,%3}, [%4];"
        : "=r"(r[0]), "=r"(r[1]), "=r"(r[2]), "=r"(r[3]) : "r"(addr));
}
__device__ __forceinline__ void mma16816(float c[4], const unsigned a[4],
                                         unsigned b0, unsigned b1) {
    asm volatile("mma.sync.aligned.m16n8k16.row.col.f32.bf16.bf16.f32 "
        "{%0,%1,%2,%3}, {%4,%5,%6,%7}, {%8,%9}, {%0,%1,%2,%3};"
        : "+f"(c[0]), "+f"(c[1]), "+f"(c[2]), "+f"(c[3])
        : "r"(a[0]), "r"(a[1]), "r"(a[2]), "r"(a[3]), "r"(b0), "r"(b1));
}
__device__ __forceinline__ unsigned pack_hi(float a, float b) {
    __nv_bfloat162 h = __floats2bfloat162_rn(a, b);
    return *(unsigned*)&h;
}
__device__ __forceinline__ unsigned pack_lo(float a, float b, unsigned hi) {
    __nv_bfloat162 h = *(__nv_bfloat162*)&hi;
    __nv_bfloat162 l = __floats2bfloat162_rn(a - __bfloat162float(__low2bfloat16(h)),
                                             b - __bfloat162float(__high2bfloat16(h)));
    return *(unsigned*)&l;
}

#define CP16(dst, src) \
    asm volatile("cp.async.cg.shared.global [%0], [%1], 16;" \
        :: "r"(dst), "l"(__cvta_generic_to_global(src)) : "memory")
#define CP_COMMIT asm volatile("cp.async.commit_group;" ::: "memory")
#define CP_WAIT0  asm volatile("cp.async.wait_group 0;" ::: "memory")

// fp32 tile -> split bf16 hi/lo smem (272B row stride)
__device__ __forceinline__ void load_split(const float* __restrict__ src,
        size_t stride, char* smc, int offH, int offL, int rows, int tid)
{
    const int total = rows * 32;
    for (int idx = tid; idx < total; idx += 256) {
        int r = idx >> 5, c4 = idx & 31;
        float4 v = *(const float4*)(src + (size_t)r * stride + c4 * 4);
        unsigned h0 = pack_hi(v.x, v.y), h1 = pack_hi(v.z, v.w);
        unsigned l0 = pack_lo(v.x, v.y, h0), l1 = pack_lo(v.z, v.w, h1);
        *(uint2*)(smc + offH + r * 272 + c4 * 8) = make_uint2(h0, h1);
        *(uint2*)(smc + offL + r * 272 + c4 * 8) = make_uint2(l0, l1);
    }
}

// packed-bf16 tile async copy: global (row stride 64 u32) -> smem 272B stride
__device__ __forceinline__ void copy_tile_async(const unsigned* __restrict__ srcH,
        const unsigned* __restrict__ srcL, unsigned sb, int offH, int offL,
        int rows, int tid)
{
    const int total = rows * 16;
    for (int idx = tid; idx < total; idx += 256) {
        int r = idx >> 4, c = idx & 15;
        CP16(sb + offH + r * 272 + c * 16, srcH + (size_t)r * 64 + c * 4);
        CP16(sb + offL + r * 272 + c * 16, srcL + (size_t)r * 64 + c * 4);
    }
}

// ---------------------------------------------------------------------------
// Kernel 0: split Wo into bf16 hi/lo
// ---------------------------------------------------------------------------
__global__ void wsplit_kernel(const float* __restrict__ Wo) {
    int i = blockIdx.x * 256 + threadIdx.x;
    float2 v = *(const float2*)(Wo + 2 * i);
    unsigned h = pack_hi(v.x, v.y);
    g_woh[i] = h;
    g_wol[i] = pack_lo(v.x, v.y, h);
}

// ---------------------------------------------------------------------------
// Kernel 1: QKV projection. 128x64 tile, 256 thr, 2 CTAs/SM.
// ---------------------------------------------------------------------------
#define QG_XH 0
#define QG_XL 34816
#define QG_WH 69632
#define QG_WL 87040
#define SMEM_QKV 104448

__global__ __launch_bounds__(256, 2) void qkv_mma_kernel(
    const float* __restrict__ x,
    const float* __restrict__ Wq, const float* __restrict__ bq,
    const float* __restrict__ Wk, const float* __restrict__ bk,
    const float* __restrict__ Wv, const float* __restrict__ bv)
{
    extern __shared__ char smc[];
    const unsigned sb = smem_u32(smc);

    const int which = blockIdx.z;
    const float* __restrict__ W    = (which == 0) ? Wq : (which == 1) ? Wk : Wv;
    const float* __restrict__ bias = (which == 0) ? bq : (which == 1) ? bk : bv;
    unsigned* __restrict__ dH = (which == 0) ? g_qh : (which == 1) ? g_kh : g_vh;
    unsigned* __restrict__ dL = (which == 0) ? g_ql : (which == 1) ? g_kl : g_vl;

    const int tid  = threadIdx.x;
    const int lane = tid & 31;
    const int wid  = tid >> 5;
    const int wm   = wid >> 1;          // 0..3 -> 32 rows
    const int wn   = wid & 1;           // 0..1 -> 32 cols
    const int gid  = lane >> 2;
    const int tig  = lane & 3;

    const int row0 = blockIdx.x << 7;   // 64 blocks
    const int col0 = blockIdx.y << 6;   // 16 blocks

    const int a_row = (lane & 15);
    const int a_col = ((lane >> 4) << 3);
    const int b_key = (lane & 7) + ((lane >> 4) << 3);
    const int b_ecol = (((lane >> 3) & 1) << 3);

    load_split(x + (size_t)row0 * E_, E_, smc, QG_XH, QG_XL, 128, tid);
    load_split(W + (size_t)col0 * E_, E_, smc, QG_WH, QG_WL, 64, tid);
    __syncthreads();

    float acc[2][4][4] = {};
    #pragma unroll
    for (int k = 0; k < 8; k++) {
        unsigned ah[2][4], al[2][4];
        #pragma unroll
        for (int mf = 0; mf < 2; mf++) {
            unsigned ao = (unsigned)((wm * 32 + mf * 16 + a_row) * 272 + (k * 16 + a_col) * 2);
            ldsm4(ah[mf], sb + QG_XH + ao);
            ldsm4(al[mf], sb + QG_XL + ao);
        }
        #pragma unroll
        for (int ng = 0; ng < 2; ng++) {
            unsigned bo = (unsigned)((wn * 32 + ng * 16 + b_key) * 272 + (k * 16 + b_ecol) * 2);
            unsigned bh4[4], bl4[4];
            ldsm4(bh4, sb + QG_WH + bo);
            ldsm4(bl4, sb + QG_WL + bo);
            #pragma unroll
            for (int mf = 0; mf < 2; mf++) {
                mma16816(acc[mf][2*ng],   ah[mf], bh4[0], bh4[1]);
                mma16816(acc[mf][2*ng],   ah[mf], bl4[0], bl4[1]);
                mma16816(acc[mf][2*ng],   al[mf], bh4[0], bh4[1]);
                mma16816(acc[mf][2*ng+1], ah[mf], bh4[2], bh4[3]);
                mma16816(acc[mf][2*ng+1], ah[mf], bl4[2], bl4[3]);
                mma16816(acc[mf][2*ng+1], al[mf], bh4[2], bh4[3]);
            }
        }
    }

    const float sc = (which == 0) ? SCALE_ : 1.0f;
    #pragma unroll
    for (int mf = 0; mf < 2; mf++) {
        const int lr0 = wm * 32 + mf * 16 + gid;
        #pragma unroll
        for (int nf = 0; nf < 4; nf++) {
            const int cb = wn * 32 + nf * 8 + 2 * tig;
            const int gcol = col0 + cb;
            const int hh = gcol >> 7, ec = gcol & 127;
            const float b0v = bias[gcol], b1v = bias[gcol + 1];
            float v0 = (acc[mf][nf][0] + b0v) * sc;
            float v1 = (acc[mf][nf][1] + b1v) * sc;
            float v2 = (acc[mf][nf][2] + b0v) * sc;
            float v3 = (acc[mf][nf][3] + b1v) * sc;
            int rw = row0 + lr0;
            int b = rw >> 9, n = rw & 511;
            size_t u = (((size_t)(b * H_ + hh) * N_ + n) << 6) + (ec >> 1);
            unsigned h0 = pack_hi(v0, v1);
            dH[u] = h0; dL[u] = pack_lo(v0, v1, h0);
            rw += 8; b = rw >> 9; n = rw & 511;
            u = (((size_t)(b * H_ + hh) * N_ + n) << 6) + (ec >> 1);
            unsigned h1 = pack_hi(v2, v3);
            dH[u] = h1; dL[u] = pack_lo(v2, v3, h1);
        }
    }
}

// ---------------------------------------------------------------------------
// Kernel 2: flash attention. 256 thr, R5 layout, dist staged via cp.async.
// ---------------------------------------------------------------------------
#define QH_OFF   0
#define QL_OFF   34816
#define KH_OFF   69632
#define KL_OFF   104448
#define PH_OFF   139264     /* P hi/lo; also dist staging (stride 528B) */
#define PL_OFF   174080
#define MK_OFF   208896
#define MS_OFF   210944
#define LS_OFF   211456
#define WMAX_OFF 211968
#define WSUM_OFF 212992
#define SMEM_ATTN 214016

__global__ __launch_bounds__(256, 1) void attn_mma_kernel(
    const float* __restrict__ dist, const float* __restrict__ mask)
{
    extern __shared__ char smc[];
    const unsigned sb = smem_u32(smc);
    float* mk   = (float*)(smc + MK_OFF);
    float* m_s  = (float*)(smc + MS_OFF);
    float* l_s  = (float*)(smc + LS_OFF);
    float* wmax = (float*)(smc + WMAX_OFF);
    float* wsum = (float*)(smc + WSUM_OFF);
    float* dsm  = (float*)(smc + PH_OFF);   // dist staging view (132 f stride)

    const int tid  = threadIdx.x;
    const int lane = tid & 31;
    const int wid  = tid >> 5;
    const int wm   = wid >> 1;
    const int wn   = wid & 1;
    const int gid  = lane >> 2;
    const int tig  = lane & 3;

    const int q0 = blockIdx.x << 7;
    const int bh = blockIdx.y;
    const int b  = bh >> 3;

    for (int i = tid; i < 512; i += 256) mk[i] = mask[b * 512 + i];
    if (tid < 128) { m_s[tid] = -3.0e38f; l_s[tid] = 0.f; }

    copy_tile_async(g_qh + (((size_t)bh * N_ + q0) << 6),
                    g_ql + (((size_t)bh * N_ + q0) << 6),
                    sb, QH_OFF, QL_OFF, 128, tid);
    CP_COMMIT;

    float o[16][4] = {};

    const int a_row = (lane & 15);
    const int a_col = ((lane >> 4) << 3);
    const int b_key = (lane & 7) + ((lane >> 4) << 3);
    const int b_ecol = (((lane >> 3) & 1) << 3);
    const int v_key = (lane & 7) + (((lane >> 3) & 1) << 3);
    const int v_ecol = ((lane >> 4) << 3);

    for (int kt = 0; kt < 4; kt++) {
        const size_t kb = ((size_t)bh * N_ + kt * 128) << 6;
        copy_tile_async(g_kh + kb, g_kl + kb, sb, KH_OFF, KL_OFF, 128, tid);
        CP_COMMIT; CP_WAIT0;
        __syncthreads();

        // prefetch dist tile into P region while S-MMA runs
        {
            const float* dsrc = dist + ((size_t)b * N_ + q0) * N_ + kt * 128;
            #pragma unroll
            for (int i = 0; i < 16; i++) {
                int idx = tid + (i << 8);
                int r = idx >> 5, c4 = idx & 31;
                CP16(sb + PH_OFF + r * 528 + c4 * 16, dsrc + (size_t)r * N_ + c4 * 4);
            }
            CP_COMMIT;
        }

        // ---- S = Q K^T (sequential 3-term) ----
        float acc[2][8][4] = {};
        #pragma unroll
        for (int k = 0; k < 8; k++) {
            unsigned ah[2][4], al[2][4];
            #pragma unroll
            for (int mf = 0; mf < 2; mf++) {
                unsigned ao = (unsigned)((wm * 32 + mf * 16 + a_row) * 272 + (k * 16 + a_col) * 2);
                ldsm4(ah[mf], sb + QH_OFF + ao);
                ldsm4(al[mf], sb + QL_OFF + ao);
            }
            #pragma unroll
            for (int ng = 0; ng < 4; ng++) {
                unsigned bo = (unsigned)((wn * 64 + ng * 16 + b_key) * 272 + (k * 16 + b_ecol) * 2);
                unsigned bh4[4], bl4[4];
                ldsm4(bh4, sb + KH_OFF + bo);
                ldsm4(bl4, sb + KL_OFF + bo);
                #pragma unroll
                for (int mf = 0; mf < 2; mf++) {
                    mma16816(acc[mf][2*ng],   ah[mf], bh4[0], bh4[1]);
                    mma16816(acc[mf][2*ng],   ah[mf], bl4[0], bl4[1]);
                    mma16816(acc[mf][2*ng],   al[mf], bh4[0], bh4[1]);
                    mma16816(acc[mf][2*ng+1], ah[mf], bh4[2], bh4[3]);
                    mma16816(acc[mf][2*ng+1], ah[mf], bl4[2], bl4[3]);
                    mma16816(acc[mf][2*ng+1], al[mf], bh4[2], bh4[3]);
                }
            }
        }
        CP_WAIT0;
        __syncthreads();   // dist staged & visible

        // ---- epilogue: + dist(smem), key mask, row max ----
        float mx[2][2] = {{-3.0e38f, -3.0e38f}, {-3.0e38f, -3.0e38f}};
        #pragma unroll
        for (int mf = 0; mf < 2; mf++) {
            const int lr0 = wm * 32 + mf * 16 + gid;
            #pragma unroll
            for (int nf = 0; nf < 8; nf++) {
                const int cb = wn * 64 + nf * 8 + 2 * tig;
                const int gcol = kt * 128 + cb;
                float2 d0 = *(float2*)&dsm[lr0 * 132 + cb];
                float2 d1 = *(float2*)&dsm[(lr0 + 8) * 132 + cb];
                const bool k0 = (mk[gcol] != 0.f), k1 = (mk[gcol + 1] != 0.f);
                float s0 = k0 ? acc[mf][nf][0] + d0.x : NEGV;
                float s1 = k1 ? acc[mf][nf][1] + d0.y : NEGV;
                float s2 = k0 ? acc[mf][nf][2] + d1.x : NEGV;
                float s3 = k1 ? acc[mf][nf][3] + d1.y : NEGV;
                acc[mf][nf][0] = s0; acc[mf][nf][1] = s1;
                acc[mf][nf][2] = s2; acc[mf][nf][3] = s3;
                mx[mf][0] = fmaxf(mx[mf][0], fmaxf(s0, s1));
                mx[mf][1] = fmaxf(mx[mf][1], fmaxf(s2, s3));
            }
        }
        #pragma unroll
        for (int mf = 0; mf < 2; mf++)
            #pragma unroll
            for (int hh = 0; hh < 2; hh++) {
                float m = mx[mf][hh];
                m = fmaxf(m, __shfl_xor_sync(0xffffffffu, m, 1));
                m = fmaxf(m, __shfl_xor_sync(0xffffffffu, m, 2));
                mx[mf][hh] = m;
            }
        if (tig == 0) {
            #pragma unroll
            for (int mf = 0; mf < 2; mf++)
                #pragma unroll
                for (int hh = 0; hh < 2; hh++)
                    wmax[wn * 128 + wm * 32 + mf * 16 + gid + 8 * hh] = mx[mf][hh];
        }
        __syncthreads();   // wmax ready; dist reads done; K smem dead

        // V chunk (async, overlapped with stats/exp below)
        const size_t vb = ((size_t)bh * N_ + kt * 128) << 6;
        copy_tile_async(g_vh + vb, g_vl + vb, sb, KH_OFF, KL_OFF, 128, tid);
        CP_COMMIT;

        // ---- online stats + P = exp(S - m_new) -> P smem (overwrites dist) ----
        float mnew[2][2], alph[2][2], rs[2][2] = {};
        #pragma unroll
        for (int mf = 0; mf < 2; mf++)
            #pragma unroll
            for (int hh = 0; hh < 2; hh++) {
                const int r = wm * 32 + mf * 16 + gid + 8 * hh;
                const float mo = m_s[r];
                const float mn = fmaxf(fmaxf(wmax[r], wmax[128 + r]), mo);
                mnew[mf][hh] = mn;
                alph[mf][hh] = __expf(mo - mn);
            }
        #pragma unroll
        for (int mf = 0; mf < 2; mf++) {
            const int lr0 = wm * 32 + mf * 16 + gid;
            #pragma unroll
            for (int nf = 0; nf < 8; nf++) {
                const int cb = wn * 64 + nf * 8 + 2 * tig;
                float p0 = __expf(acc[mf][nf][0] - mnew[mf][0]);
                float p1 = __expf(acc[mf][nf][1] - mnew[mf][0]);
                float p2 = __expf(acc[mf][nf][2] - mnew[mf][1]);
                float p3 = __expf(acc[mf][nf][3] - mnew[mf][1]);
                rs[mf][0] += p0 + p1;
                rs[mf][1] += p2 + p3;
                unsigned hA = pack_hi(p0, p1), hB = pack_hi(p2, p3);
                *(unsigned*)(smc + PH_OFF + lr0 * 272 + cb * 2)       = hA;
                *(unsigned*)(smc + PL_OFF + lr0 * 272 + cb * 2)       = pack_lo(p0, p1, hA);
                *(unsigned*)(smc + PH_OFF + (lr0 + 8) * 272 + cb * 2) = hB;
                *(unsigned*)(smc + PL_OFF + (lr0 + 8) * 272 + cb * 2) = pack_lo(p2, p3, hB);
            }
        }
        #pragma unroll
        for (int mf = 0; mf < 2; mf++)
            #pragma unroll
            for (int hh = 0; hh < 2; hh++) {
                float s = rs[mf][hh];
                s += __shfl_xor_sync(0xffffffffu, s, 1);
                s += __shfl_xor_sync(0xffffffffu, s, 2);
                rs[mf][hh] = s;
            }
        if (tig == 0) {
            #pragma unroll
            for (int mf = 0; mf < 2; mf++)
                #pragma unroll
                for (int hh = 0; hh < 2; hh++)
                    wsum[wn * 128 + wm * 32 + mf * 16 + gid + 8 * hh] = rs[mf][hh];
        }
        // rescale O accumulators (PV rows: wid*16..)
        {
            const int ro0 = wid * 16 + gid;
            const float mo0 = m_s[ro0];
            const float a0 = __expf(mo0 - fmaxf(fmaxf(wmax[ro0], wmax[128 + ro0]), mo0));
            const int ro1 = ro0 + 8;
            const float mo1 = m_s[ro1];
            const float a1 = __expf(mo1 - fmaxf(fmaxf(wmax[ro1], wmax[128 + ro1]), mo1));
            #pragma unroll
            for (int nf = 0; nf < 16; nf++) {
                o[nf][0] *= a0; o[nf][1] *= a0;
                o[nf][2] *= a1; o[nf][3] *= a1;
            }
        }
        CP_WAIT0;
        __syncthreads();   // P, V, wsum visible; m_s reads done

        if (wn == 0 && tig == 0) {
            #pragma unroll
            for (int mf = 0; mf < 2; mf++)
                #pragma unroll
                for (int hh = 0; hh < 2; hh++) {
                    const int r = wm * 32 + mf * 16 + gid + 8 * hh;
                    m_s[r] = mnew[mf][hh];
                    l_s[r] = alph[mf][hh] * l_s[r] + wsum[r] + wsum[128 + r];
                }
        }

        // ---- O += P V (sequential 3-term) ----
        #pragma unroll
        for (int k = 0; k < 8; k++) {
            unsigned ph4[4], pl4[4];
            unsigned po = (unsigned)((wid * 16 + a_row) * 272 + (k * 16 + a_col) * 2);
            ldsm4(ph4, sb + PH_OFF + po);
            ldsm4(pl4, sb + PL_OFF + po);
            #pragma unroll
            for (int ng = 0; ng < 8; ng++) {
                unsigned vo = (unsigned)((k * 16 + v_key) * 272 + (ng * 16 + v_ecol) * 2);
                unsigned vh4[4], vl4[4];
                ldsm4t(vh4, sb + KH_OFF + vo);
                ldsm4t(vl4, sb + KL_OFF + vo);
                mma16816(o[2*ng],   ph4, vh4[0], vh4[1]);
                mma16816(o[2*ng],   ph4, vl4[0], vl4[1]);
                mma16816(o[2*ng],   pl4, vh4[0], vh4[1]);
                mma16816(o[2*ng+1], ph4, vh4[2], vh4[3]);
                mma16816(o[2*ng+1], ph4, vl4[2], vl4[3]);
                mma16816(o[2*ng+1], pl4, vh4[2], vh4[3]);
            }
        }
        __syncthreads();   // PV done; P region free for next dist stage
    }

    // ---- normalize, split, store packed bf16 hi/lo ----
    const int ro0 = wid * 16 + gid;
    const float li0 = 1.f / l_s[ro0];
    const float li1 = 1.f / l_s[ro0 + 8];
    unsigned* YH = g_yh + (((size_t)bh * N_ + q0) << 6);
    unsigned* YL = g_yl + (((size_t)bh * N_ + q0) << 6);
    #pragma unroll
    for (int nf = 0; nf < 16; nf++) {
        const int e = nf * 8 + 2 * tig;
        float v0 = o[nf][0] * li0, v1 = o[nf][1] * li0;
        float v2 = o[nf][2] * li1, v3 = o[nf][3] * li1;
        unsigned h0 = pack_hi(v0, v1), h1 = pack_hi(v2, v3);
        YH[(size_t)ro0 * 64 + (e >> 1)]       = h0;
        YL[(size_t)ro0 * 64 + (e >> 1)]       = pack_lo(v0, v1, h0);
        YH[(size_t)(ro0 + 8) * 64 + (e >> 1)] = h1;
        YL[(size_t)(ro0 + 8) * 64 + (e >> 1)] = pack_lo(v2, v3, h1);
    }
}

// ---------------------------------------------------------------------------
// Kernel 3: out = Y @ Wo^T + bo, * mask. 64x64 tiles, 3 CTAs/SM, grid 256.
// ---------------------------------------------------------------------------
#define OG_AH 0
#define OG_AL 17408
#define OG_BH 34816
#define OG_BL 52224
#define SMEM_OPROJ 69632

__global__ __launch_bounds__(256, 3) void oproj_mma_kernel(
    const float* __restrict__ bo,
    const float* __restrict__ mask, float* __restrict__ out)
{
    extern __shared__ char smc[];
    const unsigned sb = smem_u32(smc);

    const int tid  = threadIdx.x;
    const int lane = tid & 31;
    const int wid  = tid >> 5;
    const int wm   = wid >> 1;          // 0..3 -> 16 rows
    const int wn   = wid & 1;           // 0..1 -> 32 cols
    const int gid  = lane >> 2;
    const int tig  = lane & 3;

    const int row0 = blockIdx.x << 6;   // 128 row blocks
    const int col0 = blockIdx.y << 6;   // 2 col blocks
    const int b    = row0 >> 9;
    const int n0   = row0 & 511;

    const int a_row = (lane & 15);
    const int a_col = ((lane >> 4) << 3);
    const int b_key = (lane & 7) + ((lane >> 4) << 3);
    const int b_ecol = (((lane >> 3) & 1) << 3);

    float acc[4][4] = {};

    for (int h = 0; h < 8; h++) {
        const size_t ab = ((size_t)(b * H_ + h) * N_ + n0) << 6;
        copy_tile_async(g_yh + ab, g_yl + ab, sb, OG_AH, OG_AL, 64, tid);
        for (int idx = tid; idx < 1024; idx += 256) {
            int r = idx >> 4, c = idx & 15;
            size_t su = (size_t)(col0 + r) * 512 + h * 64 + c * 4;
            CP16(sb + OG_BH + r * 272 + c * 16, g_woh + su);
            CP16(sb + OG_BL + r * 272 + c * 16, g_wol + su);
        }
        CP_COMMIT; CP_WAIT0;
        __syncthreads();

        #pragma unroll
        for (int k = 0; k < 8; k++) {
            unsigned ah[4], al[4];
            unsigned ao = (unsigned)((wm * 16 + a_row) * 272 + (k * 16 + a_col) * 2);
            ldsm4(ah, sb + OG_AH + ao);
            ldsm4(al, sb + OG_AL + ao);
            #pragma unroll
            for (int ng = 0; ng < 2; ng++) {
                unsigned bo_ = (unsigned)((wn * 32 + ng * 16 + b_key) * 272 + (k * 16 + b_ecol) * 2);
                unsigned bh4[4], bl4[4];
                ldsm4(bh4, sb + OG_BH + bo_);
                ldsm4(bl4, sb + OG_BL + bo_);
                mma16816(acc[2*ng],   ah, bh4[0], bh4[1]);
                mma16816(acc[2*ng],   ah, bl4[0], bl4[1]);
                mma16816(acc[2*ng],   al, bh4[0], bh4[1]);
                mma16816(acc[2*ng+1], ah, bh4[2], bh4[3]);
                mma16816(acc[2*ng+1], ah, bl4[2], bl4[3]);
                mma16816(acc[2*ng+1], al, bh4[2], bh4[3]);
            }
        }
        __syncthreads();
    }

    const int lr0 = wm * 16 + gid;
    const int rw0 = row0 + lr0;
    const float mv0 = mask[b * 512 + (rw0 & 511)];
    const float mv1 = mask[b * 512 + ((rw0 + 8) & 511)];
    #pragma unroll
    for (int nf = 0; nf < 4; nf++) {
        const int cb = col0 + wn * 32 + nf * 8 + 2 * tig;
        const float b0v = bo[cb], b1v = bo[cb + 1];
        *(float2*)&out[(size_t)rw0 * E_ + cb] =
            make_float2((acc[nf][0] + b0v) * mv0, (acc[nf][1] + b1v) * mv0);
        *(float2*)&out[(size_t)(rw0 + 8) * E_ + cb] =
            make_float2((acc[nf][2] + b0v) * mv1, (acc[nf][3] + b1v) * mv1);
    }
}

// ---------------------------------------------------------------------------
extern "C" void kernel_launch(void* const* d_in, const int* in_sizes, int n_in,
                              void* d_out, int out_size)
{
    const float* x    = (const float*)d_in[0];
    const float* dist = (const float*)d_in[1];
    const float* mask = (const float*)d_in[2];
    const float* Wq   = (const float*)d_in[3];
    const float* bq   = (const float*)d_in[4];
    const float* Wk   = (const float*)d_in[5];
    const float* bk   = (const float*)d_in[6];
    const float* Wv   = (const float*)d_in[7];
    const float* bv   = (const float*)d_in[8];
    const float* Wo   = (const float*)d_in[9];
    const float* bo   = (const float*)d_in[10];
    float* out = (float*)d_out;

    cudaFuncSetAttribute(qkv_mma_kernel,
                         cudaFuncAttributeMaxDynamicSharedMemorySize, SMEM_QKV);
    cudaFuncSetAttribute(attn_mma_kernel,
                         cudaFuncAttributeMaxDynamicSharedMemorySize, SMEM_ATTN);
    cudaFuncSetAttribute(oproj_mma_kernel,
                         cudaFuncAttributeMaxDynamicSharedMemorySize, SMEM_OPROJ);

    wsplit_kernel<<<256, 256>>>(Wo);
    qkv_mma_kernel<<<dim3(64, 16, 3), 256, SMEM_QKV>>>(x, Wq, bq, Wk, bk, Wv, bv);
    attn_mma_kernel<<<dim3(4, 128), 256, SMEM_ATTN>>>(dist, mask);
    oproj_mma_kernel<<<dim3(128, 2), 256, SMEM_OPROJ>>>(bo, mask, out);
}

// round 9
// speedup vs baseline: 1.5338x; 1.3662x over previous
#include <cuda_runtime.h>
#include <cuda_bf16.h>
#include <cuda_fp16.h>
#include <math.h>

#define B_ 16
#define N_ 512
#define H_ 8
#define E_ 128
#define BH_ (B_*H_)
#define NEGV (-1000000000.0f)
#define SCALE_ 0.08838834764831845f

// q/k/v/y/Wo as packed fp16x2 (unsigned) arrays.
__device__ unsigned g_q16[BH_*N_*E_/2];
__device__ unsigned g_k16[BH_*N_*E_/2];
__device__ unsigned g_v16[BH_*N_*E_/2];
__device__ unsigned g_y16[BH_*N_*E_/2];
__device__ unsigned g_wo16[E_*1024/2];

// ---------------------------------------------------------------------------
// helpers
// ---------------------------------------------------------------------------
__device__ __forceinline__ unsigned smem_u32(const void* p) {
    unsigned r;
    asm("{ .reg .u64 t; cvta.to.shared.u64 t, %1; cvt.u32.u64 %0, t; }" : "=r"(r) : "l"(p));
    return r;
}
__device__ __forceinline__ void ldsm4(unsigned r[4], unsigned addr) {
    asm volatile("ldmatrix.sync.aligned.m8n8.x4.shared.b16 {%0,%1,%2,%3}, [%4];"
        : "=r"(r[0]), "=r"(r[1]), "=r"(r[2]), "=r"(r[3]) : "r"(addr));
}
__device__ __forceinline__ void ldsm4t(unsigned r[4], unsigned addr) {
    asm volatile("ldmatrix.sync.aligned.m8n8.x4.trans.shared.b16 {%0,%1,%2,%3}, [%4];"
        : "=r"(r[0]), "=r"(r[1]), "=r"(r[2]), "=r"(r[3]) : "r"(addr));
}
// bf16 mma (qkv keeps split-bf16 3-term)
__device__ __forceinline__ void mma_bf16(float c[4], const unsigned a[4],
                                         unsigned b0, unsigned b1) {
    asm volatile("mma.sync.aligned.m16n8k16.row.col.f32.bf16.bf16.f32 "
        "{%0,%1,%2,%3}, {%4,%5,%6,%7}, {%8,%9}, {%0,%1,%2,%3};"
        : "+f"(c[0]), "+f"(c[1]), "+f"(c[2]), "+f"(c[3])
        : "r"(a[0]), "r"(a[1]), "r"(a[2]), "r"(a[3]), "r"(b0), "r"(b1));
}
// fp16 mma (attention + oproj, single term)
__device__ __forceinline__ void mma_f16(float c[4], const unsigned a[4],
                                        unsigned b0, unsigned b1) {
    asm volatile("mma.sync.aligned.m16n8k16.row.col.f32.f16.f16.f32 "
        "{%0,%1,%2,%3}, {%4,%5,%6,%7}, {%8,%9}, {%0,%1,%2,%3};"
        : "+f"(c[0]), "+f"(c[1]), "+f"(c[2]), "+f"(c[3])
        : "r"(a[0]), "r"(a[1]), "r"(a[2]), "r"(a[3]), "r"(b0), "r"(b1));
}
__device__ __forceinline__ unsigned pack_bh(float a, float b) {
    __nv_bfloat162 h = __floats2bfloat162_rn(a, b);
    return *(unsigned*)&h;
}
__device__ __forceinline__ unsigned pack_bl(float a, float b, unsigned hi) {
    __nv_bfloat162 h = *(__nv_bfloat162*)&hi;
    __nv_bfloat162 l = __floats2bfloat162_rn(a - __bfloat162float(__low2bfloat16(h)),
                                             b - __bfloat162float(__high2bfloat16(h)));
    return *(unsigned*)&l;
}
__device__ __forceinline__ unsigned pack_h2(float a, float b) {
    __half2 h = __floats2half2_rn(a, b);
    return *(unsigned*)&h;
}

#define CP16(dst, src) \
    asm volatile("cp.async.cg.shared.global [%0], [%1], 16;" \
        :: "r"(dst), "l"(__cvta_generic_to_global(src)) : "memory")
#define CP_COMMIT asm volatile("cp.async.commit_group;" ::: "memory")
#define CP_WAIT0  asm volatile("cp.async.wait_group 0;" ::: "memory")
#define CP_WAIT1  asm volatile("cp.async.wait_group 1;" ::: "memory")

// fp32 tile -> split bf16 hi/lo smem (272B row stride); qkv only
__device__ __forceinline__ void load_split(const float* __restrict__ src,
        size_t stride, char* smc, int offH, int offL, int rows, int tid)
{
    const int total = rows * 32;
    for (int idx = tid; idx < total; idx += 256) {
        int r = idx >> 5, c4 = idx & 31;
        float4 v = *(const float4*)(src + (size_t)r * stride + c4 * 4);
        unsigned h0 = pack_bh(v.x, v.y), h1 = pack_bh(v.z, v.w);
        unsigned l0 = pack_bl(v.x, v.y, h0), l1 = pack_bl(v.z, v.w, h1);
        *(uint2*)(smc + offH + r * 272 + c4 * 8) = make_uint2(h0, h1);
        *(uint2*)(smc + offL + r * 272 + c4 * 8) = make_uint2(l0, l1);
    }
}

// packed-fp16 tile async copy: global (row stride 64 u32) -> smem 272B stride
__device__ __forceinline__ void copy16_async(const unsigned* __restrict__ src,
        unsigned sb, int off, int rows, int tid)
{
    const int total = rows * 16;
    for (int idx = tid; idx < total; idx += 256) {
        int r = idx >> 4, c = idx & 15;
        CP16(sb + off + r * 272 + c * 16, src + (size_t)r * 64 + c * 4);
    }
}

// ---------------------------------------------------------------------------
// Kernel 0: convert Wo to packed fp16
// ---------------------------------------------------------------------------
__global__ void wsplit_kernel(const float* __restrict__ Wo) {
    int i = blockIdx.x * 256 + threadIdx.x;
    float2 v = *(const float2*)(Wo + 2 * i);
    g_wo16[i] = pack_h2(v.x, v.y);
}

// ---------------------------------------------------------------------------
// Kernel 1: QKV projection (3-term split-bf16, R5 structure = 71.5us proven).
// Outputs q(scaled)/k/v as packed fp16.
// ---------------------------------------------------------------------------
#define QG_XH 0
#define QG_XL 34816
#define QG_WH 69632
#define QG_WL 104448
#define SMEM_QKV 139264

__global__ __launch_bounds__(256, 1) void qkv_mma_kernel(
    const float* __restrict__ x,
    const float* __restrict__ Wq, const float* __restrict__ bq,
    const float* __restrict__ Wk, const float* __restrict__ bk,
    const float* __restrict__ Wv, const float* __restrict__ bv)
{
    extern __shared__ char smc[];
    const unsigned sb = smem_u32(smc);

    const int which = blockIdx.z;
    const float* __restrict__ W    = (which == 0) ? Wq : (which == 1) ? Wk : Wv;
    const float* __restrict__ bias = (which == 0) ? bq : (which == 1) ? bk : bv;
    unsigned* __restrict__ dst = (which == 0) ? g_q16 : (which == 1) ? g_k16 : g_v16;

    const int tid  = threadIdx.x;
    const int lane = tid & 31;
    const int wid  = tid >> 5;
    const int wm   = wid >> 1;
    const int wn   = wid & 1;
    const int gid  = lane >> 2;
    const int tig  = lane & 3;

    const int row0 = blockIdx.x << 7;
    const int col0 = blockIdx.y << 7;

    const int a_row = (lane & 15);
    const int a_col = ((lane >> 4) << 3);
    const int b_key = (lane & 7) + ((lane >> 4) << 3);
    const int b_ecol = (((lane >> 3) & 1) << 3);

    load_split(x + (size_t)row0 * E_, E_, smc, QG_XH, QG_XL, 128, tid);
    load_split(W + (size_t)col0 * E_, E_, smc, QG_WH, QG_WL, 128, tid);
    __syncthreads();

    float acc[2][8][4] = {};
    #pragma unroll
    for (int k = 0; k < 8; k++) {
        unsigned ah[2][4], al[2][4];
        #pragma unroll
        for (int mf = 0; mf < 2; mf++) {
            unsigned ao = (unsigned)((wm * 32 + mf * 16 + a_row) * 272 + (k * 16 + a_col) * 2);
            ldsm4(ah[mf], sb + QG_XH + ao);
            ldsm4(al[mf], sb + QG_XL + ao);
        }
        #pragma unroll
        for (int ng = 0; ng < 4; ng++) {
            unsigned bo = (unsigned)((wn * 64 + ng * 16 + b_key) * 272 + (k * 16 + b_ecol) * 2);
            unsigned bh4[4], bl4[4];
            ldsm4(bh4, sb + QG_WH + bo);
            ldsm4(bl4, sb + QG_WL + bo);
            #pragma unroll
            for (int mf = 0; mf < 2; mf++) {
                mma_bf16(acc[mf][2*ng],   ah[mf], bh4[0], bh4[1]);
                mma_bf16(acc[mf][2*ng],   ah[mf], bl4[0], bl4[1]);
                mma_bf16(acc[mf][2*ng],   al[mf], bh4[0], bh4[1]);
                mma_bf16(acc[mf][2*ng+1], ah[mf], bh4[2], bh4[3]);
                mma_bf16(acc[mf][2*ng+1], ah[mf], bl4[2], bl4[3]);
                mma_bf16(acc[mf][2*ng+1], al[mf], bh4[2], bh4[3]);
            }
        }
    }

    const int hh = col0 >> 7;
    const float sc = (which == 0) ? SCALE_ : 1.0f;
    #pragma unroll
    for (int mf = 0; mf < 2; mf++) {
        const int lr0 = wm * 32 + mf * 16 + gid;
        #pragma unroll
        for (int nf = 0; nf < 8; nf++) {
            const int cb = wn * 64 + nf * 8 + 2 * tig;
            const float b0v = bias[col0 + cb], b1v = bias[col0 + cb + 1];
            float v0 = (acc[mf][nf][0] + b0v) * sc;
            float v1 = (acc[mf][nf][1] + b1v) * sc;
            float v2 = (acc[mf][nf][2] + b0v) * sc;
            float v3 = (acc[mf][nf][3] + b1v) * sc;
            int rw = row0 + lr0;
            int b = rw >> 9, n = rw & 511;
            dst[(((size_t)(b * H_ + hh) * N_ + n) << 6) + (cb >> 1)] = pack_h2(v0, v1);
            rw += 8; b = rw >> 9; n = rw & 511;
            dst[(((size_t)(b * H_ + hh) * N_ + n) << 6) + (cb >> 1)] = pack_h2(v2, v3);
        }
    }
}

// ---------------------------------------------------------------------------
// Kernel 2: flash attention, single-term fp16. 256 thr, 1 CTA/SM.
// smem: Q 34816 | K 34816 | V 34816 | P 34816 | dist 67584 | stats
// ---------------------------------------------------------------------------
#define AQ_OFF   0
#define AK_OFF   34816
#define AV_OFF   69632
#define AP_OFF   104448
#define AD_OFF   139264
#define AMK_OFF  206848
#define AMS_OFF  208896
#define ALS_OFF  209408
#define AWMAX    209920
#define AWSUM    210944
#define SMEM_ATTN 211968

__global__ __launch_bounds__(256, 1) void attn_mma_kernel(
    const float* __restrict__ dist, const float* __restrict__ mask)
{
    extern __shared__ char smc[];
    const unsigned sb = smem_u32(smc);
    float* mk   = (float*)(smc + AMK_OFF);
    float* m_s  = (float*)(smc + AMS_OFF);
    float* l_s  = (float*)(smc + ALS_OFF);
    float* wmax = (float*)(smc + AWMAX);
    float* wsum = (float*)(smc + AWSUM);
    float* dsm  = (float*)(smc + AD_OFF);   // 132-float row stride

    const int tid  = threadIdx.x;
    const int lane = tid & 31;
    const int wid  = tid >> 5;
    const int wm   = wid >> 1;
    const int wn   = wid & 1;
    const int gid  = lane >> 2;
    const int tig  = lane & 3;

    const int q0 = blockIdx.x << 7;
    const int bh = blockIdx.y;
    const int b  = bh >> 3;

    for (int i = tid; i < 512; i += 256) mk[i] = mask[b * 512 + i];
    if (tid < 128) { m_s[tid] = -3.0e38f; l_s[tid] = 0.f; }

    copy16_async(g_q16 + (((size_t)bh * N_ + q0) << 6), sb, AQ_OFF, 128, tid);
    CP_COMMIT;                                                    // group: Q
    copy16_async(g_k16 + (((size_t)bh * N_) << 6), sb, AK_OFF, 128, tid);
    copy16_async(g_v16 + (((size_t)bh * N_) << 6), sb, AV_OFF, 128, tid);
    CP_COMMIT;                                                    // group: KV0

    float o[16][4] = {};

    const int a_row = (lane & 15);
    const int a_col = ((lane >> 4) << 3);
    const int b_key = (lane & 7) + ((lane >> 4) << 3);
    const int b_ecol = (((lane >> 3) & 1) << 3);
    const int v_key = (lane & 7) + (((lane >> 3) & 1) << 3);
    const int v_ecol = ((lane >> 4) << 3);

    for (int kt = 0; kt < 4; kt++) {
        // prefetch dist tile (hidden under S-MMA)
        {
            const float* dsrc = dist + ((size_t)b * N_ + q0) * N_ + kt * 128;
            #pragma unroll
            for (int i = 0; i < 16; i++) {
                int idx = tid + (i << 8);
                int r = idx >> 5, c4 = idx & 31;
                CP16(sb + AD_OFF + r * 528 + c4 * 16, dsrc + (size_t)r * N_ + c4 * 4);
            }
            CP_COMMIT;                                            // group: dist
        }
        CP_WAIT1;          // Q + K/V(kt) arrived (dist may be in flight)
        __syncthreads();

        // ---- S = Q K^T (fp16, 1 term) ----
        float acc[2][8][4] = {};
        #pragma unroll
        for (int k = 0; k < 8; k++) {
            unsigned ah[2][4];
            #pragma unroll
            for (int mf = 0; mf < 2; mf++) {
                unsigned ao = (unsigned)((wm * 32 + mf * 16 + a_row) * 272 + (k * 16 + a_col) * 2);
                ldsm4(ah[mf], sb + AQ_OFF + ao);
            }
            #pragma unroll
            for (int ng = 0; ng < 4; ng++) {
                unsigned bo = (unsigned)((wn * 64 + ng * 16 + b_key) * 272 + (k * 16 + b_ecol) * 2);
                unsigned bh4[4];
                ldsm4(bh4, sb + AK_OFF + bo);
                #pragma unroll
                for (int mf = 0; mf < 2; mf++) {
                    mma_f16(acc[mf][2*ng],   ah[mf], bh4[0], bh4[1]);
                    mma_f16(acc[mf][2*ng+1], ah[mf], bh4[2], bh4[3]);
                }
            }
        }
        CP_WAIT0;          // dist staged
        __syncthreads();

        // ---- epilogue: + dist(smem), key mask, row max ----
        float mx[2][2] = {{-3.0e38f, -3.0e38f}, {-3.0e38f, -3.0e38f}};
        #pragma unroll
        for (int mf = 0; mf < 2; mf++) {
            const int lr0 = wm * 32 + mf * 16 + gid;
            #pragma unroll
            for (int nf = 0; nf < 8; nf++) {
                const int cb = wn * 64 + nf * 8 + 2 * tig;
                const int gcol = kt * 128 + cb;
                float2 d0 = *(float2*)&dsm[lr0 * 132 + cb];
                float2 d1 = *(float2*)&dsm[(lr0 + 8) * 132 + cb];
                const bool k0 = (mk[gcol] != 0.f), k1 = (mk[gcol + 1] != 0.f);
                float s0 = k0 ? acc[mf][nf][0] + d0.x : NEGV;
                float s1 = k1 ? acc[mf][nf][1] + d0.y : NEGV;
                float s2 = k0 ? acc[mf][nf][2] + d1.x : NEGV;
                float s3 = k1 ? acc[mf][nf][3] + d1.y : NEGV;
                acc[mf][nf][0] = s0; acc[mf][nf][1] = s1;
                acc[mf][nf][2] = s2; acc[mf][nf][3] = s3;
                mx[mf][0] = fmaxf(mx[mf][0], fmaxf(s0, s1));
                mx[mf][1] = fmaxf(mx[mf][1], fmaxf(s2, s3));
            }
        }
        #pragma unroll
        for (int mf = 0; mf < 2; mf++)
            #pragma unroll
            for (int hh = 0; hh < 2; hh++) {
                float m = mx[mf][hh];
                m = fmaxf(m, __shfl_xor_sync(0xffffffffu, m, 1));
                m = fmaxf(m, __shfl_xor_sync(0xffffffffu, m, 2));
                mx[mf][hh] = m;
            }
        if (tig == 0) {
            #pragma unroll
            for (int mf = 0; mf < 2; mf++)
                #pragma unroll
                for (int hh = 0; hh < 2; hh++)
                    wmax[wn * 128 + wm * 32 + mf * 16 + gid + 8 * hh] = mx[mf][hh];
        }
        __syncthreads();

        // ---- online stats + P = exp(S - m_new) -> fp16 smem ----
        float mnew[2][2], alph[2][2], rs[2][2] = {};
        #pragma unroll
        for (int mf = 0; mf < 2; mf++)
            #pragma unroll
            for (int hh = 0; hh < 2; hh++) {
                const int r = wm * 32 + mf * 16 + gid + 8 * hh;
                const float mo = m_s[r];
                const float mn = fmaxf(fmaxf(wmax[r], wmax[128 + r]), mo);
                mnew[mf][hh] = mn;
                alph[mf][hh] = __expf(mo - mn);
            }
        #pragma unroll
        for (int mf = 0; mf < 2; mf++) {
            const int lr0 = wm * 32 + mf * 16 + gid;
            #pragma unroll
            for (int nf = 0; nf < 8; nf++) {
                const int cb = wn * 64 + nf * 8 + 2 * tig;
                float p0 = __expf(acc[mf][nf][0] - mnew[mf][0]);
                float p1 = __expf(acc[mf][nf][1] - mnew[mf][0]);
                float p2 = __expf(acc[mf][nf][2] - mnew[mf][1]);
                float p3 = __expf(acc[mf][nf][3] - mnew[mf][1]);
                rs[mf][0] += p0 + p1;
                rs[mf][1] += p2 + p3;
                *(unsigned*)(smc + AP_OFF + lr0 * 272 + cb * 2)       = pack_h2(p0, p1);
                *(unsigned*)(smc + AP_OFF + (lr0 + 8) * 272 + cb * 2) = pack_h2(p2, p3);
            }
        }
        #pragma unroll
        for (int mf = 0; mf < 2; mf++)
            #pragma unroll
            for (int hh = 0; hh < 2; hh++) {
                float s = rs[mf][hh];
                s += __shfl_xor_sync(0xffffffffu, s, 1);
                s += __shfl_xor_sync(0xffffffffu, s, 2);
                rs[mf][hh] = s;
            }
        if (tig == 0) {
            #pragma unroll
            for (int mf = 0; mf < 2; mf++)
                #pragma unroll
                for (int hh = 0; hh < 2; hh++)
                    wsum[wn * 128 + wm * 32 + mf * 16 + gid + 8 * hh] = rs[mf][hh];
        }
        // rescale O accumulators (PV rows: wid*16..)
        {
            const int ro0 = wid * 16 + gid;
            const float mo0 = m_s[ro0];
            const float a0 = __expf(mo0 - fmaxf(fmaxf(wmax[ro0], wmax[128 + ro0]), mo0));
            const int ro1 = ro0 + 8;
            const float mo1 = m_s[ro1];
            const float a1 = __expf(mo1 - fmaxf(fmaxf(wmax[ro1], wmax[128 + ro1]), mo1));
            #pragma unroll
            for (int nf = 0; nf < 16; nf++) {
                o[nf][0] *= a0; o[nf][1] *= a0;
                o[nf][2] *= a1; o[nf][3] *= a1;
            }
        }
        __syncthreads();

        if (wn == 0 && tig == 0) {
            #pragma unroll
            for (int mf = 0; mf < 2; mf++)
                #pragma unroll
                for (int hh = 0; hh < 2; hh++) {
                    const int r = wm * 32 + mf * 16 + gid + 8 * hh;
                    m_s[r] = mnew[mf][hh];
                    l_s[r] = alph[mf][hh] * l_s[r] + wsum[r] + wsum[128 + r];
                }
        }

        // ---- O += P V (fp16, 1 term) ----
        #pragma unroll
        for (int k = 0; k < 8; k++) {
            unsigned ph4[4];
            unsigned po = (unsigned)((wid * 16 + a_row) * 272 + (k * 16 + a_col) * 2);
            ldsm4(ph4, sb + AP_OFF + po);
            #pragma unroll
            for (int ng = 0; ng < 8; ng++) {
                unsigned vo = (unsigned)((k * 16 + v_key) * 272 + (ng * 16 + v_ecol) * 2);
                unsigned vh4[4];
                ldsm4t(vh4, sb + AV_OFF + vo);
                mma_f16(o[2*ng],   ph4, vh4[0], vh4[1]);
                mma_f16(o[2*ng+1], ph4, vh4[2], vh4[3]);
            }
        }
        __syncthreads();

        // next chunk's K/V
        if (kt < 3) {
            const size_t nb = ((size_t)bh * N_ + (kt + 1) * 128) << 6;
            copy16_async(g_k16 + nb, sb, AK_OFF, 128, tid);
            copy16_async(g_v16 + nb, sb, AV_OFF, 128, tid);
            CP_COMMIT;
        }
    }

    // ---- normalize, store packed fp16 ----
    const int ro0 = wid * 16 + gid;
    const float li0 = 1.f / l_s[ro0];
    const float li1 = 1.f / l_s[ro0 + 8];
    unsigned* Y = g_y16 + (((size_t)bh * N_ + q0) << 6);
    #pragma unroll
    for (int nf = 0; nf < 16; nf++) {
        const int e = nf * 8 + 2 * tig;
        Y[(size_t)ro0 * 64 + (e >> 1)]       = pack_h2(o[nf][0] * li0, o[nf][1] * li0);
        Y[(size_t)(ro0 + 8) * 64 + (e >> 1)] = pack_h2(o[nf][2] * li1, o[nf][3] * li1);
    }
}

// ---------------------------------------------------------------------------
// Kernel 3: out = Y @ Wo^T + bo, * mask. fp16 1-term, 64x64 tiles, grid 256.
// ---------------------------------------------------------------------------
#define OG_A 0
#define OG_B 17408
#define SMEM_OPROJ 34816

__global__ __launch_bounds__(256, 3) void oproj_mma_kernel(
    const float* __restrict__ bo,
    const float* __restrict__ mask, float* __restrict__ out)
{
    extern __shared__ char smc[];
    const unsigned sb = smem_u32(smc);

    const int tid  = threadIdx.x;
    const int lane = tid & 31;
    const int wid  = tid >> 5;
    const int wm   = wid >> 1;
    const int wn   = wid & 1;
    const int gid  = lane >> 2;
    const int tig  = lane & 3;

    const int row0 = blockIdx.x << 6;
    const int col0 = blockIdx.y << 6;
    const int b    = row0 >> 9;
    const int n0   = row0 & 511;

    const int a_row = (lane & 15);
    const int a_col = ((lane >> 4) << 3);
    const int b_key = (lane & 7) + ((lane >> 4) << 3);
    const int b_ecol = (((lane >> 3) & 1) << 3);

    float acc[4][4] = {};

    for (int h = 0; h < 8; h++) {
        const size_t ab = ((size_t)(b * H_ + h) * N_ + n0) << 6;
        copy16_async(g_y16 + ab, sb, OG_A, 64, tid);
        for (int idx = tid; idx < 1024; idx += 256) {
            int r = idx >> 4, c = idx & 15;
            size_t su = (size_t)(col0 + r) * 512 + h * 64 + c * 4;
            CP16(sb + OG_B + r * 272 + c * 16, g_wo16 + su);
        }
        CP_COMMIT; CP_WAIT0;
        __syncthreads();

        #pragma unroll
        for (int k = 0; k < 8; k++) {
            unsigned ah[4];
            unsigned ao = (unsigned)((wm * 16 + a_row) * 272 + (k * 16 + a_col) * 2);
            ldsm4(ah, sb + OG_A + ao);
            #pragma unroll
            for (int ng = 0; ng < 2; ng++) {
                unsigned bo_ = (unsigned)((wn * 32 + ng * 16 + b_key) * 272 + (k * 16 + b_ecol) * 2);
                unsigned bh4[4];
                ldsm4(bh4, sb + OG_B + bo_);
                mma_f16(acc[2*ng],   ah, bh4[0], bh4[1]);
                mma_f16(acc[2*ng+1], ah, bh4[2], bh4[3]);
            }
        }
        __syncthreads();
    }

    const int lr0 = wm * 16 + gid;
    const int rw0 = row0 + lr0;
    const float mv0 = mask[b * 512 + (rw0 & 511)];
    const float mv1 = mask[b * 512 + ((rw0 + 8) & 511)];
    #pragma unroll
    for (int nf = 0; nf < 4; nf++) {
        const int cb = col0 + wn * 32 + nf * 8 + 2 * tig;
        const float b0v = bo[cb], b1v = bo[cb + 1];
        *(float2*)&out[(size_t)rw0 * E_ + cb] =
            make_float2((acc[nf][0] + b0v) * mv0, (acc[nf][1] + b1v) * mv0);
        *(float2*)&out[(size_t)(rw0 + 8) * E_ + cb] =
            make_float2((acc[nf][2] + b0v) * mv1, (acc[nf][3] + b1v) * mv1);
    }
}

// ---------------------------------------------------------------------------
extern "C" void kernel_launch(void* const* d_in, const int* in_sizes, int n_in,
                              void* d_out, int out_size)
{
    const float* x    = (const float*)d_in[0];
    const float* dist = (const float*)d_in[1];
    const float* mask = (const float*)d_in[2];
    const float* Wq   = (const float*)d_in[3];
    const float* bq   = (const float*)d_in[4];
    const float* Wk   = (const float*)d_in[5];
    const float* bk   = (const float*)d_in[6];
    const float* Wv   = (const float*)d_in[7];
    const float* bv   = (const float*)d_in[8];
    const float* Wo   = (const float*)d_in[9];
    const float* bo   = (const float*)d_in[10];
    float* out = (float*)d_out;

    cudaFuncSetAttribute(qkv_mma_kernel,
                         cudaFuncAttributeMaxDynamicSharedMemorySize, SMEM_QKV);
    cudaFuncSetAttribute(attn_mma_kernel,
                         cudaFuncAttributeMaxDynamicSharedMemorySize, SMEM_ATTN);
    cudaFuncSetAttribute(oproj_mma_kernel,
                         cudaFuncAttributeMaxDynamicSharedMemorySize, SMEM_OPROJ);

    wsplit_kernel<<<256, 256>>>(Wo);
    qkv_mma_kernel<<<dim3(64, 8, 3), 256, SMEM_QKV>>>(x, Wq, bq, Wk, bk, Wv, bv);
    attn_mma_kernel<<<dim3(4, 128), 256, SMEM_ATTN>>>(dist, mask);
    oproj_mma_kernel<<<dim3(128, 2), 256, SMEM_OPROJ>>>(bo, mask, out);
}

// round 10
// speedup vs baseline: 2.2124x; 1.4424x over previous
#include <cuda_runtime.h>
#include <cuda_bf16.h>
#include <cuda_fp16.h>
#include <math.h>

#define B_ 16
#define N_ 512
#define H_ 8
#define E_ 128
#define BH_ (B_*H_)
#define NEGV (-1000000000.0f)
#define SCALE_ 0.08838834764831845f
#define LOG2E_ 1.4426950408889634f
#define QSCALE_ (SCALE_ * LOG2E_)

// q/k/v/y/Wo as packed fp16x2 (unsigned) arrays.
__device__ unsigned g_q16[BH_*N_*E_/2];
__device__ unsigned g_k16[BH_*N_*E_/2];
__device__ unsigned g_v16[BH_*N_*E_/2];
__device__ unsigned g_y16[BH_*N_*E_/2];
__device__ unsigned g_wo16[E_*1024/2];

// ---------------------------------------------------------------------------
// helpers
// ---------------------------------------------------------------------------
__device__ __forceinline__ unsigned smem_u32(const void* p) {
    unsigned r;
    asm("{ .reg .u64 t; cvta.to.shared.u64 t, %1; cvt.u32.u64 %0, t; }" : "=r"(r) : "l"(p));
    return r;
}
__device__ __forceinline__ void ldsm4(unsigned r[4], unsigned addr) {
    asm volatile("ldmatrix.sync.aligned.m8n8.x4.shared.b16 {%0,%1,%2,%3}, [%4];"
        : "=r"(r[0]), "=r"(r[1]), "=r"(r[2]), "=r"(r[3]) : "r"(addr));
}
__device__ __forceinline__ void ldsm4t(unsigned r[4], unsigned addr) {
    asm volatile("ldmatrix.sync.aligned.m8n8.x4.trans.shared.b16 {%0,%1,%2,%3}, [%4];"
        : "=r"(r[0]), "=r"(r[1]), "=r"(r[2]), "=r"(r[3]) : "r"(addr));
}
__device__ __forceinline__ void mma_f16(float c[4], const unsigned a[4],
                                        unsigned b0, unsigned b1) {
    asm volatile("mma.sync.aligned.m16n8k16.row.col.f32.f16.f16.f32 "
        "{%0,%1,%2,%3}, {%4,%5,%6,%7}, {%8,%9}, {%0,%1,%2,%3};"
        : "+f"(c[0]), "+f"(c[1]), "+f"(c[2]), "+f"(c[3])
        : "r"(a[0]), "r"(a[1]), "r"(a[2]), "r"(a[3]), "r"(b0), "r"(b1));
}
__device__ __forceinline__ unsigned pack_h2(float a, float b) {
    __half2 h = __floats2half2_rn(a, b);
    return *(unsigned*)&h;
}
__device__ __forceinline__ float ex2f(float x) {
    float r;
    asm("ex2.approx.f32 %0, %1;" : "=f"(r) : "f"(x));
    return r;
}

#define CP16(dst, src) \
    asm volatile("cp.async.cg.shared.global [%0], [%1], 16;" \
        :: "r"(dst), "l"(__cvta_generic_to_global(src)) : "memory")
#define CP_COMMIT asm volatile("cp.async.commit_group;" ::: "memory")
#define CP_WAIT0  asm volatile("cp.async.wait_group 0;" ::: "memory")
#define CP_WAIT1  asm volatile("cp.async.wait_group 1;" ::: "memory")

// fp32 tile -> fp16 smem (272B row stride)
__device__ __forceinline__ void load_h16(const float* __restrict__ src,
        size_t stride, char* smc, int off, int rows, int tid)
{
    const int total = rows * 32;
    for (int idx = tid; idx < total; idx += 256) {
        int r = idx >> 5, c4 = idx & 31;
        float4 v = *(const float4*)(src + (size_t)r * stride + c4 * 4);
        *(uint2*)(smc + off + r * 272 + c4 * 8) =
            make_uint2(pack_h2(v.x, v.y), pack_h2(v.z, v.w));
    }
}

// packed-fp16 tile async copy: global (row stride 64 u32) -> smem 272B stride
__device__ __forceinline__ void copy16_async(const unsigned* __restrict__ src,
        unsigned sb, int off, int rows, int tid)
{
    const int total = rows * 16;
    for (int idx = tid; idx < total; idx += 256) {
        int r = idx >> 4, c = idx & 15;
        CP16(sb + off + r * 272 + c * 16, src + (size_t)r * 64 + c * 4);
    }
}

// ---------------------------------------------------------------------------
// Kernel 0: convert Wo to packed fp16
// ---------------------------------------------------------------------------
__global__ void wsplit_kernel(const float* __restrict__ Wo) {
    int i = blockIdx.x * 256 + threadIdx.x;
    float2 v = *(const float2*)(Wo + 2 * i);
    g_wo16[i] = pack_h2(v.x, v.y);
}

// ---------------------------------------------------------------------------
// Kernel 1: QKV projection, 1-term fp16 mma. 128x128 tile, 2 CTAs/SM.
// q pre-scaled by SCALE*log2(e).
// ---------------------------------------------------------------------------
#define QG_X 0
#define QG_W 34816
#define SMEM_QKV 69632

__global__ __launch_bounds__(256, 2) void qkv_mma_kernel(
    const float* __restrict__ x,
    const float* __restrict__ Wq, const float* __restrict__ bq,
    const float* __restrict__ Wk, const float* __restrict__ bk,
    const float* __restrict__ Wv, const float* __restrict__ bv)
{
    extern __shared__ char smc[];
    const unsigned sb = smem_u32(smc);

    const int which = blockIdx.z;
    const float* __restrict__ W    = (which == 0) ? Wq : (which == 1) ? Wk : Wv;
    const float* __restrict__ bias = (which == 0) ? bq : (which == 1) ? bk : bv;
    unsigned* __restrict__ dst = (which == 0) ? g_q16 : (which == 1) ? g_k16 : g_v16;

    const int tid  = threadIdx.x;
    const int lane = tid & 31;
    const int wid  = tid >> 5;
    const int wm   = wid >> 1;
    const int wn   = wid & 1;
    const int gid  = lane >> 2;
    const int tig  = lane & 3;

    const int row0 = blockIdx.x << 7;
    const int col0 = blockIdx.y << 7;

    const int a_row = (lane & 15);
    const int a_col = ((lane >> 4) << 3);
    const int b_key = (lane & 7) + ((lane >> 4) << 3);
    const int b_ecol = (((lane >> 3) & 1) << 3);

    load_h16(x + (size_t)row0 * E_, E_, smc, QG_X, 128, tid);
    load_h16(W + (size_t)col0 * E_, E_, smc, QG_W, 128, tid);
    __syncthreads();

    float acc[2][8][4] = {};
    #pragma unroll
    for (int k = 0; k < 8; k++) {
        unsigned ah[2][4];
        #pragma unroll
        for (int mf = 0; mf < 2; mf++) {
            unsigned ao = (unsigned)((wm * 32 + mf * 16 + a_row) * 272 + (k * 16 + a_col) * 2);
            ldsm4(ah[mf], sb + QG_X + ao);
        }
        #pragma unroll
        for (int ng = 0; ng < 4; ng++) {
            unsigned bo = (unsigned)((wn * 64 + ng * 16 + b_key) * 272 + (k * 16 + b_ecol) * 2);
            unsigned bh4[4];
            ldsm4(bh4, sb + QG_W + bo);
            #pragma unroll
            for (int mf = 0; mf < 2; mf++) {
                mma_f16(acc[mf][2*ng],   ah[mf], bh4[0], bh4[1]);
                mma_f16(acc[mf][2*ng+1], ah[mf], bh4[2], bh4[3]);
            }
        }
    }

    const int hh = col0 >> 7;
    const float sc = (which == 0) ? QSCALE_ : 1.0f;
    #pragma unroll
    for (int mf = 0; mf < 2; mf++) {
        const int lr0 = wm * 32 + mf * 16 + gid;
        #pragma unroll
        for (int nf = 0; nf < 8; nf++) {
            const int cb = wn * 64 + nf * 8 + 2 * tig;
            const float b0v = bias[col0 + cb], b1v = bias[col0 + cb + 1];
            float v0 = (acc[mf][nf][0] + b0v) * sc;
            float v1 = (acc[mf][nf][1] + b1v) * sc;
            float v2 = (acc[mf][nf][2] + b0v) * sc;
            float v3 = (acc[mf][nf][3] + b1v) * sc;
            int rw = row0 + lr0;
            int b = rw >> 9, n = rw & 511;
            dst[(((size_t)(b * H_ + hh) * N_ + n) << 6) + (cb >> 1)] = pack_h2(v0, v1);
            rw += 8; b = rw >> 9; n = rw & 511;
            dst[(((size_t)(b * H_ + hh) * N_ + n) << 6) + (cb >> 1)] = pack_h2(v2, v3);
        }
    }
}

// ---------------------------------------------------------------------------
// Kernel 2: flash attention, FA2 row ownership: warp w owns rows w*16..w*16+15
// across ALL 128 keys of each chunk. P stays in registers. 256 thr, 1 CTA/SM.
// ---------------------------------------------------------------------------
#define AQ_OFF   0
#define AK_OFF   34816
#define AV_OFF   69632
#define AD_OFF   104448      /* 128 x 528B */
#define AMK_OFF  172032      /* 512 f32 */
#define SMEM_ATTN 174080

__global__ __launch_bounds__(256, 1) void attn_mma_kernel(
    const float* __restrict__ dist, const float* __restrict__ mask)
{
    extern __shared__ char smc[];
    const unsigned sb = smem_u32(smc);
    float* mk  = (float*)(smc + AMK_OFF);
    float* dsm = (float*)(smc + AD_OFF);   // 132-float row stride

    const int tid  = threadIdx.x;
    const int lane = tid & 31;
    const int w    = tid >> 5;            // warp owns rows w*16..+15
    const int gid  = lane >> 2;
    const int tig  = lane & 3;

    const int q0 = blockIdx.x << 7;
    const int bh = blockIdx.y;
    const int b  = bh >> 3;

    for (int i = tid; i < 512; i += 256) mk[i] = mask[b * 512 + i];

    copy16_async(g_q16 + (((size_t)bh * N_ + q0) << 6), sb, AQ_OFF, 128, tid);
    CP_COMMIT;                                             // group: Q
    copy16_async(g_k16 + (((size_t)bh * N_) << 6), sb, AK_OFF, 128, tid);
    copy16_async(g_v16 + (((size_t)bh * N_) << 6), sb, AV_OFF, 128, tid);
    CP_COMMIT;                                             // group: KV0

    float o[16][4] = {};
    float m0 = -3.0e38f, m1 = -3.0e38f, l0 = 0.f, l1 = 0.f;

    const int a_row = (lane & 15);
    const int a_col = ((lane >> 4) << 3);
    const int b_key = (lane & 7) + ((lane >> 4) << 3);
    const int b_ecol = (((lane >> 3) & 1) << 3);
    const int v_key = (lane & 7) + (((lane >> 3) & 1) << 3);
    const int v_ecol = ((lane >> 4) << 3);

    const int r0 = w * 16 + gid;          // global row (within q-tile)
    const int r1 = r0 + 8;

    for (int kt = 0; kt < 4; kt++) {
        // stage dist tile (rows of this q-tile, 128 key cols) -- hidden by S
        {
            const float* dsrc = dist + ((size_t)b * N_ + q0) * N_ + kt * 128;
            #pragma unroll
            for (int i = 0; i < 16; i++) {
                int idx = tid + (i << 8);
                int r = idx >> 5, c4 = idx & 31;
                CP16(sb + AD_OFF + r * 528 + c4 * 16, dsrc + (size_t)r * N_ + c4 * 4);
            }
            CP_COMMIT;                                     // group: dist
        }
        CP_WAIT1;                 // Q + K/V(kt) ready; dist may be in flight
        __syncthreads();

        // ---- S = Q K^T : warp computes 16 rows x 128 keys ----
        float acc[16][4] = {};
        #pragma unroll
        for (int ks = 0; ks < 8; ks++) {
            unsigned aq[4];
            ldsm4(aq, sb + AQ_OFF + (unsigned)((w * 16 + a_row) * 272 + (ks * 16 + a_col) * 2));
            #pragma unroll
            for (int ng = 0; ng < 8; ng++) {
                unsigned bk4[4];
                ldsm4(bk4, sb + AK_OFF + (unsigned)((ng * 16 + b_key) * 272 + (ks * 16 + b_ecol) * 2));
                mma_f16(acc[2*ng],   aq, bk4[0], bk4[1]);
                mma_f16(acc[2*ng+1], aq, bk4[2], bk4[3]);
            }
        }
        CP_WAIT0;                 // dist staged
        __syncthreads();

        // ---- epilogue pass 1: + dist*log2e, key mask, row max ----
        float mx0 = -3.0e38f, mx1 = -3.0e38f;
        #pragma unroll
        for (int nf = 0; nf < 16; nf++) {
            const int c = nf * 8 + 2 * tig;
            const int gcol = kt * 128 + c;
            float2 d0 = *(float2*)&dsm[r0 * 132 + c];
            float2 d1 = *(float2*)&dsm[r1 * 132 + c];
            const bool k0 = (mk[gcol] != 0.f), k1 = (mk[gcol + 1] != 0.f);
            float s0 = k0 ? fmaf(d0.x, LOG2E_, acc[nf][0]) : NEGV;
            float s1 = k1 ? fmaf(d0.y, LOG2E_, acc[nf][1]) : NEGV;
            float s2 = k0 ? fmaf(d1.x, LOG2E_, acc[nf][2]) : NEGV;
            float s3 = k1 ? fmaf(d1.y, LOG2E_, acc[nf][3]) : NEGV;
            acc[nf][0] = s0; acc[nf][1] = s1; acc[nf][2] = s2; acc[nf][3] = s3;
            mx0 = fmaxf(mx0, fmaxf(s0, s1));
            mx1 = fmaxf(mx1, fmaxf(s2, s3));
        }
        mx0 = fmaxf(mx0, __shfl_xor_sync(0xffffffffu, mx0, 1));
        mx0 = fmaxf(mx0, __shfl_xor_sync(0xffffffffu, mx0, 2));
        mx1 = fmaxf(mx1, __shfl_xor_sync(0xffffffffu, mx1, 1));
        mx1 = fmaxf(mx1, __shfl_xor_sync(0xffffffffu, mx1, 2));

        const float mn0 = fmaxf(m0, mx0), mn1 = fmaxf(m1, mx1);
        const float al0 = ex2f(m0 - mn0), al1 = ex2f(m1 - mn1);

        // ---- pass 2: P = exp2(S - m), pack directly into PV A-fragments ----
        unsigned pa[8][4];
        float rs0 = 0.f, rs1 = 0.f;
        #pragma unroll
        for (int ks = 0; ks < 8; ks++) {
            float p0 = ex2f(acc[2*ks][0] - mn0);
            float p1 = ex2f(acc[2*ks][1] - mn0);
            float p2 = ex2f(acc[2*ks][2] - mn1);
            float p3 = ex2f(acc[2*ks][3] - mn1);
            float p4 = ex2f(acc[2*ks+1][0] - mn0);
            float p5 = ex2f(acc[2*ks+1][1] - mn0);
            float p6 = ex2f(acc[2*ks+1][2] - mn1);
            float p7 = ex2f(acc[2*ks+1][3] - mn1);
            rs0 += (p0 + p1) + (p4 + p5);
            rs1 += (p2 + p3) + (p6 + p7);
            pa[ks][0] = pack_h2(p0, p1);
            pa[ks][1] = pack_h2(p2, p3);
            pa[ks][2] = pack_h2(p4, p5);
            pa[ks][3] = pack_h2(p6, p7);
        }
        rs0 += __shfl_xor_sync(0xffffffffu, rs0, 1);
        rs0 += __shfl_xor_sync(0xffffffffu, rs0, 2);
        rs1 += __shfl_xor_sync(0xffffffffu, rs1, 1);
        rs1 += __shfl_xor_sync(0xffffffffu, rs1, 2);
        l0 = al0 * l0 + rs0;  l1 = al1 * l1 + rs1;
        m0 = mn0;             m1 = mn1;

        // rescale O
        #pragma unroll
        for (int nf = 0; nf < 16; nf++) {
            o[nf][0] *= al0; o[nf][1] *= al0;
            o[nf][2] *= al1; o[nf][3] *= al1;
        }

        // ---- O += P V ----
        #pragma unroll
        for (int ks = 0; ks < 8; ks++) {
            #pragma unroll
            for (int ng = 0; ng < 8; ng++) {
                unsigned vh4[4];
                ldsm4t(vh4, sb + AV_OFF + (unsigned)((ks * 16 + v_key) * 272 + (ng * 16 + v_ecol) * 2));
                mma_f16(o[2*ng],   pa[ks], vh4[0], vh4[1]);
                mma_f16(o[2*ng+1], pa[ks], vh4[2], vh4[3]);
            }
        }
        __syncthreads();          // PV done -> safe to overwrite K/V/dist

        if (kt < 3) {
            const size_t nb = ((size_t)bh * N_ + (kt + 1) * 128) << 6;
            copy16_async(g_k16 + nb, sb, AK_OFF, 128, tid);
            copy16_async(g_v16 + nb, sb, AV_OFF, 128, tid);
            CP_COMMIT;            // group: KV(kt+1)
        }
    }

    // ---- normalize, store packed fp16 ----
    const float li0 = 1.f / l0, li1 = 1.f / l1;
    unsigned* Y = g_y16 + (((size_t)bh * N_ + q0) << 6);
    #pragma unroll
    for (int nf = 0; nf < 16; nf++) {
        const int e = nf * 8 + 2 * tig;
        Y[(size_t)r0 * 64 + (e >> 1)] = pack_h2(o[nf][0] * li0, o[nf][1] * li0);
        Y[(size_t)r1 * 64 + (e >> 1)] = pack_h2(o[nf][2] * li1, o[nf][3] * li1);
    }
}

// ---------------------------------------------------------------------------
// Kernel 3: out = Y @ Wo^T + bo, * mask. fp16 1-term, 64x64 tiles, grid 256.
// ---------------------------------------------------------------------------
#define OG_A 0
#define OG_B 17408
#define SMEM_OPROJ 34816

__global__ __launch_bounds__(256, 3) void oproj_mma_kernel(
    const float* __restrict__ bo,
    const float* __restrict__ mask, float* __restrict__ out)
{
    extern __shared__ char smc[];
    const unsigned sb = smem_u32(smc);

    const int tid  = threadIdx.x;
    const int lane = tid & 31;
    const int wid  = tid >> 5;
    const int wm   = wid >> 1;
    const int wn   = wid & 1;
    const int gid  = lane >> 2;
    const int tig  = lane & 3;

    const int row0 = blockIdx.x << 6;
    const int col0 = blockIdx.y << 6;
    const int b    = row0 >> 9;
    const int n0   = row0 & 511;

    const int a_row = (lane & 15);
    const int a_col = ((lane >> 4) << 3);
    const int b_key = (lane & 7) + ((lane >> 4) << 3);
    const int b_ecol = (((lane >> 3) & 1) << 3);

    float acc[4][4] = {};

    for (int h = 0; h < 8; h++) {
        const size_t ab = ((size_t)(b * H_ + h) * N_ + n0) << 6;
        copy16_async(g_y16 + ab, sb, OG_A, 64, tid);
        for (int idx = tid; idx < 1024; idx += 256) {
            int r = idx >> 4, c = idx & 15;
            size_t su = (size_t)(col0 + r) * 512 + h * 64 + c * 4;
            CP16(sb + OG_B + r * 272 + c * 16, g_wo16 + su);
        }
        CP_COMMIT; CP_WAIT0;
        __syncthreads();

        #pragma unroll
        for (int k = 0; k < 8; k++) {
            unsigned ah[4];
            unsigned ao = (unsigned)((wm * 16 + a_row) * 272 + (k * 16 + a_col) * 2);
            ldsm4(ah, sb + OG_A + ao);
            #pragma unroll
            for (int ng = 0; ng < 2; ng++) {
                unsigned bo_ = (unsigned)((wn * 32 + ng * 16 + b_key) * 272 + (k * 16 + b_ecol) * 2);
                unsigned bh4[4];
                ldsm4(bh4, sb + OG_B + bo_);
                mma_f16(acc[2*ng],   ah, bh4[0], bh4[1]);
                mma_f16(acc[2*ng+1], ah, bh4[2], bh4[3]);
            }
        }
        __syncthreads();
    }

    const int lr0 = wm * 16 + gid;
    const int rw0 = row0 + lr0;
    const float mv0 = mask[b * 512 + (rw0 & 511)];
    const float mv1 = mask[b * 512 + ((rw0 + 8) & 511)];
    #pragma unroll
    for (int nf = 0; nf < 4; nf++) {
        const int cb = col0 + wn * 32 + nf * 8 + 2 * tig;
        const float b0v = bo[cb], b1v = bo[cb + 1];
        *(float2*)&out[(size_t)rw0 * E_ + cb] =
            make_float2((acc[nf][0] + b0v) * mv0, (acc[nf][1] + b1v) * mv0);
        *(float2*)&out[(size_t)(rw0 + 8) * E_ + cb] =
            make_float2((acc[nf][2] + b0v) * mv1, (acc[nf][3] + b1v) * mv1);
    }
}

// ---------------------------------------------------------------------------
extern "C" void kernel_launch(void* const* d_in, const int* in_sizes, int n_in,
                              void* d_out, int out_size)
{
    const float* x    = (const float*)d_in[0];
    const float* dist = (const float*)d_in[1];
    const float* mask = (const float*)d_in[2];
    const float* Wq   = (const float*)d_in[3];
    const float* bq   = (const float*)d_in[4];
    const float* Wk   = (const float*)d_in[5];
    const float* bk   = (const float*)d_in[6];
    const float* Wv   = (const float*)d_in[7];
    const float* bv   = (const float*)d_in[8];
    const float* Wo   = (const float*)d_in[9];
    const float* bo   = (const float*)d_in[10];
    float* out = (float*)d_out;

    cudaFuncSetAttribute(qkv_mma_kernel,
                         cudaFuncAttributeMaxDynamicSharedMemorySize, SMEM_QKV);
    cudaFuncSetAttribute(attn_mma_kernel,
                         cudaFuncAttributeMaxDynamicSharedMemorySize, SMEM_ATTN);
    cudaFuncSetAttribute(oproj_mma_kernel,
                         cudaFuncAttributeMaxDynamicSharedMemorySize, SMEM_OPROJ);

    wsplit_kernel<<<256, 256>>>(Wo);
    qkv_mma_kernel<<<dim3(64, 8, 3), 256, SMEM_QKV>>>(x, Wq, bq, Wk, bk, Wv, bv);
    attn_mma_kernel<<<dim3(4, 128), 256, SMEM_ATTN>>>(dist, mask);
    oproj_mma_kernel<<<dim3(128, 2), 256, SMEM_OPROJ>>>(bo, mask, out);
}

// round 11
// speedup vs baseline: 2.2369x; 1.0111x over previous
#include <cuda_runtime.h>
#include <cuda_bf16.h>
#include <cuda_fp16.h>
#include <math.h>

#define B_ 16
#define N_ 512
#define H_ 8
#define E_ 128
#define BH_ (B_*H_)
#define NEGV (-1000000000.0f)
#define SCALE_ 0.08838834764831845f
#define LOG2E_ 1.4426950408889634f
#define QSCALE_ (SCALE_ * LOG2E_)

// q/k/v/y/Wo as packed fp16x2 (unsigned) arrays.
__device__ unsigned g_q16[BH_*N_*E_/2];
__device__ unsigned g_k16[BH_*N_*E_/2];
__device__ unsigned g_v16[BH_*N_*E_/2];
__device__ unsigned g_y16[BH_*N_*E_/2];
__device__ unsigned g_wo16[E_*1024/2];

// ---------------------------------------------------------------------------
// helpers
// ---------------------------------------------------------------------------
__device__ __forceinline__ unsigned smem_u32(const void* p) {
    unsigned r;
    asm("{ .reg .u64 t; cvta.to.shared.u64 t, %1; cvt.u32.u64 %0, t; }" : "=r"(r) : "l"(p));
    return r;
}
__device__ __forceinline__ void ldsm4(unsigned r[4], unsigned addr) {
    asm volatile("ldmatrix.sync.aligned.m8n8.x4.shared.b16 {%0,%1,%2,%3}, [%4];"
        : "=r"(r[0]), "=r"(r[1]), "=r"(r[2]), "=r"(r[3]) : "r"(addr));
}
__device__ __forceinline__ void ldsm4t(unsigned r[4], unsigned addr) {
    asm volatile("ldmatrix.sync.aligned.m8n8.x4.trans.shared.b16 {%0,%1,%2,%3}, [%4];"
        : "=r"(r[0]), "=r"(r[1]), "=r"(r[2]), "=r"(r[3]) : "r"(addr));
}
__device__ __forceinline__ void mma_f16(float c[4], const unsigned a[4],
                                        unsigned b0, unsigned b1) {
    asm volatile("mma.sync.aligned.m16n8k16.row.col.f32.f16.f16.f32 "
        "{%0,%1,%2,%3}, {%4,%5,%6,%7}, {%8,%9}, {%0,%1,%2,%3};"
        : "+f"(c[0]), "+f"(c[1]), "+f"(c[2]), "+f"(c[3])
        : "r"(a[0]), "r"(a[1]), "r"(a[2]), "r"(a[3]), "r"(b0), "r"(b1));
}
__device__ __forceinline__ unsigned pack_h2(float a, float b) {
    __half2 h = __floats2half2_rn(a, b);
    return *(unsigned*)&h;
}
__device__ __forceinline__ float ex2f(float x) {
    float r;
    asm("ex2.approx.f32 %0, %1;" : "=f"(r) : "f"(x));
    return r;
}

#define CP16(dst, src) \
    asm volatile("cp.async.cg.shared.global [%0], [%1], 16;" \
        :: "r"(dst), "l"(__cvta_generic_to_global(src)) : "memory")
#define CP_COMMIT asm volatile("cp.async.commit_group;" ::: "memory")
#define CP_WAIT0  asm volatile("cp.async.wait_group 0;" ::: "memory")

// fp32 tile -> fp16 smem (272B row stride); 256 threads
__device__ __forceinline__ void load_h16(const float* __restrict__ src,
        size_t stride, char* smc, int off, int rows, int tid)
{
    const int total = rows * 32;
    for (int idx = tid; idx < total; idx += 256) {
        int r = idx >> 5, c4 = idx & 31;
        float4 v = *(const float4*)(src + (size_t)r * stride + c4 * 4);
        *(uint2*)(smc + off + r * 272 + c4 * 8) =
            make_uint2(pack_h2(v.x, v.y), pack_h2(v.z, v.w));
    }
}

// packed-fp16 tile async copy: global (row stride 64 u32) -> smem 272B stride
__device__ __forceinline__ void copy16_async(const unsigned* __restrict__ src,
        unsigned sb, int off, int rows, int tid, int nthr)
{
    const int total = rows * 16;
    for (int idx = tid; idx < total; idx += nthr) {
        int r = idx >> 4, c = idx & 15;
        CP16(sb + off + r * 272 + c * 16, src + (size_t)r * 64 + c * 4);
    }
}

// ---------------------------------------------------------------------------
// Kernel 0: convert Wo to packed fp16
// ---------------------------------------------------------------------------
__global__ void wsplit_kernel(const float* __restrict__ Wo) {
    int i = blockIdx.x * 256 + threadIdx.x;
    float2 v = *(const float2*)(Wo + 2 * i);
    g_wo16[i] = pack_h2(v.x, v.y);
}

// ---------------------------------------------------------------------------
// Kernel 1: QKV projection, 1-term fp16 mma (unchanged from R10, ~30us).
// ---------------------------------------------------------------------------
#define QG_X 0
#define QG_W 34816
#define SMEM_QKV 69632

__global__ __launch_bounds__(256, 2) void qkv_mma_kernel(
    const float* __restrict__ x,
    const float* __restrict__ Wq, const float* __restrict__ bq,
    const float* __restrict__ Wk, const float* __restrict__ bk,
    const float* __restrict__ Wv, const float* __restrict__ bv)
{
    extern __shared__ char smc[];
    const unsigned sb = smem_u32(smc);

    const int which = blockIdx.z;
    const float* __restrict__ W    = (which == 0) ? Wq : (which == 1) ? Wk : Wv;
    const float* __restrict__ bias = (which == 0) ? bq : (which == 1) ? bk : bv;
    unsigned* __restrict__ dst = (which == 0) ? g_q16 : (which == 1) ? g_k16 : g_v16;

    const int tid  = threadIdx.x;
    const int lane = tid & 31;
    const int wid  = tid >> 5;
    const int wm   = wid >> 1;
    const int wn   = wid & 1;
    const int gid  = lane >> 2;
    const int tig  = lane & 3;

    const int row0 = blockIdx.x << 7;
    const int col0 = blockIdx.y << 7;

    const int a_row = (lane & 15);
    const int a_col = ((lane >> 4) << 3);
    const int b_key = (lane & 7) + ((lane >> 4) << 3);
    const int b_ecol = (((lane >> 3) & 1) << 3);

    load_h16(x + (size_t)row0 * E_, E_, smc, QG_X, 128, tid);
    load_h16(W + (size_t)col0 * E_, E_, smc, QG_W, 128, tid);
    __syncthreads();

    float acc[2][8][4] = {};
    #pragma unroll
    for (int k = 0; k < 8; k++) {
        unsigned ah[2][4];
        #pragma unroll
        for (int mf = 0; mf < 2; mf++) {
            unsigned ao = (unsigned)((wm * 32 + mf * 16 + a_row) * 272 + (k * 16 + a_col) * 2);
            ldsm4(ah[mf], sb + QG_X + ao);
        }
        #pragma unroll
        for (int ng = 0; ng < 4; ng++) {
            unsigned bo = (unsigned)((wn * 64 + ng * 16 + b_key) * 272 + (k * 16 + b_ecol) * 2);
            unsigned bh4[4];
            ldsm4(bh4, sb + QG_W + bo);
            #pragma unroll
            for (int mf = 0; mf < 2; mf++) {
                mma_f16(acc[mf][2*ng],   ah[mf], bh4[0], bh4[1]);
                mma_f16(acc[mf][2*ng+1], ah[mf], bh4[2], bh4[3]);
            }
        }
    }

    const int hh = col0 >> 7;
    const float sc = (which == 0) ? QSCALE_ : 1.0f;
    #pragma unroll
    for (int mf = 0; mf < 2; mf++) {
        const int lr0 = wm * 32 + mf * 16 + gid;
        #pragma unroll
        for (int nf = 0; nf < 8; nf++) {
            const int cb = wn * 64 + nf * 8 + 2 * tig;
            const float b0v = bias[col0 + cb], b1v = bias[col0 + cb + 1];
            float v0 = (acc[mf][nf][0] + b0v) * sc;
            float v1 = (acc[mf][nf][1] + b1v) * sc;
            float v2 = (acc[mf][nf][2] + b0v) * sc;
            float v3 = (acc[mf][nf][3] + b1v) * sc;
            int rw = row0 + lr0;
            int b = rw >> 9, n = rw & 511;
            dst[(((size_t)(b * H_ + hh) * N_ + n) << 6) + (cb >> 1)] = pack_h2(v0, v1);
            rw += 8; b = rw >> 9; n = rw & 511;
            dst[(((size_t)(b * H_ + hh) * N_ + n) << 6) + (cb >> 1)] = pack_h2(v2, v3);
        }
    }
}

// ---------------------------------------------------------------------------
// Kernel 2: flash attention. 64 q-rows x 64-key chunks, 128 thr (4 warps x
// 16 rows), 3 CTAs/SM so softmax phases of one CTA overlap MMA of others.
// ---------------------------------------------------------------------------
#define AQ_OFF   0           /* 64 x 272 = 17408 */
#define AK_OFF   17408       /* 64 x 272 */
#define AV_OFF   34816       /* 64 x 272 */
#define AD_OFF   52224       /* dist fp32: 64 rows x 272B (68 floats) */
#define AMK_OFF  69632       /* 512 f32 */
#define SMEM_ATTN 71680

__global__ __launch_bounds__(128, 3) void attn_mma_kernel(
    const float* __restrict__ dist, const float* __restrict__ mask)
{
    extern __shared__ char smc[];
    const unsigned sb = smem_u32(smc);
    float* mk  = (float*)(smc + AMK_OFF);
    float* dsm = (float*)(smc + AD_OFF);   // 68-float row stride

    const int tid  = threadIdx.x;
    const int lane = tid & 31;
    const int w    = tid >> 5;            // warp owns rows w*16..+15 (of 64)
    const int gid  = lane >> 2;
    const int tig  = lane & 3;

    const int q0 = blockIdx.x << 6;       // 8 q-tiles of 64
    const int bh = blockIdx.y;
    const int b  = bh >> 3;

    for (int i = tid; i < 512; i += 128) mk[i] = mask[b * 512 + i];

    // prologue loads: Q + chunk-0 K/V/dist, one group
    copy16_async(g_q16 + (((size_t)bh * N_ + q0) << 6), sb, AQ_OFF, 64, tid, 128);
    copy16_async(g_k16 + (((size_t)bh * N_) << 6), sb, AK_OFF, 64, tid, 128);
    copy16_async(g_v16 + (((size_t)bh * N_) << 6), sb, AV_OFF, 64, tid, 128);
    {
        const float* dsrc = dist + ((size_t)b * N_ + q0) * N_;
        #pragma unroll
        for (int i = 0; i < 8; i++) {
            int idx = tid + (i << 7);
            int r = idx >> 4, c = idx & 15;
            CP16(sb + AD_OFF + r * 272 + c * 16, dsrc + (size_t)r * N_ + c * 4);
        }
    }
    CP_COMMIT;

    float o[16][4] = {};
    float m0 = -3.0e38f, m1 = -3.0e38f, l0 = 0.f, l1 = 0.f;

    const int a_row = (lane & 15);
    const int a_col = ((lane >> 4) << 3);
    const int b_key = (lane & 7) + ((lane >> 4) << 3);
    const int b_ecol = (((lane >> 3) & 1) << 3);
    const int v_key = (lane & 7) + (((lane >> 3) & 1) << 3);
    const int v_ecol = ((lane >> 4) << 3);

    const int r0 = w * 16 + gid;          // local q-row
    const int r1 = r0 + 8;

    for (int kt = 0; kt < 8; kt++) {
        CP_WAIT0;
        __syncthreads();

        // ---- S = Q K^T : 16 rows x 64 keys per warp ----
        float acc[8][4] = {};
        #pragma unroll
        for (int ks = 0; ks < 8; ks++) {
            unsigned aq[4];
            ldsm4(aq, sb + AQ_OFF + (unsigned)((w * 16 + a_row) * 272 + (ks * 16 + a_col) * 2));
            #pragma unroll
            for (int ng = 0; ng < 4; ng++) {
                unsigned bk4[4];
                ldsm4(bk4, sb + AK_OFF + (unsigned)((ng * 16 + b_key) * 272 + (ks * 16 + b_ecol) * 2));
                mma_f16(acc[2*ng],   aq, bk4[0], bk4[1]);
                mma_f16(acc[2*ng+1], aq, bk4[2], bk4[3]);
            }
        }

        // ---- + dist*log2e, key mask, row max ----
        float mx0 = -3.0e38f, mx1 = -3.0e38f;
        #pragma unroll
        for (int nf = 0; nf < 8; nf++) {
            const int c = nf * 8 + 2 * tig;
            const int gcol = kt * 64 + c;
            float2 d0 = *(float2*)&dsm[r0 * 68 + c];
            float2 d1 = *(float2*)&dsm[r1 * 68 + c];
            const bool k0 = (mk[gcol] != 0.f), k1 = (mk[gcol + 1] != 0.f);
            float s0 = k0 ? fmaf(d0.x, LOG2E_, acc[nf][0]) : NEGV;
            float s1 = k1 ? fmaf(d0.y, LOG2E_, acc[nf][1]) : NEGV;
            float s2 = k0 ? fmaf(d1.x, LOG2E_, acc[nf][2]) : NEGV;
            float s3 = k1 ? fmaf(d1.y, LOG2E_, acc[nf][3]) : NEGV;
            acc[nf][0] = s0; acc[nf][1] = s1; acc[nf][2] = s2; acc[nf][3] = s3;
            mx0 = fmaxf(mx0, fmaxf(s0, s1));
            mx1 = fmaxf(mx1, fmaxf(s2, s3));
        }
        mx0 = fmaxf(mx0, __shfl_xor_sync(0xffffffffu, mx0, 1));
        mx0 = fmaxf(mx0, __shfl_xor_sync(0xffffffffu, mx0, 2));
        mx1 = fmaxf(mx1, __shfl_xor_sync(0xffffffffu, mx1, 1));
        mx1 = fmaxf(mx1, __shfl_xor_sync(0xffffffffu, mx1, 2));

        const float mn0 = fmaxf(m0, mx0), mn1 = fmaxf(m1, mx1);
        const float al0 = ex2f(m0 - mn0), al1 = ex2f(m1 - mn1);

        // ---- P = exp2(S - m) directly into PV A-fragments ----
        unsigned pa[4][4];
        float rs0 = 0.f, rs1 = 0.f;
        #pragma unroll
        for (int ks = 0; ks < 4; ks++) {
            float p0 = ex2f(acc[2*ks][0] - mn0);
            float p1 = ex2f(acc[2*ks][1] - mn0);
            float p2 = ex2f(acc[2*ks][2] - mn1);
            float p3 = ex2f(acc[2*ks][3] - mn1);
            float p4 = ex2f(acc[2*ks+1][0] - mn0);
            float p5 = ex2f(acc[2*ks+1][1] - mn0);
            float p6 = ex2f(acc[2*ks+1][2] - mn1);
            float p7 = ex2f(acc[2*ks+1][3] - mn1);
            rs0 += (p0 + p1) + (p4 + p5);
            rs1 += (p2 + p3) + (p6 + p7);
            pa[ks][0] = pack_h2(p0, p1);
            pa[ks][1] = pack_h2(p2, p3);
            pa[ks][2] = pack_h2(p4, p5);
            pa[ks][3] = pack_h2(p6, p7);
        }
        rs0 += __shfl_xor_sync(0xffffffffu, rs0, 1);
        rs0 += __shfl_xor_sync(0xffffffffu, rs0, 2);
        rs1 += __shfl_xor_sync(0xffffffffu, rs1, 1);
        rs1 += __shfl_xor_sync(0xffffffffu, rs1, 2);
        l0 = al0 * l0 + rs0;  l1 = al1 * l1 + rs1;
        m0 = mn0;             m1 = mn1;

        #pragma unroll
        for (int nf = 0; nf < 16; nf++) {
            o[nf][0] *= al0; o[nf][1] *= al0;
            o[nf][2] *= al1; o[nf][3] *= al1;
        }

        // ---- O += P V ----
        #pragma unroll
        for (int ks = 0; ks < 4; ks++) {
            #pragma unroll
            for (int ng = 0; ng < 8; ng++) {
                unsigned vh4[4];
                ldsm4t(vh4, sb + AV_OFF + (unsigned)((ks * 16 + v_key) * 272 + (ng * 16 + v_ecol) * 2));
                mma_f16(o[2*ng],   pa[ks], vh4[0], vh4[1]);
                mma_f16(o[2*ng+1], pa[ks], vh4[2], vh4[3]);
            }
        }
        __syncthreads();          // all reads of K/V/dist done

        if (kt < 7) {
            const size_t nb = ((size_t)bh * N_ + (kt + 1) * 64) << 6;
            copy16_async(g_k16 + nb, sb, AK_OFF, 64, tid, 128);
            copy16_async(g_v16 + nb, sb, AV_OFF, 64, tid, 128);
            const float* dsrc = dist + ((size_t)b * N_ + q0) * N_ + (kt + 1) * 64;
            #pragma unroll
            for (int i = 0; i < 8; i++) {
                int idx = tid + (i << 7);
                int r = idx >> 4, c = idx & 15;
                CP16(sb + AD_OFF + r * 272 + c * 16, dsrc + (size_t)r * N_ + c * 4);
            }
            CP_COMMIT;
        }
    }

    // ---- normalize, store packed fp16 ----
    const float li0 = 1.f / l0, li1 = 1.f / l1;
    unsigned* Y = g_y16 + (((size_t)bh * N_ + q0) << 6);
    #pragma unroll
    for (int nf = 0; nf < 16; nf++) {
        const int e = nf * 8 + 2 * tig;
        Y[(size_t)r0 * 64 + (e >> 1)] = pack_h2(o[nf][0] * li0, o[nf][1] * li0);
        Y[(size_t)r1 * 64 + (e >> 1)] = pack_h2(o[nf][2] * li1, o[nf][3] * li1);
    }
}

// ---------------------------------------------------------------------------
// Kernel 3: out = Y @ Wo^T + bo, * mask (unchanged from R10, ~18us).
// ---------------------------------------------------------------------------
#define OG_A 0
#define OG_B 17408
#define SMEM_OPROJ 34816

__global__ __launch_bounds__(256, 3) void oproj_mma_kernel(
    const float* __restrict__ bo,
    const float* __restrict__ mask, float* __restrict__ out)
{
    extern __shared__ char smc[];
    const unsigned sb = smem_u32(smc);

    const int tid  = threadIdx.x;
    const int lane = tid & 31;
    const int wid  = tid >> 5;
    const int wm   = wid >> 1;
    const int wn   = wid & 1;
    const int gid  = lane >> 2;
    const int tig  = lane & 3;

    const int row0 = blockIdx.x << 6;
    const int col0 = blockIdx.y << 6;
    const int b    = row0 >> 9;
    const int n0   = row0 & 511;

    const int a_row = (lane & 15);
    const int a_col = ((lane >> 4) << 3);
    const int b_key = (lane & 7) + ((lane >> 4) << 3);
    const int b_ecol = (((lane >> 3) & 1) << 3);

    float acc[4][4] = {};

    for (int h = 0; h < 8; h++) {
        const size_t ab = ((size_t)(b * H_ + h) * N_ + n0) << 6;
        copy16_async(g_y16 + ab, sb, OG_A, 64, tid, 256);
        for (int idx = tid; idx < 1024; idx += 256) {
            int r = idx >> 4, c = idx & 15;
            size_t su = (size_t)(col0 + r) * 512 + h * 64 + c * 4;
            CP16(sb + OG_B + r * 272 + c * 16, g_wo16 + su);
        }
        CP_COMMIT; CP_WAIT0;
        __syncthreads();

        #pragma unroll
        for (int k = 0; k < 8; k++) {
            unsigned ah[4];
            unsigned ao = (unsigned)((wm * 16 + a_row) * 272 + (k * 16 + a_col) * 2);
            ldsm4(ah, sb + OG_A + ao);
            #pragma unroll
            for (int ng = 0; ng < 2; ng++) {
                unsigned bo_ = (unsigned)((wn * 32 + ng * 16 + b_key) * 272 + (k * 16 + b_ecol) * 2);
                unsigned bh4[4];
                ldsm4(bh4, sb + OG_B + bo_);
                mma_f16(acc[2*ng],   ah, bh4[0], bh4[1]);
                mma_f16(acc[2*ng+1], ah, bh4[2], bh4[3]);
            }
        }
        __syncthreads();
    }

    const int lr0 = wm * 16 + gid;
    const int rw0 = row0 + lr0;
    const float mv0 = mask[b * 512 + (rw0 & 511)];
    const float mv1 = mask[b * 512 + ((rw0 + 8) & 511)];
    #pragma unroll
    for (int nf = 0; nf < 4; nf++) {
        const int cb = col0 + wn * 32 + nf * 8 + 2 * tig;
        const float b0v = bo[cb], b1v = bo[cb + 1];
        *(float2*)&out[(size_t)rw0 * E_ + cb] =
            make_float2((acc[nf][0] + b0v) * mv0, (acc[nf][1] + b1v) * mv0);
        *(float2*)&out[(size_t)(rw0 + 8) * E_ + cb] =
            make_float2((acc[nf][2] + b0v) * mv1, (acc[nf][3] + b1v) * mv1);
    }
}

// ---------------------------------------------------------------------------
extern "C" void kernel_launch(void* const* d_in, const int* in_sizes, int n_in,
                              void* d_out, int out_size)
{
    const float* x    = (const float*)d_in[0];
    const float* dist = (const float*)d_in[1];
    const float* mask = (const float*)d_in[2];
    const float* Wq   = (const float*)d_in[3];
    const float* bq   = (const float*)d_in[4];
    const float* Wk   = (const float*)d_in[5];
    const float* bk   = (const float*)d_in[6];
    const float* Wv   = (const float*)d_in[7];
    const float* bv   = (const float*)d_in[8];
    const float* Wo   = (const float*)d_in[9];
    const float* bo   = (const float*)d_in[10];
    float* out = (float*)d_out;

    cudaFuncSetAttribute(qkv_mma_kernel,
                         cudaFuncAttributeMaxDynamicSharedMemorySize, SMEM_QKV);
    cudaFuncSetAttribute(attn_mma_kernel,
                         cudaFuncAttributeMaxDynamicSharedMemorySize, SMEM_ATTN);
    cudaFuncSetAttribute(oproj_mma_kernel,
                         cudaFuncAttributeMaxDynamicSharedMemorySize, SMEM_OPROJ);

    wsplit_kernel<<<256, 256>>>(Wo);
    qkv_mma_kernel<<<dim3(64, 8, 3), 256, SMEM_QKV>>>(x, Wq, bq, Wk, bk, Wv, bv);
    attn_mma_kernel<<<dim3(8, 128), 128, SMEM_ATTN>>>(dist, mask);
    oproj_mma_kernel<<<dim3(128, 2), 256, SMEM_OPROJ>>>(bo, mask, out);
}

// round 12
// speedup vs baseline: 2.2686x; 1.0142x over previous
#include <cuda_runtime.h>
#include <cuda_bf16.h>
#include <cuda_fp16.h>
#include <math.h>

#define B_ 16
#define N_ 512
#define H_ 8
#define E_ 128
#define BH_ (B_*H_)
#define NEGV (-1000000000.0f)
#define SCALE_ 0.08838834764831845f
#define LOG2E_ 1.4426950408889634f
#define QSCALE_ (SCALE_ * LOG2E_)

// q/k/v/y/Wo as packed fp16x2 (unsigned) arrays. dist pre-scaled fp16.
__device__ unsigned g_q16[BH_*N_*E_/2];
__device__ unsigned g_k16[BH_*N_*E_/2];
__device__ unsigned g_v16[BH_*N_*E_/2];
__device__ unsigned g_y16[BH_*N_*E_/2];
__device__ unsigned g_wo16[E_*1024/2];
__device__ unsigned g_d16[B_*N_*N_/2];

// ---------------------------------------------------------------------------
// helpers
// ---------------------------------------------------------------------------
__device__ __forceinline__ unsigned smem_u32(const void* p) {
    unsigned r;
    asm("{ .reg .u64 t; cvta.to.shared.u64 t, %1; cvt.u32.u64 %0, t; }" : "=r"(r) : "l"(p));
    return r;
}
__device__ __forceinline__ void ldsm4(unsigned r[4], unsigned addr) {
    asm volatile("ldmatrix.sync.aligned.m8n8.x4.shared.b16 {%0,%1,%2,%3}, [%4];"
        : "=r"(r[0]), "=r"(r[1]), "=r"(r[2]), "=r"(r[3]) : "r"(addr));
}
__device__ __forceinline__ void ldsm4t(unsigned r[4], unsigned addr) {
    asm volatile("ldmatrix.sync.aligned.m8n8.x4.trans.shared.b16 {%0,%1,%2,%3}, [%4];"
        : "=r"(r[0]), "=r"(r[1]), "=r"(r[2]), "=r"(r[3]) : "r"(addr));
}
__device__ __forceinline__ void mma_f16(float c[4], const unsigned a[4],
                                        unsigned b0, unsigned b1) {
    asm volatile("mma.sync.aligned.m16n8k16.row.col.f32.f16.f16.f32 "
        "{%0,%1,%2,%3}, {%4,%5,%6,%7}, {%8,%9}, {%0,%1,%2,%3};"
        : "+f"(c[0]), "+f"(c[1]), "+f"(c[2]), "+f"(c[3])
        : "r"(a[0]), "r"(a[1]), "r"(a[2]), "r"(a[3]), "r"(b0), "r"(b1));
}
__device__ __forceinline__ unsigned pack_h2(float a, float b) {
    __half2 h = __floats2half2_rn(a, b);
    return *(unsigned*)&h;
}
__device__ __forceinline__ float ex2f(float x) {
    float r;
    asm("ex2.approx.f32 %0, %1;" : "=f"(r) : "f"(x));
    return r;
}

#define CP16(dst, src) \
    asm volatile("cp.async.cg.shared.global [%0], [%1], 16;" \
        :: "r"(dst), "l"(__cvta_generic_to_global(src)) : "memory")
#define CP_COMMIT asm volatile("cp.async.commit_group;" ::: "memory")
#define CP_WAIT0  asm volatile("cp.async.wait_group 0;" ::: "memory")
#define CP_WAIT1  asm volatile("cp.async.wait_group 1;" ::: "memory")

// fp32 tile -> fp16 smem (272B row stride); 256 threads
__device__ __forceinline__ void load_h16(const float* __restrict__ src,
        size_t stride, char* smc, int off, int rows, int tid)
{
    const int total = rows * 32;
    for (int idx = tid; idx < total; idx += 256) {
        int r = idx >> 5, c4 = idx & 31;
        float4 v = *(const float4*)(src + (size_t)r * stride + c4 * 4);
        *(uint2*)(smc + off + r * 272 + c4 * 8) =
            make_uint2(pack_h2(v.x, v.y), pack_h2(v.z, v.w));
    }
}

// packed-fp16 tile async copy: global (row stride 64 u32) -> smem 272B stride
__device__ __forceinline__ void copy16_async(const unsigned* __restrict__ src,
        unsigned sb, int off, int rows, int tid, int nthr)
{
    const int total = rows * 16;
    for (int idx = tid; idx < total; idx += nthr) {
        int r = idx >> 4, c = idx & 15;
        CP16(sb + off + r * 272 + c * 16, src + (size_t)r * 64 + c * 4);
    }
}

// ---------------------------------------------------------------------------
// Kernel 0a: convert Wo to packed fp16
// ---------------------------------------------------------------------------
__global__ void wsplit_kernel(const float* __restrict__ Wo) {
    int i = blockIdx.x * 256 + threadIdx.x;
    float2 v = *(const float2*)(Wo + 2 * i);
    g_wo16[i] = pack_h2(v.x, v.y);
}
// Kernel 0b: convert dist to fp16, pre-scaled by log2(e)
__global__ void dprep_kernel(const float* __restrict__ dist) {
    int i = blockIdx.x * 256 + threadIdx.x;
    float2 v = *(const float2*)(dist + 2 * i);
    g_d16[i] = pack_h2(v.x * LOG2E_, v.y * LOG2E_);
}

// ---------------------------------------------------------------------------
// Kernel 1: QKV projection, 1-term fp16 mma (unchanged, ~30us).
// ---------------------------------------------------------------------------
#define QG_X 0
#define QG_W 34816
#define SMEM_QKV 69632

__global__ __launch_bounds__(256, 2) void qkv_mma_kernel(
    const float* __restrict__ x,
    const float* __restrict__ Wq, const float* __restrict__ bq,
    const float* __restrict__ Wk, const float* __restrict__ bk,
    const float* __restrict__ Wv, const float* __restrict__ bv)
{
    extern __shared__ char smc[];
    const unsigned sb = smem_u32(smc);

    const int which = blockIdx.z;
    const float* __restrict__ W    = (which == 0) ? Wq : (which == 1) ? Wk : Wv;
    const float* __restrict__ bias = (which == 0) ? bq : (which == 1) ? bk : bv;
    unsigned* __restrict__ dst = (which == 0) ? g_q16 : (which == 1) ? g_k16 : g_v16;

    const int tid  = threadIdx.x;
    const int lane = tid & 31;
    const int wid  = tid >> 5;
    const int wm   = wid >> 1;
    const int wn   = wid & 1;
    const int gid  = lane >> 2;
    const int tig  = lane & 3;

    const int row0 = blockIdx.x << 7;
    const int col0 = blockIdx.y << 7;

    const int a_row = (lane & 15);
    const int a_col = ((lane >> 4) << 3);
    const int b_key = (lane & 7) + ((lane >> 4) << 3);
    const int b_ecol = (((lane >> 3) & 1) << 3);

    load_h16(x + (size_t)row0 * E_, E_, smc, QG_X, 128, tid);
    load_h16(W + (size_t)col0 * E_, E_, smc, QG_W, 128, tid);
    __syncthreads();

    float acc[2][8][4] = {};
    #pragma unroll
    for (int k = 0; k < 8; k++) {
        unsigned ah[2][4];
        #pragma unroll
        for (int mf = 0; mf < 2; mf++) {
            unsigned ao = (unsigned)((wm * 32 + mf * 16 + a_row) * 272 + (k * 16 + a_col) * 2);
            ldsm4(ah[mf], sb + QG_X + ao);
        }
        #pragma unroll
        for (int ng = 0; ng < 4; ng++) {
            unsigned bo = (unsigned)((wn * 64 + ng * 16 + b_key) * 272 + (k * 16 + b_ecol) * 2);
            unsigned bh4[4];
            ldsm4(bh4, sb + QG_W + bo);
            #pragma unroll
            for (int mf = 0; mf < 2; mf++) {
                mma_f16(acc[mf][2*ng],   ah[mf], bh4[0], bh4[1]);
                mma_f16(acc[mf][2*ng+1], ah[mf], bh4[2], bh4[3]);
            }
        }
    }

    const int hh = col0 >> 7;
    const float sc = (which == 0) ? QSCALE_ : 1.0f;
    #pragma unroll
    for (int mf = 0; mf < 2; mf++) {
        const int lr0 = wm * 32 + mf * 16 + gid;
        #pragma unroll
        for (int nf = 0; nf < 8; nf++) {
            const int cb = wn * 64 + nf * 8 + 2 * tig;
            const float b0v = bias[col0 + cb], b1v = bias[col0 + cb + 1];
            float v0 = (acc[mf][nf][0] + b0v) * sc;
            float v1 = (acc[mf][nf][1] + b1v) * sc;
            float v2 = (acc[mf][nf][2] + b0v) * sc;
            float v3 = (acc[mf][nf][3] + b1v) * sc;
            int rw = row0 + lr0;
            int b = rw >> 9, n = rw & 511;
            dst[(((size_t)(b * H_ + hh) * N_ + n) << 6) + (cb >> 1)] = pack_h2(v0, v1);
            rw += 8; b = rw >> 9; n = rw & 511;
            dst[(((size_t)(b * H_ + hh) * N_ + n) << 6) + (cb >> 1)] = pack_h2(v2, v3);
        }
    }
}

// ---------------------------------------------------------------------------
// Kernel 2: flash attention. 64 q-rows x 64-key chunks, double-buffered
// K/V/dist(fp16), 128 thr, 2 CTAs/SM. Loads lead compute by 2 chunks.
// ---------------------------------------------------------------------------
#define AQ_OFF    0            /* 64 x 272 = 17408 */
#define AK0_OFF   17408
#define AV0_OFF   34816
#define AD0_OFF   52224        /* dist fp16: 64 rows x 144B = 9216 */
#define AK1_OFF   61440
#define AV1_OFF   78848
#define AD1_OFF   96256
#define AMK_OFF   105472       /* 512 f32 */
#define SMEM_ATTN 107520

__global__ __launch_bounds__(128, 2) void attn_mma_kernel(
    const float* __restrict__ mask)
{
    extern __shared__ char smc[];
    const unsigned sb = smem_u32(smc);
    float* mk = (float*)(smc + AMK_OFF);

    const int tid  = threadIdx.x;
    const int lane = tid & 31;
    const int w    = tid >> 5;
    const int gid  = lane >> 2;
    const int tig  = lane & 3;

    const int q0 = blockIdx.x << 6;
    const int bh = blockIdx.y;
    const int b  = bh >> 3;

    for (int i = tid; i < 512; i += 128) mk[i] = mask[b * 512 + i];

    // chunk loader: K/V (fp16 tiles) + dist row block (fp16, 144B stride)
    auto loadKVD = [&](int kt, int kOff, int vOff, int dOff) {
        const size_t nb = ((size_t)bh * N_ + kt * 64) << 6;
        copy16_async(g_k16 + nb, sb, kOff, 64, tid, 128);
        copy16_async(g_v16 + nb, sb, vOff, 64, tid, 128);
        const unsigned* dsrc = g_d16 + ((size_t)b * N_ + q0) * 256 + kt * 32;
        #pragma unroll
        for (int i = 0; i < 4; i++) {
            int idx = tid + (i << 7);
            int r = idx >> 3, c = idx & 7;
            CP16(sb + dOff + r * 144 + c * 16, dsrc + (size_t)r * 256 + c * 4);
        }
    };

    // prologue: Q + chunk0 (group 0), chunk1 (group 1)
    copy16_async(g_q16 + (((size_t)bh * N_ + q0) << 6), sb, AQ_OFF, 64, tid, 128);
    loadKVD(0, AK0_OFF, AV0_OFF, AD0_OFF);
    CP_COMMIT;
    loadKVD(1, AK1_OFF, AV1_OFF, AD1_OFF);
    CP_COMMIT;

    float o[16][4] = {};
    float m0 = -3.0e38f, m1 = -3.0e38f, l0 = 0.f, l1 = 0.f;

    const int a_row = (lane & 15);
    const int a_col = ((lane >> 4) << 3);
    const int b_key = (lane & 7) + ((lane >> 4) << 3);
    const int b_ecol = (((lane >> 3) & 1) << 3);
    const int v_key = (lane & 7) + (((lane >> 3) & 1) << 3);
    const int v_ecol = ((lane >> 4) << 3);

    const int r0 = w * 16 + gid;
    const int r1 = r0 + 8;

    for (int kt = 0; kt < 8; kt++) {
        if (kt == 7) { CP_WAIT0; } else { CP_WAIT1; }
        __syncthreads();

        const int pK = (kt & 1) ? AK1_OFF : AK0_OFF;
        const int pV = (kt & 1) ? AV1_OFF : AV0_OFF;
        const int pD = (kt & 1) ? AD1_OFF : AD0_OFF;

        // ---- S = Q K^T : 16 rows x 64 keys per warp ----
        float acc[8][4] = {};
        #pragma unroll
        for (int ks = 0; ks < 8; ks++) {
            unsigned aq[4];
            ldsm4(aq, sb + AQ_OFF + (unsigned)((w * 16 + a_row) * 272 + (ks * 16 + a_col) * 2));
            #pragma unroll
            for (int ng = 0; ng < 4; ng++) {
                unsigned bk4[4];
                ldsm4(bk4, sb + pK + (unsigned)((ng * 16 + b_key) * 272 + (ks * 16 + b_ecol) * 2));
                mma_f16(acc[2*ng],   aq, bk4[0], bk4[1]);
                mma_f16(acc[2*ng+1], aq, bk4[2], bk4[3]);
            }
        }

        // ---- + dist (pre-scaled fp16), key mask, row max ----
        float mx0 = -3.0e38f, mx1 = -3.0e38f;
        #pragma unroll
        for (int nf = 0; nf < 8; nf++) {
            const int c = nf * 8 + 2 * tig;
            const int gcol = kt * 64 + c;
            unsigned du0 = *(const unsigned*)(smc + pD + r0 * 144 + c * 2);
            unsigned du1 = *(const unsigned*)(smc + pD + r1 * 144 + c * 2);
            float2 d0 = __half22float2(*(__half2*)&du0);
            float2 d1 = __half22float2(*(__half2*)&du1);
            const bool k0 = (mk[gcol] != 0.f), k1 = (mk[gcol + 1] != 0.f);
            float s0 = k0 ? acc[nf][0] + d0.x : NEGV;
            float s1 = k1 ? acc[nf][1] + d0.y : NEGV;
            float s2 = k0 ? acc[nf][2] + d1.x : NEGV;
            float s3 = k1 ? acc[nf][3] + d1.y : NEGV;
            acc[nf][0] = s0; acc[nf][1] = s1; acc[nf][2] = s2; acc[nf][3] = s3;
            mx0 = fmaxf(mx0, fmaxf(s0, s1));
            mx1 = fmaxf(mx1, fmaxf(s2, s3));
        }
        mx0 = fmaxf(mx0, __shfl_xor_sync(0xffffffffu, mx0, 1));
        mx0 = fmaxf(mx0, __shfl_xor_sync(0xffffffffu, mx0, 2));
        mx1 = fmaxf(mx1, __shfl_xor_sync(0xffffffffu, mx1, 1));
        mx1 = fmaxf(mx1, __shfl_xor_sync(0xffffffffu, mx1, 2));

        const float mn0 = fmaxf(m0, mx0), mn1 = fmaxf(m1, mx1);
        const float al0 = ex2f(m0 - mn0), al1 = ex2f(m1 - mn1);

        // ---- P = exp2(S - m) into PV A-fragments ----
        unsigned pa[4][4];
        float rs0 = 0.f, rs1 = 0.f;
        #pragma unroll
        for (int ks = 0; ks < 4; ks++) {
            float p0 = ex2f(acc[2*ks][0] - mn0);
            float p1 = ex2f(acc[2*ks][1] - mn0);
            float p2 = ex2f(acc[2*ks][2] - mn1);
            float p3 = ex2f(acc[2*ks][3] - mn1);
            float p4 = ex2f(acc[2*ks+1][0] - mn0);
            float p5 = ex2f(acc[2*ks+1][1] - mn0);
            float p6 = ex2f(acc[2*ks+1][2] - mn1);
            float p7 = ex2f(acc[2*ks+1][3] - mn1);
            rs0 += (p0 + p1) + (p4 + p5);
            rs1 += (p2 + p3) + (p6 + p7);
            pa[ks][0] = pack_h2(p0, p1);
            pa[ks][1] = pack_h2(p2, p3);
            pa[ks][2] = pack_h2(p4, p5);
            pa[ks][3] = pack_h2(p6, p7);
        }
        rs0 += __shfl_xor_sync(0xffffffffu, rs0, 1);
        rs0 += __shfl_xor_sync(0xffffffffu, rs0, 2);
        rs1 += __shfl_xor_sync(0xffffffffu, rs1, 1);
        rs1 += __shfl_xor_sync(0xffffffffu, rs1, 2);
        l0 = al0 * l0 + rs0;  l1 = al1 * l1 + rs1;
        m0 = mn0;             m1 = mn1;

        #pragma unroll
        for (int nf = 0; nf < 16; nf++) {
            o[nf][0] *= al0; o[nf][1] *= al0;
            o[nf][2] *= al1; o[nf][3] *= al1;
        }

        // ---- O += P V ----
        #pragma unroll
        for (int ks = 0; ks < 4; ks++) {
            #pragma unroll
            for (int ng = 0; ng < 8; ng++) {
                unsigned vh4[4];
                ldsm4t(vh4, sb + pV + (unsigned)((ks * 16 + v_key) * 272 + (ng * 16 + v_ecol) * 2));
                mma_f16(o[2*ng],   pa[ks], vh4[0], vh4[1]);
                mma_f16(o[2*ng+1], pa[ks], vh4[2], vh4[3]);
            }
        }
        __syncthreads();          // buffer pK/pV/pD fully consumed

        if (kt < 6) {
            loadKVD(kt + 2, pK, pV, pD);
            CP_COMMIT;
        }
    }

    // ---- normalize, store packed fp16 ----
    const float li0 = 1.f / l0, li1 = 1.f / l1;
    unsigned* Y = g_y16 + (((size_t)bh * N_ + q0) << 6);
    #pragma unroll
    for (int nf = 0; nf < 16; nf++) {
        const int e = nf * 8 + 2 * tig;
        Y[(size_t)r0 * 64 + (e >> 1)] = pack_h2(o[nf][0] * li0, o[nf][1] * li0);
        Y[(size_t)r1 * 64 + (e >> 1)] = pack_h2(o[nf][2] * li1, o[nf][3] * li1);
    }
}

// ---------------------------------------------------------------------------
// Kernel 3: out = Y @ Wo^T + bo, * mask (unchanged, ~18us).
// ---------------------------------------------------------------------------
#define OG_A 0
#define OG_B 17408
#define SMEM_OPROJ 34816

__global__ __launch_bounds__(256, 3) void oproj_mma_kernel(
    const float* __restrict__ bo,
    const float* __restrict__ mask, float* __restrict__ out)
{
    extern __shared__ char smc[];
    const unsigned sb = smem_u32(smc);

    const int tid  = threadIdx.x;
    const int lane = tid & 31;
    const int wid  = tid >> 5;
    const int wm   = wid >> 1;
    const int wn   = wid & 1;
    const int gid  = lane >> 2;
    const int tig  = lane & 3;

    const int row0 = blockIdx.x << 6;
    const int col0 = blockIdx.y << 6;
    const int b    = row0 >> 9;
    const int n0   = row0 & 511;

    const int a_row = (lane & 15);
    const int a_col = ((lane >> 4) << 3);
    const int b_key = (lane & 7) + ((lane >> 4) << 3);
    const int b_ecol = (((lane >> 3) & 1) << 3);

    float acc[4][4] = {};

    for (int h = 0; h < 8; h++) {
        const size_t ab = ((size_t)(b * H_ + h) * N_ + n0) << 6;
        copy16_async(g_y16 + ab, sb, OG_A, 64, tid, 256);
        for (int idx = tid; idx < 1024; idx += 256) {
            int r = idx >> 4, c = idx & 15;
            size_t su = (size_t)(col0 + r) * 512 + h * 64 + c * 4;
            CP16(sb + OG_B + r * 272 + c * 16, g_wo16 + su);
        }
        CP_COMMIT; CP_WAIT0;
        __syncthreads();

        #pragma unroll
        for (int k = 0; k < 8; k++) {
            unsigned ah[4];
            unsigned ao = (unsigned)((wm * 16 + a_row) * 272 + (k * 16 + a_col) * 2);
            ldsm4(ah, sb + OG_A + ao);
            #pragma unroll
            for (int ng = 0; ng < 2; ng++) {
                unsigned bo_ = (unsigned)((wn * 32 + ng * 16 + b_key) * 272 + (k * 16 + b_ecol) * 2);
                unsigned bh4[4];
                ldsm4(bh4, sb + OG_B + bo_);
                mma_f16(acc[2*ng],   ah, bh4[0], bh4[1]);
                mma_f16(acc[2*ng+1], ah, bh4[2], bh4[3]);
            }
        }
        __syncthreads();
    }

    const int lr0 = wm * 16 + gid;
    const int rw0 = row0 + lr0;
    const float mv0 = mask[b * 512 + (rw0 & 511)];
    const float mv1 = mask[b * 512 + ((rw0 + 8) & 511)];
    #pragma unroll
    for (int nf = 0; nf < 4; nf++) {
        const int cb = col0 + wn * 32 + nf * 8 + 2 * tig;
        const float b0v = bo[cb], b1v = bo[cb + 1];
        *(float2*)&out[(size_t)rw0 * E_ + cb] =
            make_float2((acc[nf][0] + b0v) * mv0, (acc[nf][1] + b1v) * mv0);
        *(float2*)&out[(size_t)(rw0 + 8) * E_ + cb] =
            make_float2((acc[nf][2] + b0v) * mv1, (acc[nf][3] + b1v) * mv1);
    }
}

// ---------------------------------------------------------------------------
extern "C" void kernel_launch(void* const* d_in, const int* in_sizes, int n_in,
                              void* d_out, int out_size)
{
    const float* x    = (const float*)d_in[0];
    const float* dist = (const float*)d_in[1];
    const float* mask = (const float*)d_in[2];
    const float* Wq   = (const float*)d_in[3];
    const float* bq   = (const float*)d_in[4];
    const float* Wk   = (const float*)d_in[5];
    const float* bk   = (const float*)d_in[6];
    const float* Wv   = (const float*)d_in[7];
    const float* bv   = (const float*)d_in[8];
    const float* Wo   = (const float*)d_in[9];
    const float* bo   = (const float*)d_in[10];
    float* out = (float*)d_out;

    cudaFuncSetAttribute(qkv_mma_kernel,
                         cudaFuncAttributeMaxDynamicSharedMemorySize, SMEM_QKV);
    cudaFuncSetAttribute(attn_mma_kernel,
                         cudaFuncAttributeMaxDynamicSharedMemorySize, SMEM_ATTN);
    cudaFuncSetAttribute(oproj_mma_kernel,
                         cudaFuncAttributeMaxDynamicSharedMemorySize, SMEM_OPROJ);

    wsplit_kernel<<<256, 256>>>(Wo);
    dprep_kernel<<<8192, 256>>>(dist);
    qkv_mma_kernel<<<dim3(64, 8, 3), 256, SMEM_QKV>>>(x, Wq, bq, Wk, bk, Wv, bv);
    attn_mma_kernel<<<dim3(8, 128), 128, SMEM_ATTN>>>(mask);
    oproj_mma_kernel<<<dim3(128, 2), 256, SMEM_OPROJ>>>(bo, mask, out);
}

// round 13
// speedup vs baseline: 2.3497x; 1.0357x over previous
#include <cuda_runtime.h>
#include <cuda_bf16.h>
#include <cuda_fp16.h>
#include <math.h>

#define B_ 16
#define N_ 512
#define H_ 8
#define E_ 128
#define BH_ (B_*H_)
#define NEGV (-1000000000.0f)
#define SCALE_ 0.08838834764831845f
#define LOG2E_ 1.4426950408889634f
#define QSCALE_ (SCALE_ * LOG2E_)
#define DNEG_ (-30000.0f)

// q/k/v/y/Wo as packed fp16x2 arrays. dist pre-scaled by log2e with key-mask baked in.
__device__ unsigned g_q16[BH_*N_*E_/2];
__device__ unsigned g_k16[BH_*N_*E_/2];
__device__ unsigned g_v16[BH_*N_*E_/2];
__device__ unsigned g_y16[BH_*N_*E_/2];
__device__ unsigned g_wo16[E_*1024/2];
__device__ unsigned g_d16[B_*N_*N_/2];

// ---------------------------------------------------------------------------
// helpers
// ---------------------------------------------------------------------------
__device__ __forceinline__ unsigned smem_u32(const void* p) {
    unsigned r;
    asm("{ .reg .u64 t; cvta.to.shared.u64 t, %1; cvt.u32.u64 %0, t; }" : "=r"(r) : "l"(p));
    return r;
}
__device__ __forceinline__ void ldsm4(unsigned r[4], unsigned addr) {
    asm volatile("ldmatrix.sync.aligned.m8n8.x4.shared.b16 {%0,%1,%2,%3}, [%4];"
        : "=r"(r[0]), "=r"(r[1]), "=r"(r[2]), "=r"(r[3]) : "r"(addr));
}
__device__ __forceinline__ void ldsm4t(unsigned r[4], unsigned addr) {
    asm volatile("ldmatrix.sync.aligned.m8n8.x4.trans.shared.b16 {%0,%1,%2,%3}, [%4];"
        : "=r"(r[0]), "=r"(r[1]), "=r"(r[2]), "=r"(r[3]) : "r"(addr));
}
__device__ __forceinline__ void mma_f16(float c[4], const unsigned a[4],
                                        unsigned b0, unsigned b1) {
    asm volatile("mma.sync.aligned.m16n8k16.row.col.f32.f16.f16.f32 "
        "{%0,%1,%2,%3}, {%4,%5,%6,%7}, {%8,%9}, {%0,%1,%2,%3};"
        : "+f"(c[0]), "+f"(c[1]), "+f"(c[2]), "+f"(c[3])
        : "r"(a[0]), "r"(a[1]), "r"(a[2]), "r"(a[3]), "r"(b0), "r"(b1));
}
__device__ __forceinline__ unsigned pack_h2(float a, float b) {
    __half2 h = __floats2half2_rn(a, b);
    return *(unsigned*)&h;
}
__device__ __forceinline__ float ex2f(float x) {
    float r;
    asm("ex2.approx.f32 %0, %1;" : "=f"(r) : "f"(x));
    return r;
}

#define CP16(dst, src) \
    asm volatile("cp.async.cg.shared.global [%0], [%1], 16;" \
        :: "r"(dst), "l"(__cvta_generic_to_global(src)) : "memory")
#define CP_COMMIT asm volatile("cp.async.commit_group;" ::: "memory")
#define CP_WAIT0  asm volatile("cp.async.wait_group 0;" ::: "memory")
#define CP_WAIT1  asm volatile("cp.async.wait_group 1;" ::: "memory")

// fp32 tile -> fp16 smem (272B row stride); 256 threads
__device__ __forceinline__ void load_h16(const float* __restrict__ src,
        size_t stride, char* smc, int off, int rows, int tid)
{
    const int total = rows * 32;
    for (int idx = tid; idx < total; idx += 256) {
        int r = idx >> 5, c4 = idx & 31;
        float4 v = *(const float4*)(src + (size_t)r * stride + c4 * 4);
        *(uint2*)(smc + off + r * 272 + c4 * 8) =
            make_uint2(pack_h2(v.x, v.y), pack_h2(v.z, v.w));
    }
}

// packed-fp16 tile async copy: global (row stride 64 u32) -> smem 272B stride
__device__ __forceinline__ void copy16_async(const unsigned* __restrict__ src,
        unsigned sb, int off, int rows, int tid, int nthr)
{
    const int total = rows * 16;
    for (int idx = tid; idx < total; idx += nthr) {
        int r = idx >> 4, c = idx & 15;
        CP16(sb + off + r * 272 + c * 16, src + (size_t)r * 64 + c * 4);
    }
}

// ---------------------------------------------------------------------------
// Kernel 1: QKV projection (z<3) + fused prep slice (z==3: Wo + dist convert).
// ---------------------------------------------------------------------------
#define QG_X 0
#define QG_W 34816
#define SMEM_QKV 69632

__global__ __launch_bounds__(256, 2) void qkv_mma_kernel(
    const float* __restrict__ x,
    const float* __restrict__ Wq, const float* __restrict__ bq,
    const float* __restrict__ Wk, const float* __restrict__ bk,
    const float* __restrict__ Wv, const float* __restrict__ bv,
    const float* __restrict__ Wo, const float* __restrict__ dist,
    const float* __restrict__ mask)
{
    const int which = blockIdx.z;
    const int tid  = threadIdx.x;

    if (which == 3) {
        // ---- prep slice: 512 CTAs x 256 threads ----
        const int flat = (blockIdx.y * 64 + blockIdx.x) * 256 + tid;  // 0..131071
        // Wo -> fp16 (65536 pairs)
        if (flat < 65536) {
            float2 v = *(const float2*)(Wo + 2 * flat);
            g_wo16[flat] = pack_h2(v.x, v.y);
        }
        // dist -> fp16 * log2e with key mask baked in (2,097,152 pairs)
        #pragma unroll
        for (int j = 0; j < 16; j++) {
            int i = flat + j * 131072;
            float2 v = *(const float2*)(dist + 2 * (size_t)i);
            int k0 = (2 * i) & 511;
            int row = i >> 8;              // b*512 + q
            int b = row >> 9;
            float m0 = mask[b * 512 + k0], m1 = mask[b * 512 + k0 + 1];
            g_d16[i] = pack_h2((m0 != 0.f) ? v.x * LOG2E_ : DNEG_,
                               (m1 != 0.f) ? v.y * LOG2E_ : DNEG_);
        }
        return;
    }

    extern __shared__ char smc[];
    const unsigned sb = smem_u32(smc);

    const float* __restrict__ W    = (which == 0) ? Wq : (which == 1) ? Wk : Wv;
    const float* __restrict__ bias = (which == 0) ? bq : (which == 1) ? bk : bv;
    unsigned* __restrict__ dst = (which == 0) ? g_q16 : (which == 1) ? g_k16 : g_v16;

    const int lane = tid & 31;
    const int wid  = tid >> 5;
    const int wm   = wid >> 1;
    const int wn   = wid & 1;
    const int gid  = lane >> 2;
    const int tig  = lane & 3;

    const int row0 = blockIdx.x << 7;
    const int col0 = blockIdx.y << 7;

    const int a_row = (lane & 15);
    const int a_col = ((lane >> 4) << 3);
    const int b_key = (lane & 7) + ((lane >> 4) << 3);
    const int b_ecol = (((lane >> 3) & 1) << 3);

    load_h16(x + (size_t)row0 * E_, E_, smc, QG_X, 128, tid);
    load_h16(W + (size_t)col0 * E_, E_, smc, QG_W, 128, tid);
    __syncthreads();

    float acc[2][8][4] = {};
    #pragma unroll
    for (int k = 0; k < 8; k++) {
        unsigned ah[2][4];
        #pragma unroll
        for (int mf = 0; mf < 2; mf++) {
            unsigned ao = (unsigned)((wm * 32 + mf * 16 + a_row) * 272 + (k * 16 + a_col) * 2);
            ldsm4(ah[mf], sb + QG_X + ao);
        }
        #pragma unroll
        for (int ng = 0; ng < 4; ng++) {
            unsigned bo = (unsigned)((wn * 64 + ng * 16 + b_key) * 272 + (k * 16 + b_ecol) * 2);
            unsigned bh4[4];
            ldsm4(bh4, sb + QG_W + bo);
            #pragma unroll
            for (int mf = 0; mf < 2; mf++) {
                mma_f16(acc[mf][2*ng],   ah[mf], bh4[0], bh4[1]);
                mma_f16(acc[mf][2*ng+1], ah[mf], bh4[2], bh4[3]);
            }
        }
    }

    const int hh = col0 >> 7;
    const float sc = (which == 0) ? QSCALE_ : 1.0f;
    #pragma unroll
    for (int mf = 0; mf < 2; mf++) {
        const int lr0 = wm * 32 + mf * 16 + gid;
        #pragma unroll
        for (int nf = 0; nf < 8; nf++) {
            const int cb = wn * 64 + nf * 8 + 2 * tig;
            const float b0v = bias[col0 + cb], b1v = bias[col0 + cb + 1];
            float v0 = (acc[mf][nf][0] + b0v) * sc;
            float v1 = (acc[mf][nf][1] + b1v) * sc;
            float v2 = (acc[mf][nf][2] + b0v) * sc;
            float v3 = (acc[mf][nf][3] + b1v) * sc;
            int rw = row0 + lr0;
            int b = rw >> 9, n = rw & 511;
            dst[(((size_t)(b * H_ + hh) * N_ + n) << 6) + (cb >> 1)] = pack_h2(v0, v1);
            rw += 8; b = rw >> 9; n = rw & 511;
            dst[(((size_t)(b * H_ + hh) * N_ + n) << 6) + (cb >> 1)] = pack_h2(v2, v3);
        }
    }
}

// ---------------------------------------------------------------------------
// Kernel 2: flash attention. 64 q-rows x 64-key chunks, double-buffered
// K/V/dist(fp16, mask baked in), 128 thr, 2 CTAs/SM.
// ---------------------------------------------------------------------------
#define AQ_OFF    0
#define AK0_OFF   17408
#define AV0_OFF   34816
#define AD0_OFF   52224
#define AK1_OFF   61440
#define AV1_OFF   78848
#define AD1_OFF   96256
#define SMEM_ATTN 105472

__global__ __launch_bounds__(128, 2) void attn_mma_kernel()
{
    extern __shared__ char smc[];
    const unsigned sb = smem_u32(smc);

    const int tid  = threadIdx.x;
    const int lane = tid & 31;
    const int w    = tid >> 5;
    const int gid  = lane >> 2;
    const int tig  = lane & 3;

    const int q0 = blockIdx.x << 6;
    const int bh = blockIdx.y;
    const int b  = bh >> 3;

    auto loadKVD = [&](int kt, int kOff, int vOff, int dOff) {
        const size_t nb = ((size_t)bh * N_ + kt * 64) << 6;
        copy16_async(g_k16 + nb, sb, kOff, 64, tid, 128);
        copy16_async(g_v16 + nb, sb, vOff, 64, tid, 128);
        const unsigned* dsrc = g_d16 + ((size_t)b * N_ + q0) * 256 + kt * 32;
        #pragma unroll
        for (int i = 0; i < 4; i++) {
            int idx = tid + (i << 7);
            int r = idx >> 3, c = idx & 7;
            CP16(sb + dOff + r * 144 + c * 16, dsrc + (size_t)r * 256 + c * 4);
        }
    };

    copy16_async(g_q16 + (((size_t)bh * N_ + q0) << 6), sb, AQ_OFF, 64, tid, 128);
    loadKVD(0, AK0_OFF, AV0_OFF, AD0_OFF);
    CP_COMMIT;
    loadKVD(1, AK1_OFF, AV1_OFF, AD1_OFF);
    CP_COMMIT;

    float o[16][4] = {};
    float m0 = -3.0e38f, m1 = -3.0e38f, l0 = 0.f, l1 = 0.f;

    const int a_row = (lane & 15);
    const int a_col = ((lane >> 4) << 3);
    const int b_key = (lane & 7) + ((lane >> 4) << 3);
    const int b_ecol = (((lane >> 3) & 1) << 3);
    const int v_key = (lane & 7) + (((lane >> 3) & 1) << 3);
    const int v_ecol = ((lane >> 4) << 3);

    const int r0 = w * 16 + gid;
    const int r1 = r0 + 8;

    for (int kt = 0; kt < 8; kt++) {
        if (kt == 7) { CP_WAIT0; } else { CP_WAIT1; }
        __syncthreads();

        const int pK = (kt & 1) ? AK1_OFF : AK0_OFF;
        const int pV = (kt & 1) ? AV1_OFF : AV0_OFF;
        const int pD = (kt & 1) ? AD1_OFF : AD0_OFF;

        // ---- S = Q K^T ----
        float acc[8][4] = {};
        #pragma unroll
        for (int ks = 0; ks < 8; ks++) {
            unsigned aq[4];
            ldsm4(aq, sb + AQ_OFF + (unsigned)((w * 16 + a_row) * 272 + (ks * 16 + a_col) * 2));
            #pragma unroll
            for (int ng = 0; ng < 4; ng++) {
                unsigned bk4[4];
                ldsm4(bk4, sb + pK + (unsigned)((ng * 16 + b_key) * 272 + (ks * 16 + b_ecol) * 2));
                mma_f16(acc[2*ng],   aq, bk4[0], bk4[1]);
                mma_f16(acc[2*ng+1], aq, bk4[2], bk4[3]);
            }
        }

        // ---- + dist (mask baked in), row max ----
        float mx0 = -3.0e38f, mx1 = -3.0e38f;
        #pragma unroll
        for (int nf = 0; nf < 8; nf++) {
            const int c = nf * 8 + 2 * tig;
            unsigned du0 = *(const unsigned*)(smc + pD + r0 * 144 + c * 2);
            unsigned du1 = *(const unsigned*)(smc + pD + r1 * 144 + c * 2);
            float2 d0 = __half22float2(*(__half2*)&du0);
            float2 d1 = __half22float2(*(__half2*)&du1);
            float s0 = acc[nf][0] + d0.x;
            float s1 = acc[nf][1] + d0.y;
            float s2 = acc[nf][2] + d1.x;
            float s3 = acc[nf][3] + d1.y;
            acc[nf][0] = s0; acc[nf][1] = s1; acc[nf][2] = s2; acc[nf][3] = s3;
            mx0 = fmaxf(mx0, fmaxf(s0, s1));
            mx1 = fmaxf(mx1, fmaxf(s2, s3));
        }
        mx0 = fmaxf(mx0, __shfl_xor_sync(0xffffffffu, mx0, 1));
        mx0 = fmaxf(mx0, __shfl_xor_sync(0xffffffffu, mx0, 2));
        mx1 = fmaxf(mx1, __shfl_xor_sync(0xffffffffu, mx1, 1));
        mx1 = fmaxf(mx1, __shfl_xor_sync(0xffffffffu, mx1, 2));

        const float mn0 = fmaxf(m0, mx0), mn1 = fmaxf(m1, mx1);
        const float al0 = ex2f(m0 - mn0), al1 = ex2f(m1 - mn1);

        // ---- P = exp2(S - m) into PV A-fragments ----
        unsigned pa[4][4];
        float rs0 = 0.f, rs1 = 0.f;
        #pragma unroll
        for (int ks = 0; ks < 4; ks++) {
            float p0 = ex2f(acc[2*ks][0] - mn0);
            float p1 = ex2f(acc[2*ks][1] - mn0);
            float p2 = ex2f(acc[2*ks][2] - mn1);
            float p3 = ex2f(acc[2*ks][3] - mn1);
            float p4 = ex2f(acc[2*ks+1][0] - mn0);
            float p5 = ex2f(acc[2*ks+1][1] - mn0);
            float p6 = ex2f(acc[2*ks+1][2] - mn1);
            float p7 = ex2f(acc[2*ks+1][3] - mn1);
            rs0 += (p0 + p1) + (p4 + p5);
            rs1 += (p2 + p3) + (p6 + p7);
            pa[ks][0] = pack_h2(p0, p1);
            pa[ks][1] = pack_h2(p2, p3);
            pa[ks][2] = pack_h2(p4, p5);
            pa[ks][3] = pack_h2(p6, p7);
        }
        rs0 += __shfl_xor_sync(0xffffffffu, rs0, 1);
        rs0 += __shfl_xor_sync(0xffffffffu, rs0, 2);
        rs1 += __shfl_xor_sync(0xffffffffu, rs1, 1);
        rs1 += __shfl_xor_sync(0xffffffffu, rs1, 2);
        l0 = al0 * l0 + rs0;  l1 = al1 * l1 + rs1;
        m0 = mn0;             m1 = mn1;

        #pragma unroll
        for (int nf = 0; nf < 16; nf++) {
            o[nf][0] *= al0; o[nf][1] *= al0;
            o[nf][2] *= al1; o[nf][3] *= al1;
        }

        // ---- O += P V ----
        #pragma unroll
        for (int ks = 0; ks < 4; ks++) {
            #pragma unroll
            for (int ng = 0; ng < 8; ng++) {
                unsigned vh4[4];
                ldsm4t(vh4, sb + pV + (unsigned)((ks * 16 + v_key) * 272 + (ng * 16 + v_ecol) * 2));
                mma_f16(o[2*ng],   pa[ks], vh4[0], vh4[1]);
                mma_f16(o[2*ng+1], pa[ks], vh4[2], vh4[3]);
            }
        }
        __syncthreads();

        if (kt < 6) {
            loadKVD(kt + 2, pK, pV, pD);
            CP_COMMIT;
        }
    }

    const float li0 = 1.f / l0, li1 = 1.f / l1;
    unsigned* Y = g_y16 + (((size_t)bh * N_ + q0) << 6);
    #pragma unroll
    for (int nf = 0; nf < 16; nf++) {
        const int e = nf * 8 + 2 * tig;
        Y[(size_t)r0 * 64 + (e >> 1)] = pack_h2(o[nf][0] * li0, o[nf][1] * li0);
        Y[(size_t)r1 * 64 + (e >> 1)] = pack_h2(o[nf][2] * li1, o[nf][3] * li1);
    }
}

// ---------------------------------------------------------------------------
// Kernel 3: out = Y @ Wo^T + bo, * mask (unchanged, ~18us).
// ---------------------------------------------------------------------------
#define OG_A 0
#define OG_B 17408
#define SMEM_OPROJ 34816

__global__ __launch_bounds__(256, 3) void oproj_mma_kernel(
    const float* __restrict__ bo,
    const float* __restrict__ mask, float* __restrict__ out)
{
    extern __shared__ char smc[];
    const unsigned sb = smem_u32(smc);

    const int tid  = threadIdx.x;
    const int lane = tid & 31;
    const int wid  = tid >> 5;
    const int wm   = wid >> 1;
    const int wn   = wid & 1;
    const int gid  = lane >> 2;
    const int tig  = lane & 3;

    const int row0 = blockIdx.x << 6;
    const int col0 = blockIdx.y << 6;
    const int b    = row0 >> 9;
    const int n0   = row0 & 511;

    const int a_row = (lane & 15);
    const int a_col = ((lane >> 4) << 3);
    const int b_key = (lane & 7) + ((lane >> 4) << 3);
    const int b_ecol = (((lane >> 3) & 1) << 3);

    float acc[4][4] = {};

    for (int h = 0; h < 8; h++) {
        const size_t ab = ((size_t)(b * H_ + h) * N_ + n0) << 6;
        copy16_async(g_y16 + ab, sb, OG_A, 64, tid, 256);
        for (int idx = tid; idx < 1024; idx += 256) {
            int r = idx >> 4, c = idx & 15;
            size_t su = (size_t)(col0 + r) * 512 + h * 64 + c * 4;
            CP16(sb + OG_B + r * 272 + c * 16, g_wo16 + su);
        }
        CP_COMMIT; CP_WAIT0;
        __syncthreads();

        #pragma unroll
        for (int k = 0; k < 8; k++) {
            unsigned ah[4];
            unsigned ao = (unsigned)((wm * 16 + a_row) * 272 + (k * 16 + a_col) * 2);
            ldsm4(ah, sb + OG_A + ao);
            #pragma unroll
            for (int ng = 0; ng < 2; ng++) {
                unsigned bo_ = (unsigned)((wn * 32 + ng * 16 + b_key) * 272 + (k * 16 + b_ecol) * 2);
                unsigned bh4[4];
                ldsm4(bh4, sb + OG_B + bo_);
                mma_f16(acc[2*ng],   ah, bh4[0], bh4[1]);
                mma_f16(acc[2*ng+1], ah, bh4[2], bh4[3]);
            }
        }
        __syncthreads();
    }

    const int lr0 = wm * 16 + gid;
    const int rw0 = row0 + lr0;
    const float mv0 = mask[b * 512 + (rw0 & 511)];
    const float mv1 = mask[b * 512 + ((rw0 + 8) & 511)];
    #pragma unroll
    for (int nf = 0; nf < 4; nf++) {
        const int cb = col0 + wn * 32 + nf * 8 + 2 * tig;
        const float b0v = bo[cb], b1v = bo[cb + 1];
        *(float2*)&out[(size_t)rw0 * E_ + cb] =
            make_float2((acc[nf][0] + b0v) * mv0, (acc[nf][1] + b1v) * mv0);
        *(float2*)&out[(size_t)(rw0 + 8) * E_ + cb] =
            make_float2((acc[nf][2] + b0v) * mv1, (acc[nf][3] + b1v) * mv1);
    }
}

// ---------------------------------------------------------------------------
extern "C" void kernel_launch(void* const* d_in, const int* in_sizes, int n_in,
                              void* d_out, int out_size)
{
    const float* x    = (const float*)d_in[0];
    const float* dist = (const float*)d_in[1];
    const float* mask = (const float*)d_in[2];
    const float* Wq   = (const float*)d_in[3];
    const float* bq   = (const float*)d_in[4];
    const float* Wk   = (const float*)d_in[5];
    const float* bk   = (const float*)d_in[6];
    const float* Wv   = (const float*)d_in[7];
    const float* bv   = (const float*)d_in[8];
    const float* Wo   = (const float*)d_in[9];
    const float* bo   = (const float*)d_in[10];
    float* out = (float*)d_out;

    cudaFuncSetAttribute(qkv_mma_kernel,
                         cudaFuncAttributeMaxDynamicSharedMemorySize, SMEM_QKV);
    cudaFuncSetAttribute(attn_mma_kernel,
                         cudaFuncAttributeMaxDynamicSharedMemorySize, SMEM_ATTN);
    cudaFuncSetAttribute(oproj_mma_kernel,
                         cudaFuncAttributeMaxDynamicSharedMemorySize, SMEM_OPROJ);

    qkv_mma_kernel<<<dim3(64, 8, 4), 256, SMEM_QKV>>>(x, Wq, bq, Wk, bk, Wv, bv,
                                                      Wo, dist, mask);
    attn_mma_kernel<<<dim3(8, 128), 128, SMEM_ATTN>>>();
    oproj_mma_kernel<<<dim3(128, 2), 256, SMEM_OPROJ>>>(bo, mask, out);
}

// round 14
// speedup vs baseline: 2.9460x; 1.2538x over previous
#include <cuda_runtime.h>
#include <cuda_bf16.h>
#include <cuda_fp16.h>
#include <math.h>

#define B_ 16
#define N_ 512
#define H_ 8
#define E_ 128
#define BH_ (B_*H_)
#define NEGV (-1000000000.0f)
#define SCALE_ 0.08838834764831845f
#define LOG2E_ 1.4426950408889634f
#define QSCALE_ (SCALE_ * LOG2E_)
#define DNEG_ (-30000.0f)

// fp16 packed (u32 = h2) arrays
__device__ unsigned g_x16[B_*N_*E_/2];        // [8192][64]
__device__ unsigned g_wq16[1024*E_/2];        // [1024][64]
__device__ unsigned g_wk16[1024*E_/2];
__device__ unsigned g_wv16[1024*E_/2];
__device__ unsigned g_wo16[E_*1024/2];        // [128][512]
__device__ unsigned g_q16[BH_*N_*E_/2];
__device__ unsigned g_k16[BH_*N_*E_/2];
__device__ unsigned g_v16[BH_*N_*E_/2];
__device__ unsigned g_y16[BH_*N_*E_/2];
__device__ unsigned g_d16[B_*N_*N_/2];        // dist * log2e, mask-baked

// ---------------------------------------------------------------------------
// helpers
// ---------------------------------------------------------------------------
__device__ __forceinline__ unsigned smem_u32(const void* p) {
    unsigned r;
    asm("{ .reg .u64 t; cvta.to.shared.u64 t, %1; cvt.u32.u64 %0, t; }" : "=r"(r) : "l"(p));
    return r;
}
__device__ __forceinline__ void ldsm4(unsigned r[4], unsigned addr) {
    asm volatile("ldmatrix.sync.aligned.m8n8.x4.shared.b16 {%0,%1,%2,%3}, [%4];"
        : "=r"(r[0]), "=r"(r[1]), "=r"(r[2]), "=r"(r[3]) : "r"(addr));
}
__device__ __forceinline__ void ldsm4t(unsigned r[4], unsigned addr) {
    asm volatile("ldmatrix.sync.aligned.m8n8.x4.trans.shared.b16 {%0,%1,%2,%3}, [%4];"
        : "=r"(r[0]), "=r"(r[1]), "=r"(r[2]), "=r"(r[3]) : "r"(addr));
}
__device__ __forceinline__ void mma_f16(float c[4], const unsigned a[4],
                                        unsigned b0, unsigned b1) {
    asm volatile("mma.sync.aligned.m16n8k16.row.col.f32.f16.f16.f32 "
        "{%0,%1,%2,%3}, {%4,%5,%6,%7}, {%8,%9}, {%0,%1,%2,%3};"
        : "+f"(c[0]), "+f"(c[1]), "+f"(c[2]), "+f"(c[3])
        : "r"(a[0]), "r"(a[1]), "r"(a[2]), "r"(a[3]), "r"(b0), "r"(b1));
}
__device__ __forceinline__ unsigned pack_h2(float a, float b) {
    __half2 h = __floats2half2_rn(a, b);
    return *(unsigned*)&h;
}
__device__ __forceinline__ float ex2f(float x) {
    float r;
    asm("ex2.approx.f32 %0, %1;" : "=f"(r) : "f"(x));
    return r;
}

#define CP16(dst, src) \
    asm volatile("cp.async.cg.shared.global [%0], [%1], 16;" \
        :: "r"(dst), "l"(__cvta_generic_to_global(src)) : "memory")
#define CP_COMMIT asm volatile("cp.async.commit_group;" ::: "memory")
#define CP_WAIT0  asm volatile("cp.async.wait_group 0;" ::: "memory")
#define CP_WAIT1  asm volatile("cp.async.wait_group 1;" ::: "memory")

// packed-fp16 tile async copy: global (row stride 64 u32) -> smem 272B stride
__device__ __forceinline__ void copy16_async(const unsigned* __restrict__ src,
        unsigned sb, int off, int rows, int tid, int nthr)
{
    const int total = rows * 16;
    for (int idx = tid; idx < total; idx += nthr) {
        int r = idx >> 4, c = idx & 15;
        CP16(sb + off + r * 272 + c * 16, src + (size_t)r * 64 + c * 4);
    }
}

// ---------------------------------------------------------------------------
// Kernel 0: convert all fp32 inputs to fp16 (x, Wq/k/v, Wo, dist+mask).
// 512 CTAs x 256 thr, pure streaming (~27MB).
// ---------------------------------------------------------------------------
__global__ __launch_bounds__(256) void prep_kernel(
    const float* __restrict__ x,
    const float* __restrict__ Wq, const float* __restrict__ Wk,
    const float* __restrict__ Wv, const float* __restrict__ Wo,
    const float* __restrict__ dist, const float* __restrict__ mask)
{
    const int flat = blockIdx.x * 256 + threadIdx.x;   // 0..131071

    // x: 524288 pairs -> 4 per thread
    #pragma unroll
    for (int j = 0; j < 4; j++) {
        int i = flat + j * 131072;
        float2 v = *(const float2*)(x + 2 * (size_t)i);
        g_x16[i] = pack_h2(v.x, v.y);
    }
    // weights: 65536 pairs each
    if (flat < 65536) {
        float2 vq = *(const float2*)(Wq + 2 * flat);
        float2 vk = *(const float2*)(Wk + 2 * flat);
        float2 vv = *(const float2*)(Wv + 2 * flat);
        float2 vo = *(const float2*)(Wo + 2 * flat);
        g_wq16[flat] = pack_h2(vq.x, vq.y);
        g_wk16[flat] = pack_h2(vk.x, vk.y);
        g_wv16[flat] = pack_h2(vv.x, vv.y);
        g_wo16[flat] = pack_h2(vo.x, vo.y);
    }
    // dist: 2,097,152 pairs -> 16 per thread, *log2e, key mask baked in
    #pragma unroll
    for (int j = 0; j < 16; j++) {
        int i = flat + j * 131072;
        float2 v = *(const float2*)(dist + 2 * (size_t)i);
        int k0 = (2 * i) & 511;
        int row = i >> 8;
        int b = row >> 9;
        float m0 = mask[b * 512 + k0], m1 = mask[b * 512 + k0 + 1];
        g_d16[i] = pack_h2((m0 != 0.f) ? v.x * LOG2E_ : DNEG_,
                           (m1 != 0.f) ? v.y * LOG2E_ : DNEG_);
    }
}

// ---------------------------------------------------------------------------
// Kernel 1: QKV projection, pure fp16 GEMM, cp.async loads. 2 CTAs/SM.
// ---------------------------------------------------------------------------
#define QG_X 0
#define QG_W 34816
#define SMEM_QKV 69632

__global__ __launch_bounds__(256, 2) void qkv_mma_kernel(
    const float* __restrict__ bq, const float* __restrict__ bk,
    const float* __restrict__ bv)
{
    extern __shared__ char smc[];
    const unsigned sb = smem_u32(smc);

    const int which = blockIdx.z;
    const unsigned* __restrict__ Wsel =
        (which == 0) ? g_wq16 : (which == 1) ? g_wk16 : g_wv16;
    const float* __restrict__ bias = (which == 0) ? bq : (which == 1) ? bk : bv;
    unsigned* __restrict__ dst = (which == 0) ? g_q16 : (which == 1) ? g_k16 : g_v16;

    const int tid  = threadIdx.x;
    const int lane = tid & 31;
    const int wid  = tid >> 5;
    const int wm   = wid >> 1;
    const int wn   = wid & 1;
    const int gid  = lane >> 2;
    const int tig  = lane & 3;

    const int row0 = blockIdx.x << 7;
    const int col0 = blockIdx.y << 7;

    const int a_row = (lane & 15);
    const int a_col = ((lane >> 4) << 3);
    const int b_key = (lane & 7) + ((lane >> 4) << 3);
    const int b_ecol = (((lane >> 3) & 1) << 3);

    copy16_async(g_x16 + (size_t)row0 * 64, sb, QG_X, 128, tid, 256);
    copy16_async(Wsel + (size_t)col0 * 64, sb, QG_W, 128, tid, 256);
    CP_COMMIT; CP_WAIT0;
    __syncthreads();

    float acc[2][8][4] = {};
    #pragma unroll
    for (int k = 0; k < 8; k++) {
        unsigned ah[2][4];
        #pragma unroll
        for (int mf = 0; mf < 2; mf++) {
            unsigned ao = (unsigned)((wm * 32 + mf * 16 + a_row) * 272 + (k * 16 + a_col) * 2);
            ldsm4(ah[mf], sb + QG_X + ao);
        }
        #pragma unroll
        for (int ng = 0; ng < 4; ng++) {
            unsigned bo = (unsigned)((wn * 64 + ng * 16 + b_key) * 272 + (k * 16 + b_ecol) * 2);
            unsigned bh4[4];
            ldsm4(bh4, sb + QG_W + bo);
            #pragma unroll
            for (int mf = 0; mf < 2; mf++) {
                mma_f16(acc[mf][2*ng],   ah[mf], bh4[0], bh4[1]);
                mma_f16(acc[mf][2*ng+1], ah[mf], bh4[2], bh4[3]);
            }
        }
    }

    const int hh = col0 >> 7;
    const float sc = (which == 0) ? QSCALE_ : 1.0f;
    #pragma unroll
    for (int mf = 0; mf < 2; mf++) {
        const int lr0 = wm * 32 + mf * 16 + gid;
        #pragma unroll
        for (int nf = 0; nf < 8; nf++) {
            const int cb = wn * 64 + nf * 8 + 2 * tig;
            const float b0v = bias[col0 + cb], b1v = bias[col0 + cb + 1];
            float v0 = (acc[mf][nf][0] + b0v) * sc;
            float v1 = (acc[mf][nf][1] + b1v) * sc;
            float v2 = (acc[mf][nf][2] + b0v) * sc;
            float v3 = (acc[mf][nf][3] + b1v) * sc;
            int rw = row0 + lr0;
            int b = rw >> 9, n = rw & 511;
            dst[(((size_t)(b * H_ + hh) * N_ + n) << 6) + (cb >> 1)] = pack_h2(v0, v1);
            rw += 8; b = rw >> 9; n = rw & 511;
            dst[(((size_t)(b * H_ + hh) * N_ + n) << 6) + (cb >> 1)] = pack_h2(v2, v3);
        }
    }
}

// ---------------------------------------------------------------------------
// Kernel 2: flash attention (unchanged from R13: 64x64 chunks, double-
// buffered K/V/dist fp16 w/ baked mask, 128 thr, 2 CTAs/SM).
// ---------------------------------------------------------------------------
#define AQ_OFF    0
#define AK0_OFF   17408
#define AV0_OFF   34816
#define AD0_OFF   52224
#define AK1_OFF   61440
#define AV1_OFF   78848
#define AD1_OFF   96256
#define SMEM_ATTN 105472

__global__ __launch_bounds__(128, 2) void attn_mma_kernel()
{
    extern __shared__ char smc[];
    const unsigned sb = smem_u32(smc);

    const int tid  = threadIdx.x;
    const int lane = tid & 31;
    const int w    = tid >> 5;
    const int gid  = lane >> 2;
    const int tig  = lane & 3;

    const int q0 = blockIdx.x << 6;
    const int bh = blockIdx.y;
    const int b  = bh >> 3;

    auto loadKVD = [&](int kt, int kOff, int vOff, int dOff) {
        const size_t nb = ((size_t)bh * N_ + kt * 64) << 6;
        copy16_async(g_k16 + nb, sb, kOff, 64, tid, 128);
        copy16_async(g_v16 + nb, sb, vOff, 64, tid, 128);
        const unsigned* dsrc = g_d16 + ((size_t)b * N_ + q0) * 256 + kt * 32;
        #pragma unroll
        for (int i = 0; i < 4; i++) {
            int idx = tid + (i << 7);
            int r = idx >> 3, c = idx & 7;
            CP16(sb + dOff + r * 144 + c * 16, dsrc + (size_t)r * 256 + c * 4);
        }
    };

    copy16_async(g_q16 + (((size_t)bh * N_ + q0) << 6), sb, AQ_OFF, 64, tid, 128);
    loadKVD(0, AK0_OFF, AV0_OFF, AD0_OFF);
    CP_COMMIT;
    loadKVD(1, AK1_OFF, AV1_OFF, AD1_OFF);
    CP_COMMIT;

    float o[16][4] = {};
    float m0 = -3.0e38f, m1 = -3.0e38f, l0 = 0.f, l1 = 0.f;

    const int a_row = (lane & 15);
    const int a_col = ((lane >> 4) << 3);
    const int b_key = (lane & 7) + ((lane >> 4) << 3);
    const int b_ecol = (((lane >> 3) & 1) << 3);
    const int v_key = (lane & 7) + (((lane >> 3) & 1) << 3);
    const int v_ecol = ((lane >> 4) << 3);

    const int r0 = w * 16 + gid;
    const int r1 = r0 + 8;

    for (int kt = 0; kt < 8; kt++) {
        if (kt == 7) { CP_WAIT0; } else { CP_WAIT1; }
        __syncthreads();

        const int pK = (kt & 1) ? AK1_OFF : AK0_OFF;
        const int pV = (kt & 1) ? AV1_OFF : AV0_OFF;
        const int pD = (kt & 1) ? AD1_OFF : AD0_OFF;

        float acc[8][4] = {};
        #pragma unroll
        for (int ks = 0; ks < 8; ks++) {
            unsigned aq[4];
            ldsm4(aq, sb + AQ_OFF + (unsigned)((w * 16 + a_row) * 272 + (ks * 16 + a_col) * 2));
            #pragma unroll
            for (int ng = 0; ng < 4; ng++) {
                unsigned bk4[4];
                ldsm4(bk4, sb + pK + (unsigned)((ng * 16 + b_key) * 272 + (ks * 16 + b_ecol) * 2));
                mma_f16(acc[2*ng],   aq, bk4[0], bk4[1]);
                mma_f16(acc[2*ng+1], aq, bk4[2], bk4[3]);
            }
        }

        float mx0 = -3.0e38f, mx1 = -3.0e38f;
        #pragma unroll
        for (int nf = 0; nf < 8; nf++) {
            const int c = nf * 8 + 2 * tig;
            unsigned du0 = *(const unsigned*)(smc + pD + r0 * 144 + c * 2);
            unsigned du1 = *(const unsigned*)(smc + pD + r1 * 144 + c * 2);
            float2 d0 = __half22float2(*(__half2*)&du0);
            float2 d1 = __half22float2(*(__half2*)&du1);
            float s0 = acc[nf][0] + d0.x;
            float s1 = acc[nf][1] + d0.y;
            float s2 = acc[nf][2] + d1.x;
            float s3 = acc[nf][3] + d1.y;
            acc[nf][0] = s0; acc[nf][1] = s1; acc[nf][2] = s2; acc[nf][3] = s3;
            mx0 = fmaxf(mx0, fmaxf(s0, s1));
            mx1 = fmaxf(mx1, fmaxf(s2, s3));
        }
        mx0 = fmaxf(mx0, __shfl_xor_sync(0xffffffffu, mx0, 1));
        mx0 = fmaxf(mx0, __shfl_xor_sync(0xffffffffu, mx0, 2));
        mx1 = fmaxf(mx1, __shfl_xor_sync(0xffffffffu, mx1, 1));
        mx1 = fmaxf(mx1, __shfl_xor_sync(0xffffffffu, mx1, 2));

        const float mn0 = fmaxf(m0, mx0), mn1 = fmaxf(m1, mx1);
        const float al0 = ex2f(m0 - mn0), al1 = ex2f(m1 - mn1);

        unsigned pa[4][4];
        float rs0 = 0.f, rs1 = 0.f;
        #pragma unroll
        for (int ks = 0; ks < 4; ks++) {
            float p0 = ex2f(acc[2*ks][0] - mn0);
            float p1 = ex2f(acc[2*ks][1] - mn0);
            float p2 = ex2f(acc[2*ks][2] - mn1);
            float p3 = ex2f(acc[2*ks][3] - mn1);
            float p4 = ex2f(acc[2*ks+1][0] - mn0);
            float p5 = ex2f(acc[2*ks+1][1] - mn0);
            float p6 = ex2f(acc[2*ks+1][2] - mn1);
            float p7 = ex2f(acc[2*ks+1][3] - mn1);
            rs0 += (p0 + p1) + (p4 + p5);
            rs1 += (p2 + p3) + (p6 + p7);
            pa[ks][0] = pack_h2(p0, p1);
            pa[ks][1] = pack_h2(p2, p3);
            pa[ks][2] = pack_h2(p4, p5);
            pa[ks][3] = pack_h2(p6, p7);
        }
        rs0 += __shfl_xor_sync(0xffffffffu, rs0, 1);
        rs0 += __shfl_xor_sync(0xffffffffu, rs0, 2);
        rs1 += __shfl_xor_sync(0xffffffffu, rs1, 1);
        rs1 += __shfl_xor_sync(0xffffffffu, rs1, 2);
        l0 = al0 * l0 + rs0;  l1 = al1 * l1 + rs1;
        m0 = mn0;             m1 = mn1;

        #pragma unroll
        for (int nf = 0; nf < 16; nf++) {
            o[nf][0] *= al0; o[nf][1] *= al0;
            o[nf][2] *= al1; o[nf][3] *= al1;
        }

        #pragma unroll
        for (int ks = 0; ks < 4; ks++) {
            #pragma unroll
            for (int ng = 0; ng < 8; ng++) {
                unsigned vh4[4];
                ldsm4t(vh4, sb + pV + (unsigned)((ks * 16 + v_key) * 272 + (ng * 16 + v_ecol) * 2));
                mma_f16(o[2*ng],   pa[ks], vh4[0], vh4[1]);
                mma_f16(o[2*ng+1], pa[ks], vh4[2], vh4[3]);
            }
        }
        __syncthreads();

        if (kt < 6) {
            loadKVD(kt + 2, pK, pV, pD);
            CP_COMMIT;
        }
    }

    const float li0 = 1.f / l0, li1 = 1.f / l1;
    unsigned* Y = g_y16 + (((size_t)bh * N_ + q0) << 6);
    #pragma unroll
    for (int nf = 0; nf < 16; nf++) {
        const int e = nf * 8 + 2 * tig;
        Y[(size_t)r0 * 64 + (e >> 1)] = pack_h2(o[nf][0] * li0, o[nf][1] * li0);
        Y[(size_t)r1 * 64 + (e >> 1)] = pack_h2(o[nf][2] * li1, o[nf][3] * li1);
    }
}

// ---------------------------------------------------------------------------
// Kernel 3: out = Y @ Wo^T + bo, * mask (unchanged, ~18us).
// ---------------------------------------------------------------------------
#define OG_A 0
#define OG_B 17408
#define SMEM_OPROJ 34816

__global__ __launch_bounds__(256, 3) void oproj_mma_kernel(
    const float* __restrict__ bo,
    const float* __restrict__ mask, float* __restrict__ out)
{
    extern __shared__ char smc[];
    const unsigned sb = smem_u32(smc);

    const int tid  = threadIdx.x;
    const int lane = tid & 31;
    const int wid  = tid >> 5;
    const int wm   = wid >> 1;
    const int wn   = wid & 1;
    const int gid  = lane >> 2;
    const int tig  = lane & 3;

    const int row0 = blockIdx.x << 6;
    const int col0 = blockIdx.y << 6;
    const int b    = row0 >> 9;
    const int n0   = row0 & 511;

    const int a_row = (lane & 15);
    const int a_col = ((lane >> 4) << 3);
    const int b_key = (lane & 7) + ((lane >> 4) << 3);
    const int b_ecol = (((lane >> 3) & 1) << 3);

    float acc[4][4] = {};

    for (int h = 0; h < 8; h++) {
        const size_t ab = ((size_t)(b * H_ + h) * N_ + n0) << 6;
        copy16_async(g_y16 + ab, sb, OG_A, 64, tid, 256);
        for (int idx = tid; idx < 1024; idx += 256) {
            int r = idx >> 4, c = idx & 15;
            size_t su = (size_t)(col0 + r) * 512 + h * 64 + c * 4;
            CP16(sb + OG_B + r * 272 + c * 16, g_wo16 + su);
        }
        CP_COMMIT; CP_WAIT0;
        __syncthreads();

        #pragma unroll
        for (int k = 0; k < 8; k++) {
            unsigned ah[4];
            unsigned ao = (unsigned)((wm * 16 + a_row) * 272 + (k * 16 + a_col) * 2);
            ldsm4(ah, sb + OG_A + ao);
            #pragma unroll
            for (int ng = 0; ng < 2; ng++) {
                unsigned bo_ = (unsigned)((wn * 32 + ng * 16 + b_key) * 272 + (k * 16 + b_ecol) * 2);
                unsigned bh4[4];
                ldsm4(bh4, sb + OG_B + bo_);
                mma_f16(acc[2*ng],   ah, bh4[0], bh4[1]);
                mma_f16(acc[2*ng+1], ah, bh4[2], bh4[3]);
            }
        }
        __syncthreads();
    }

    const int lr0 = wm * 16 + gid;
    const int rw0 = row0 + lr0;
    const float mv0 = mask[b * 512 + (rw0 & 511)];
    const float mv1 = mask[b * 512 + ((rw0 + 8) & 511)];
    #pragma unroll
    for (int nf = 0; nf < 4; nf++) {
        const int cb = col0 + wn * 32 + nf * 8 + 2 * tig;
        const float b0v = bo[cb], b1v = bo[cb + 1];
        *(float2*)&out[(size_t)rw0 * E_ + cb] =
            make_float2((acc[nf][0] + b0v) * mv0, (acc[nf][1] + b1v) * mv0);
        *(float2*)&out[(size_t)(rw0 + 8) * E_ + cb] =
            make_float2((acc[nf][2] + b0v) * mv1, (acc[nf][3] + b1v) * mv1);
    }
}

// ---------------------------------------------------------------------------
extern "C" void kernel_launch(void* const* d_in, const int* in_sizes, int n_in,
                              void* d_out, int out_size)
{
    const float* x    = (const float*)d_in[0];
    const float* dist = (const float*)d_in[1];
    const float* mask = (const float*)d_in[2];
    const float* Wq   = (const float*)d_in[3];
    const float* bq   = (const float*)d_in[4];
    const float* Wk   = (const float*)d_in[5];
    const float* bk   = (const float*)d_in[6];
    const float* Wv   = (const float*)d_in[7];
    const float* bv   = (const float*)d_in[8];
    const float* Wo   = (const float*)d_in[9];
    const float* bo   = (const float*)d_in[10];
    float* out = (float*)d_out;

    cudaFuncSetAttribute(qkv_mma_kernel,
                         cudaFuncAttributeMaxDynamicSharedMemorySize, SMEM_QKV);
    cudaFuncSetAttribute(attn_mma_kernel,
                         cudaFuncAttributeMaxDynamicSharedMemorySize, SMEM_ATTN);
    cudaFuncSetAttribute(oproj_mma_kernel,
                         cudaFuncAttributeMaxDynamicSharedMemorySize, SMEM_OPROJ);

    prep_kernel<<<512, 256>>>(x, Wq, Wk, Wv, Wo, dist, mask);
    qkv_mma_kernel<<<dim3(64, 8, 3), 256, SMEM_QKV>>>(bq, bk, bv);
    attn_mma_kernel<<<dim3(8, 128), 128, SMEM_ATTN>>>();
    oproj_mma_kernel<<<dim3(128, 2), 256, SMEM_OPROJ>>>(bo, mask, out);
}

// round 15
// speedup vs baseline: 3.0957x; 1.0508x over previous
#include <cuda_runtime.h>
#include <cuda_bf16.h>
#include <cuda_fp16.h>
#include <math.h>

#define B_ 16
#define N_ 512
#define H_ 8
#define E_ 128
#define BH_ (B_*H_)
#define SCALE_ 0.08838834764831845f
#define LOG2E_ 1.4426950408889634f
#define QSCALE_ (SCALE_ * LOG2E_)
#define DNEG_ (-30000.0f)

// fp16 packed (u32 = h2) arrays
__device__ unsigned g_x16[B_*N_*E_/2];
__device__ unsigned g_wq16[1024*E_/2];
__device__ unsigned g_wk16[1024*E_/2];
__device__ unsigned g_wv16[1024*E_/2];
__device__ unsigned g_wo16[E_*1024/2];
__device__ unsigned g_q16[BH_*N_*E_/2];
__device__ unsigned g_k16[BH_*N_*E_/2];
__device__ unsigned g_v16[BH_*N_*E_/2];
__device__ unsigned g_y16[BH_*N_*E_/2];
__device__ unsigned g_d16[B_*N_*N_/2];

// ---------------------------------------------------------------------------
// helpers
// ---------------------------------------------------------------------------
__device__ __forceinline__ unsigned smem_u32(const void* p) {
    unsigned r;
    asm("{ .reg .u64 t; cvta.to.shared.u64 t, %1; cvt.u32.u64 %0, t; }" : "=r"(r) : "l"(p));
    return r;
}
__device__ __forceinline__ void ldsm4(unsigned r[4], unsigned addr) {
    asm volatile("ldmatrix.sync.aligned.m8n8.x4.shared.b16 {%0,%1,%2,%3}, [%4];"
        : "=r"(r[0]), "=r"(r[1]), "=r"(r[2]), "=r"(r[3]) : "r"(addr));
}
__device__ __forceinline__ void ldsm4t(unsigned r[4], unsigned addr) {
    asm volatile("ldmatrix.sync.aligned.m8n8.x4.trans.shared.b16 {%0,%1,%2,%3}, [%4];"
        : "=r"(r[0]), "=r"(r[1]), "=r"(r[2]), "=r"(r[3]) : "r"(addr));
}
__device__ __forceinline__ void mma_f16(float c[4], const unsigned a[4],
                                        unsigned b0, unsigned b1) {
    asm volatile("mma.sync.aligned.m16n8k16.row.col.f32.f16.f16.f32 "
        "{%0,%1,%2,%3}, {%4,%5,%6,%7}, {%8,%9}, {%0,%1,%2,%3};"
        : "+f"(c[0]), "+f"(c[1]), "+f"(c[2]), "+f"(c[3])
        : "r"(a[0]), "r"(a[1]), "r"(a[2]), "r"(a[3]), "r"(b0), "r"(b1));
}
__device__ __forceinline__ unsigned pack_h2(float a, float b) {
    __half2 h = __floats2half2_rn(a, b);
    return *(unsigned*)&h;
}
__device__ __forceinline__ float ex2f(float x) {
    float r;
    asm("ex2.approx.f32 %0, %1;" : "=f"(r) : "f"(x));
    return r;
}

#define CP16(dst, src) \
    asm volatile("cp.async.cg.shared.global [%0], [%1], 16;" \
        :: "r"(dst), "l"(__cvta_generic_to_global(src)) : "memory")
#define CP_COMMIT asm volatile("cp.async.commit_group;" ::: "memory")
#define CP_WAIT0  asm volatile("cp.async.wait_group 0;" ::: "memory")
#define CP_WAIT1  asm volatile("cp.async.wait_group 1;" ::: "memory")

// packed-fp16 tile async copy: global (row stride 64 u32) -> smem 272B stride
__device__ __forceinline__ void copy16_async(const unsigned* __restrict__ src,
        unsigned sb, int off, int rows, int tid, int nthr)
{
    const int total = rows * 16;
    for (int idx = tid; idx < total; idx += nthr) {
        int r = idx >> 4, c = idx & 15;
        CP16(sb + off + r * 272 + c * 16, src + (size_t)r * 64 + c * 4);
    }
}

// ---------------------------------------------------------------------------
// Kernel 0: convert all fp32 inputs to fp16 (unchanged).
// ---------------------------------------------------------------------------
__global__ __launch_bounds__(256) void prep_kernel(
    const float* __restrict__ x,
    const float* __restrict__ Wq, const float* __restrict__ Wk,
    const float* __restrict__ Wv, const float* __restrict__ Wo,
    const float* __restrict__ dist, const float* __restrict__ mask)
{
    const int flat = blockIdx.x * 256 + threadIdx.x;

    #pragma unroll
    for (int j = 0; j < 4; j++) {
        int i = flat + j * 131072;
        float2 v = *(const float2*)(x + 2 * (size_t)i);
        g_x16[i] = pack_h2(v.x, v.y);
    }
    if (flat < 65536) {
        float2 vq = *(const float2*)(Wq + 2 * flat);
        float2 vk = *(const float2*)(Wk + 2 * flat);
        float2 vv = *(const float2*)(Wv + 2 * flat);
        float2 vo = *(const float2*)(Wo + 2 * flat);
        g_wq16[flat] = pack_h2(vq.x, vq.y);
        g_wk16[flat] = pack_h2(vk.x, vk.y);
        g_wv16[flat] = pack_h2(vv.x, vv.y);
        g_wo16[flat] = pack_h2(vo.x, vo.y);
    }
    #pragma unroll
    for (int j = 0; j < 16; j++) {
        int i = flat + j * 131072;
        float2 v = *(const float2*)(dist + 2 * (size_t)i);
        int k0 = (2 * i) & 511;
        int row = i >> 8;
        int b = row >> 9;
        float m0 = mask[b * 512 + k0], m1 = mask[b * 512 + k0 + 1];
        g_d16[i] = pack_h2((m0 != 0.f) ? v.x * LOG2E_ : DNEG_,
                           (m1 != 0.f) ? v.y * LOG2E_ : DNEG_);
    }
}

// ---------------------------------------------------------------------------
// Kernel 1: QKV projection, pure fp16 GEMM (unchanged).
// ---------------------------------------------------------------------------
#define QG_X 0
#define QG_W 34816
#define SMEM_QKV 69632

__global__ __launch_bounds__(256, 2) void qkv_mma_kernel(
    const float* __restrict__ bq, const float* __restrict__ bk,
    const float* __restrict__ bv)
{
    extern __shared__ char smc[];
    const unsigned sb = smem_u32(smc);

    const int which = blockIdx.z;
    const unsigned* __restrict__ Wsel =
        (which == 0) ? g_wq16 : (which == 1) ? g_wk16 : g_wv16;
    const float* __restrict__ bias = (which == 0) ? bq : (which == 1) ? bk : bv;
    unsigned* __restrict__ dst = (which == 0) ? g_q16 : (which == 1) ? g_k16 : g_v16;

    const int tid  = threadIdx.x;
    const int lane = tid & 31;
    const int wid  = tid >> 5;
    const int wm   = wid >> 1;
    const int wn   = wid & 1;
    const int gid  = lane >> 2;
    const int tig  = lane & 3;

    const int row0 = blockIdx.x << 7;
    const int col0 = blockIdx.y << 7;

    const int a_row = (lane & 15);
    const int a_col = ((lane >> 4) << 3);
    const int b_key = (lane & 7) + ((lane >> 4) << 3);
    const int b_ecol = (((lane >> 3) & 1) << 3);

    copy16_async(g_x16 + (size_t)row0 * 64, sb, QG_X, 128, tid, 256);
    copy16_async(Wsel + (size_t)col0 * 64, sb, QG_W, 128, tid, 256);
    CP_COMMIT; CP_WAIT0;
    __syncthreads();

    float acc[2][8][4] = {};
    #pragma unroll
    for (int k = 0; k < 8; k++) {
        unsigned ah[2][4];
        #pragma unroll
        for (int mf = 0; mf < 2; mf++) {
            unsigned ao = (unsigned)((wm * 32 + mf * 16 + a_row) * 272 + (k * 16 + a_col) * 2);
            ldsm4(ah[mf], sb + QG_X + ao);
        }
        #pragma unroll
        for (int ng = 0; ng < 4; ng++) {
            unsigned bo = (unsigned)((wn * 64 + ng * 16 + b_key) * 272 + (k * 16 + b_ecol) * 2);
            unsigned bh4[4];
            ldsm4(bh4, sb + QG_W + bo);
            #pragma unroll
            for (int mf = 0; mf < 2; mf++) {
                mma_f16(acc[mf][2*ng],   ah[mf], bh4[0], bh4[1]);
                mma_f16(acc[mf][2*ng+1], ah[mf], bh4[2], bh4[3]);
            }
        }
    }

    const int hh = col0 >> 7;
    const float sc = (which == 0) ? QSCALE_ : 1.0f;
    #pragma unroll
    for (int mf = 0; mf < 2; mf++) {
        const int lr0 = wm * 32 + mf * 16 + gid;
        #pragma unroll
        for (int nf = 0; nf < 8; nf++) {
            const int cb = wn * 64 + nf * 8 + 2 * tig;
            const float b0v = bias[col0 + cb], b1v = bias[col0 + cb + 1];
            float v0 = (acc[mf][nf][0] + b0v) * sc;
            float v1 = (acc[mf][nf][1] + b1v) * sc;
            float v2 = (acc[mf][nf][2] + b0v) * sc;
            float v3 = (acc[mf][nf][3] + b1v) * sc;
            int rw = row0 + lr0;
            int b = rw >> 9, n = rw & 511;
            dst[(((size_t)(b * H_ + hh) * N_ + n) << 6) + (cb >> 1)] = pack_h2(v0, v1);
            rw += 8; b = rw >> 9; n = rw & 511;
            dst[(((size_t)(b * H_ + hh) * N_ + n) << 6) + (cb >> 1)] = pack_h2(v2, v3);
        }
    }
}

// ---------------------------------------------------------------------------
// Kernel 2: flash attention. dist now seeds the S accumulators (no add pass).
// ---------------------------------------------------------------------------
#define AQ_OFF    0
#define AK0_OFF   17408
#define AV0_OFF   34816
#define AD0_OFF   52224
#define AK1_OFF   61440
#define AV1_OFF   78848
#define AD1_OFF   96256
#define SMEM_ATTN 105472

__global__ __launch_bounds__(128, 2) void attn_mma_kernel()
{
    extern __shared__ char smc[];
    const unsigned sb = smem_u32(smc);

    const int tid  = threadIdx.x;
    const int lane = tid & 31;
    const int w    = tid >> 5;
    const int gid  = lane >> 2;
    const int tig  = lane & 3;

    const int q0 = blockIdx.x << 6;
    const int bh = blockIdx.y;
    const int b  = bh >> 3;

    auto loadKVD = [&](int kt, int kOff, int vOff, int dOff) {
        const size_t nb = ((size_t)bh * N_ + kt * 64) << 6;
        copy16_async(g_k16 + nb, sb, kOff, 64, tid, 128);
        copy16_async(g_v16 + nb, sb, vOff, 64, tid, 128);
        const unsigned* dsrc = g_d16 + ((size_t)b * N_ + q0) * 256 + kt * 32;
        #pragma unroll
        for (int i = 0; i < 4; i++) {
            int idx = tid + (i << 7);
            int r = idx >> 3, c = idx & 7;
            CP16(sb + dOff + r * 144 + c * 16, dsrc + (size_t)r * 256 + c * 4);
        }
    };

    copy16_async(g_q16 + (((size_t)bh * N_ + q0) << 6), sb, AQ_OFF, 64, tid, 128);
    loadKVD(0, AK0_OFF, AV0_OFF, AD0_OFF);
    CP_COMMIT;
    loadKVD(1, AK1_OFF, AV1_OFF, AD1_OFF);
    CP_COMMIT;

    float o[16][4] = {};
    float m0 = -3.0e38f, m1 = -3.0e38f, l0 = 0.f, l1 = 0.f;

    const int a_row = (lane & 15);
    const int a_col = ((lane >> 4) << 3);
    const int b_key = (lane & 7) + ((lane >> 4) << 3);
    const int b_ecol = (((lane >> 3) & 1) << 3);
    const int v_key = (lane & 7) + (((lane >> 3) & 1) << 3);
    const int v_ecol = ((lane >> 4) << 3);

    const int r0 = w * 16 + gid;
    const int r1 = r0 + 8;

    for (int kt = 0; kt < 8; kt++) {
        if (kt == 7) { CP_WAIT0; } else { CP_WAIT1; }
        __syncthreads();

        const int pK = (kt & 1) ? AK1_OFF : AK0_OFF;
        const int pV = (kt & 1) ? AV1_OFF : AV0_OFF;
        const int pD = (kt & 1) ? AD1_OFF : AD0_OFF;

        // ---- seed S accumulators with dist (mask baked in) ----
        float acc[8][4];
        #pragma unroll
        for (int nf = 0; nf < 8; nf++) {
            const int c = nf * 8 + 2 * tig;
            unsigned du0 = *(const unsigned*)(smc + pD + r0 * 144 + c * 2);
            unsigned du1 = *(const unsigned*)(smc + pD + r1 * 144 + c * 2);
            float2 d0 = __half22float2(*(__half2*)&du0);
            float2 d1 = __half22float2(*(__half2*)&du1);
            acc[nf][0] = d0.x; acc[nf][1] = d0.y;
            acc[nf][2] = d1.x; acc[nf][3] = d1.y;
        }

        // ---- S += Q K^T ----
        #pragma unroll
        for (int ks = 0; ks < 8; ks++) {
            unsigned aq[4];
            ldsm4(aq, sb + AQ_OFF + (unsigned)((w * 16 + a_row) * 272 + (ks * 16 + a_col) * 2));
            #pragma unroll
            for (int ng = 0; ng < 4; ng++) {
                unsigned bk4[4];
                ldsm4(bk4, sb + pK + (unsigned)((ng * 16 + b_key) * 272 + (ks * 16 + b_ecol) * 2));
                mma_f16(acc[2*ng],   aq, bk4[0], bk4[1]);
                mma_f16(acc[2*ng+1], aq, bk4[2], bk4[3]);
            }
        }

        // ---- row max ----
        float mx0 = -3.0e38f, mx1 = -3.0e38f;
        #pragma unroll
        for (int nf = 0; nf < 8; nf++) {
            mx0 = fmaxf(mx0, fmaxf(acc[nf][0], acc[nf][1]));
            mx1 = fmaxf(mx1, fmaxf(acc[nf][2], acc[nf][3]));
        }
        mx0 = fmaxf(mx0, __shfl_xor_sync(0xffffffffu, mx0, 1));
        mx0 = fmaxf(mx0, __shfl_xor_sync(0xffffffffu, mx0, 2));
        mx1 = fmaxf(mx1, __shfl_xor_sync(0xffffffffu, mx1, 1));
        mx1 = fmaxf(mx1, __shfl_xor_sync(0xffffffffu, mx1, 2));

        const float mn0 = fmaxf(m0, mx0), mn1 = fmaxf(m1, mx1);
        const float al0 = ex2f(m0 - mn0), al1 = ex2f(m1 - mn1);

        // ---- P = exp2(S - m) into PV A-fragments ----
        unsigned pa[4][4];
        float rs0 = 0.f, rs1 = 0.f;
        #pragma unroll
        for (int ks = 0; ks < 4; ks++) {
            float p0 = ex2f(acc[2*ks][0] - mn0);
            float p1 = ex2f(acc[2*ks][1] - mn0);
            float p2 = ex2f(acc[2*ks][2] - mn1);
            float p3 = ex2f(acc[2*ks][3] - mn1);
            float p4 = ex2f(acc[2*ks+1][0] - mn0);
            float p5 = ex2f(acc[2*ks+1][1] - mn0);
            float p6 = ex2f(acc[2*ks+1][2] - mn1);
            float p7 = ex2f(acc[2*ks+1][3] - mn1);
            rs0 += (p0 + p1) + (p4 + p5);
            rs1 += (p2 + p3) + (p6 + p7);
            pa[ks][0] = pack_h2(p0, p1);
            pa[ks][1] = pack_h2(p2, p3);
            pa[ks][2] = pack_h2(p4, p5);
            pa[ks][3] = pack_h2(p6, p7);
        }
        rs0 += __shfl_xor_sync(0xffffffffu, rs0, 1);
        rs0 += __shfl_xor_sync(0xffffffffu, rs0, 2);
        rs1 += __shfl_xor_sync(0xffffffffu, rs1, 1);
        rs1 += __shfl_xor_sync(0xffffffffu, rs1, 2);
        l0 = al0 * l0 + rs0;  l1 = al1 * l1 + rs1;
        m0 = mn0;             m1 = mn1;

        #pragma unroll
        for (int nf = 0; nf < 16; nf++) {
            o[nf][0] *= al0; o[nf][1] *= al0;
            o[nf][2] *= al1; o[nf][3] *= al1;
        }

        // ---- O += P V ----
        #pragma unroll
        for (int ks = 0; ks < 4; ks++) {
            #pragma unroll
            for (int ng = 0; ng < 8; ng++) {
                unsigned vh4[4];
                ldsm4t(vh4, sb + pV + (unsigned)((ks * 16 + v_key) * 272 + (ng * 16 + v_ecol) * 2));
                mma_f16(o[2*ng],   pa[ks], vh4[0], vh4[1]);
                mma_f16(o[2*ng+1], pa[ks], vh4[2], vh4[3]);
            }
        }
        __syncthreads();

        if (kt < 6) {
            loadKVD(kt + 2, pK, pV, pD);
            CP_COMMIT;
        }
    }

    const float li0 = 1.f / l0, li1 = 1.f / l1;
    unsigned* Y = g_y16 + (((size_t)bh * N_ + q0) << 6);
    #pragma unroll
    for (int nf = 0; nf < 16; nf++) {
        const int e = nf * 8 + 2 * tig;
        Y[(size_t)r0 * 64 + (e >> 1)] = pack_h2(o[nf][0] * li0, o[nf][1] * li0);
        Y[(size_t)r1 * 64 + (e >> 1)] = pack_h2(o[nf][2] * li1, o[nf][3] * li1);
    }
}

// ---------------------------------------------------------------------------
// Kernel 3: out = Y @ Wo^T + bo, * mask. DOUBLE-BUFFERED h-loop, 3 CTAs/SM.
// ---------------------------------------------------------------------------
#define OG_A0 0
#define OG_B0 17408
#define OG_A1 34816
#define OG_B1 52224
#define SMEM_OPROJ 69632

__global__ __launch_bounds__(256, 3) void oproj_mma_kernel(
    const float* __restrict__ bo,
    const float* __restrict__ mask, float* __restrict__ out)
{
    extern __shared__ char smc[];
    const unsigned sb = smem_u32(smc);

    const int tid  = threadIdx.x;
    const int lane = tid & 31;
    const int wid  = tid >> 5;
    const int wm   = wid >> 1;
    const int wn   = wid & 1;
    const int gid  = lane >> 2;
    const int tig  = lane & 3;

    const int row0 = blockIdx.x << 6;
    const int col0 = blockIdx.y << 6;
    const int b    = row0 >> 9;
    const int n0   = row0 & 511;

    const int a_row = (lane & 15);
    const int a_col = ((lane >> 4) << 3);
    const int b_key = (lane & 7) + ((lane >> 4) << 3);
    const int b_ecol = (((lane >> 3) & 1) << 3);

    auto loadAB = [&](int h, int aOff, int bOff) {
        const size_t ab = ((size_t)(b * H_ + h) * N_ + n0) << 6;
        copy16_async(g_y16 + ab, sb, aOff, 64, tid, 256);
        for (int idx = tid; idx < 1024; idx += 256) {
            int r = idx >> 4, c = idx & 15;
            size_t su = (size_t)(col0 + r) * 512 + h * 64 + c * 4;
            CP16(sb + bOff + r * 272 + c * 16, g_wo16 + su);
        }
    };

    float acc[4][4] = {};

    loadAB(0, OG_A0, OG_B0);
    CP_COMMIT;

    for (int h = 0; h < 8; h++) {
        const int pA = (h & 1) ? OG_A1 : OG_A0;
        const int pB = (h & 1) ? OG_B1 : OG_B0;
        // issue next tile into the other buffer (protected by prev iter's
        // trailing sync), then wait for the current tile only.
        if (h < 7) {
            loadAB(h + 1, (h & 1) ? OG_A0 : OG_A1, (h & 1) ? OG_B0 : OG_B1);
            CP_COMMIT;
            CP_WAIT1;
        } else {
            CP_WAIT0;
        }
        __syncthreads();

        #pragma unroll
        for (int k = 0; k < 8; k++) {
            unsigned ah[4];
            unsigned ao = (unsigned)((wm * 16 + a_row) * 272 + (k * 16 + a_col) * 2);
            ldsm4(ah, sb + pA + ao);
            #pragma unroll
            for (int ng = 0; ng < 2; ng++) {
                unsigned bo_ = (unsigned)((wn * 32 + ng * 16 + b_key) * 272 + (k * 16 + b_ecol) * 2);
                unsigned bh4[4];
                ldsm4(bh4, sb + pB + bo_);
                mma_f16(acc[2*ng],   ah, bh4[0], bh4[1]);
                mma_f16(acc[2*ng+1], ah, bh4[2], bh4[3]);
            }
        }
        __syncthreads();
    }

    const int lr0 = wm * 16 + gid;
    const int rw0 = row0 + lr0;
    const float mv0 = mask[b * 512 + (rw0 & 511)];
    const float mv1 = mask[b * 512 + ((rw0 + 8) & 511)];
    #pragma unroll
    for (int nf = 0; nf < 4; nf++) {
        const int cb = col0 + wn * 32 + nf * 8 + 2 * tig;
        const float b0v = bo[cb], b1v = bo[cb + 1];
        *(float2*)&out[(size_t)rw0 * E_ + cb] =
            make_float2((acc[nf][0] + b0v) * mv0, (acc[nf][1] + b1v) * mv0);
        *(float2*)&out[(size_t)(rw0 + 8) * E_ + cb] =
            make_float2((acc[nf][2] + b0v) * mv1, (acc[nf][3] + b1v) * mv1);
    }
}

// ---------------------------------------------------------------------------
extern "C" void kernel_launch(void* const* d_in, const int* in_sizes, int n_in,
                              void* d_out, int out_size)
{
    const float* x    = (const float*)d_in[0];
    const float* dist = (const float*)d_in[1];
    const float* mask = (const float*)d_in[2];
    const float* Wq   = (const float*)d_in[3];
    const float* bq   = (const float*)d_in[4];
    const float* Wk   = (const float*)d_in[5];
    const float* bk   = (const float*)d_in[6];
    const float* Wv   = (const float*)d_in[7];
    const float* bv   = (const float*)d_in[8];
    const float* Wo   = (const float*)d_in[9];
    const float* bo   = (const float*)d_in[10];
    float* out = (float*)d_out;

    cudaFuncSetAttribute(qkv_mma_kernel,
                         cudaFuncAttributeMaxDynamicSharedMemorySize, SMEM_QKV);
    cudaFuncSetAttribute(attn_mma_kernel,
                         cudaFuncAttributeMaxDynamicSharedMemorySize, SMEM_ATTN);
    cudaFuncSetAttribute(oproj_mma_kernel,
                         cudaFuncAttributeMaxDynamicSharedMemorySize, SMEM_OPROJ);

    prep_kernel<<<512, 256>>>(x, Wq, Wk, Wv, Wo, dist, mask);
    qkv_mma_kernel<<<dim3(64, 8, 3), 256, SMEM_QKV>>>(bq, bk, bv);
    attn_mma_kernel<<<dim3(8, 128), 128, SMEM_ATTN>>>();
    oproj_mma_kernel<<<dim3(128, 2), 256, SMEM_OPROJ>>>(bo, mask, out);
}